// round 8
// baseline (speedup 1.0000x reference)
#include <cuda_runtime.h>
#include <math.h>

// ---------------- problem constants ----------------
#define Bb   2
#define Ss   1024
#define Dd   2048
#define Hh   16
#define DHh  128
#define Ee   8
#define HIDh 4096
#define Tt   (Bb * Ss)       // 2048 tokens
#define NPAIR (Tt * 2)       // 4096 (token, expert) pairs, always exactly this

// ---------------- device scratch (no allocations allowed) ----------------
__device__ float g_xn1[Tt * Dd];
__device__ float g_q  [Tt * Dd];
__device__ float g_k  [Tt * Dd];
__device__ float g_v  [Tt * Dd];
__device__ float g_att[Tt * Dd];
__device__ float g_x2 [Tt * Dd];
__device__ float g_xn2[Tt * Dd];
__device__ int   g_tid2[NPAIR];     // per (token,k) expert id
__device__ float g_twt [NPAIR];     // per (token,k) routing weight
__device__ int   g_cnt[Ee];
__device__ int   g_off[Ee];
__device__ int   g_tok[NPAIR];      // expert-grouped token ids
__device__ int   g_prow[NPAIR];     // (token,k) -> row in grouped buffers
__device__ float g_gb[(size_t)NPAIR * HIDh];   // gate -> h (in place)
__device__ float g_ub[(size_t)NPAIR * HIDh];   // up
__device__ float g_eo[(size_t)NPAIR * Dd];     // expert outputs

// ---------------- rmsnorm ----------------
__global__ void rmsnorm_kernel(const float* __restrict__ x,
                               const float* __restrict__ w,
                               float* __restrict__ out) {
    int t = blockIdx.x;
    const float* xr = x + (size_t)t * Dd;
    float ss = 0.f;
    for (int i = threadIdx.x; i < Dd; i += 256) { float vv = xr[i]; ss += vv * vv; }
    __shared__ float red[8];
    #pragma unroll
    for (int o = 16; o; o >>= 1) ss += __shfl_xor_sync(0xffffffffu, ss, o);
    if ((threadIdx.x & 31) == 0) red[threadIdx.x >> 5] = ss;
    __syncthreads();
    if (threadIdx.x < 8) {
        float v = red[threadIdx.x];
        #pragma unroll
        for (int o = 4; o; o >>= 1) v += __shfl_xor_sync(0xffu, v, o);
        if (threadIdx.x == 0) red[0] = v;
    }
    __syncthreads();
    float inv = 1.f / sqrtf(red[0] / (float)Dd + 1e-8f);
    float* orow = out + (size_t)t * Dd;
    for (int i = threadIdx.x; i < Dd; i += 256) orow[i] = xr[i] * inv * w[i];
}

// ---------------- generic sgemm: C[M,N] = A[M,K] @ B[N,K]^T (+bias)(+resid) ----------------
#define BM 128
#define BN 128
#define BK 8

__global__ __launch_bounds__(256, 2)
void sgemm_kernel(const float* __restrict__ A, const float* __restrict__ B,
                  float* __restrict__ C, const float* __restrict__ bias,
                  const float* __restrict__ resid, int N, int K) {
    __shared__ float As[BK][BM];
    __shared__ float Bs[BK][BN];
    const int tid = threadIdx.x;
    const int bm = blockIdx.y * BM;
    const int bn = blockIdx.x * BN;
    const int ty = tid >> 4;          // 0..15
    const int tx = tid & 15;          // 0..15
    const int lr = tid >> 1;          // 0..127
    const int lc = (tid & 1) * 4;     // 0 or 4

    const float* Ap = A + (size_t)(bm + lr) * K + lc;
    const float* Bp = B + (size_t)(bn + lr) * K + lc;

    float acc[8][8];
    #pragma unroll
    for (int i = 0; i < 8; i++)
        #pragma unroll
        for (int j = 0; j < 8; j++) acc[i][j] = 0.f;

    for (int k0 = 0; k0 < K; k0 += BK) {
        float4 a4 = *reinterpret_cast<const float4*>(Ap + k0);
        float4 b4 = *reinterpret_cast<const float4*>(Bp + k0);
        As[lc + 0][lr] = a4.x; As[lc + 1][lr] = a4.y; As[lc + 2][lr] = a4.z; As[lc + 3][lr] = a4.w;
        Bs[lc + 0][lr] = b4.x; Bs[lc + 1][lr] = b4.y; Bs[lc + 2][lr] = b4.z; Bs[lc + 3][lr] = b4.w;
        __syncthreads();
        #pragma unroll
        for (int k = 0; k < BK; k++) {
            float ra[8], rb[8];
            *(float4*)(ra)     = *(const float4*)&As[k][ty * 8];
            *(float4*)(ra + 4) = *(const float4*)&As[k][ty * 8 + 4];
            *(float4*)(rb)     = *(const float4*)&Bs[k][tx * 8];
            *(float4*)(rb + 4) = *(const float4*)&Bs[k][tx * 8 + 4];
            #pragma unroll
            for (int i = 0; i < 8; i++)
                #pragma unroll
                for (int j = 0; j < 8; j++)
                    acc[i][j] = fmaf(ra[i], rb[j], acc[i][j]);
        }
        __syncthreads();
    }
    #pragma unroll
    for (int i = 0; i < 8; i++) {
        int row = bm + ty * 8 + i;
        float* crow = C + (size_t)row * N + bn + tx * 8;
        #pragma unroll
        for (int j = 0; j < 8; j += 4) {
            float4 v;
            v.x = acc[i][j + 0]; v.y = acc[i][j + 1]; v.z = acc[i][j + 2]; v.w = acc[i][j + 3];
            if (bias) {
                int c = bn + tx * 8 + j;
                v.x += bias[c]; v.y += bias[c + 1]; v.z += bias[c + 2]; v.w += bias[c + 3];
            }
            if (resid) {
                float4 r = *(const float4*)(resid + (size_t)row * N + bn + tx * 8 + j);
                v.x += r.x; v.y += r.y; v.z += r.z; v.w += r.w;
            }
            *(float4*)(crow + j) = v;
        }
    }
}

// ---------------- MoE grouped gemm (per-expert segments, optional A gather) ----------------
template <bool GATHER>
__global__ __launch_bounds__(256, 2)
void moe_gemm_kernel(const float* __restrict__ Abase, const float* __restrict__ Bbase,
                     float* __restrict__ Cbase, int N, int K) {
    int e = blockIdx.z;
    int cnt = g_cnt[e];
    int bm = blockIdx.y * BM;
    if (bm >= cnt) return;
    int seg = g_off[e];
    int bn = blockIdx.x * BN;

    __shared__ float As[BK][BM];
    __shared__ float Bs[BK][BN];
    const int tid = threadIdx.x;
    const int ty = tid >> 4;
    const int tx = tid & 15;
    const int lr = tid >> 1;
    const int lc = (tid & 1) * 4;

    int gr = bm + lr;
    if (gr >= cnt) gr = cnt - 1;  // clamp (compute garbage, never stored)
    const float* Ap;
    if (GATHER) Ap = Abase + (size_t)g_tok[seg + gr] * K + lc;
    else        Ap = Abase + (size_t)(seg + gr) * K + lc;
    const float* Bp = Bbase + (size_t)e * N * K + (size_t)(bn + lr) * K + lc;

    float acc[8][8];
    #pragma unroll
    for (int i = 0; i < 8; i++)
        #pragma unroll
        for (int j = 0; j < 8; j++) acc[i][j] = 0.f;

    for (int k0 = 0; k0 < K; k0 += BK) {
        float4 a4 = *reinterpret_cast<const float4*>(Ap + k0);
        float4 b4 = *reinterpret_cast<const float4*>(Bp + k0);
        As[lc + 0][lr] = a4.x; As[lc + 1][lr] = a4.y; As[lc + 2][lr] = a4.z; As[lc + 3][lr] = a4.w;
        Bs[lc + 0][lr] = b4.x; Bs[lc + 1][lr] = b4.y; Bs[lc + 2][lr] = b4.z; Bs[lc + 3][lr] = b4.w;
        __syncthreads();
        #pragma unroll
        for (int k = 0; k < BK; k++) {
            float ra[8], rb[8];
            *(float4*)(ra)     = *(const float4*)&As[k][ty * 8];
            *(float4*)(ra + 4) = *(const float4*)&As[k][ty * 8 + 4];
            *(float4*)(rb)     = *(const float4*)&Bs[k][tx * 8];
            *(float4*)(rb + 4) = *(const float4*)&Bs[k][tx * 8 + 4];
            #pragma unroll
            for (int i = 0; i < 8; i++)
                #pragma unroll
                for (int j = 0; j < 8; j++)
                    acc[i][j] = fmaf(ra[i], rb[j], acc[i][j]);
        }
        __syncthreads();
    }
    #pragma unroll
    for (int i = 0; i < 8; i++) {
        int lrow = bm + ty * 8 + i;
        if (lrow >= cnt) continue;
        float* crow = Cbase + (size_t)(seg + lrow) * N + bn + tx * 8;
        #pragma unroll
        for (int j = 0; j < 8; j += 4) {
            float4 v;
            v.x = acc[i][j + 0]; v.y = acc[i][j + 1]; v.z = acc[i][j + 2]; v.w = acc[i][j + 3];
            *(float4*)(crow + j) = v;
        }
    }
}

// ---------------- RoPE (angle depends on HEAD index, per reference) ----------------
__global__ void rope_kernel(float* __restrict__ q) {
    int gid = blockIdx.x * 256 + threadIdx.x;   // over T * H * 64 pairs
    int t = gid >> 10;
    int r = gid & 1023;
    int h = r >> 6;
    int p = r & 63;
    // inv_freq = 10000^(-p/64); angle = h * inv_freq
    float ang = (float)h * expf(-(float)p * (9.210340371976184f / 64.f));
    float c = cosf(ang), s = sinf(ang);
    float* base = q + (size_t)t * Dd + h * DHh + 2 * p;
    float x1 = base[0], x2 = base[1];
    base[0] = x1 * c - x2 * s;
    base[1] = x1 * s + x2 * c;
}

// ---------------- flash-style causal attention ----------------
#define KT 32
__global__ void attn_kernel(const float* __restrict__ Q, const float* __restrict__ Kx,
                            const float* __restrict__ V, float* __restrict__ O) {
    __shared__ float Ks[KT][DHh];
    __shared__ float Vs[KT][DHh];
    int b = blockIdx.z, h = blockIdx.y, qg = blockIdx.x;
    int warp = threadIdx.x >> 5, lane = threadIdx.x & 31;
    int sq = qg * 8 + warp;
    int tq = b * Ss + sq;
    const float* qrow = Q + (size_t)tq * Dd + h * DHh;
    float qr[4];
    #pragma unroll
    for (int i = 0; i < 4; i++) qr[i] = qrow[lane + 32 * i];
    float m = -INFINITY, l = 0.f, o[4] = {0.f, 0.f, 0.f, 0.f};

    int ntiles = (qg * 8 + 8 + KT - 1) / KT;
    for (int kt = 0; kt < ntiles; kt++) {
        for (int idx = threadIdx.x; idx < KT * DHh; idx += 256) {
            int rr = idx >> 7, cc = idx & 127;
            size_t g = ((size_t)(b * Ss + kt * KT + rr)) * Dd + h * DHh + cc;
            Ks[rr][cc] = Kx[g];
            Vs[rr][cc] = V[g];
        }
        __syncthreads();
        int kmax = sq - kt * KT + 1;
        if (kmax > KT) kmax = KT;
        for (int j = 0; j < kmax; j++) {
            float p = qr[0] * Ks[j][lane] + qr[1] * Ks[j][lane + 32] +
                      qr[2] * Ks[j][lane + 64] + qr[3] * Ks[j][lane + 96];
            #pragma unroll
            for (int ofs = 16; ofs; ofs >>= 1) p += __shfl_xor_sync(0xffffffffu, p, ofs);
            p *= 0.08838834764831845f;  // 1/sqrt(128)
            float mnew = fmaxf(m, p);
            float corr = __expf(m - mnew);
            float w = __expf(p - mnew);
            l = l * corr + w;
            #pragma unroll
            for (int i = 0; i < 4; i++) o[i] = o[i] * corr + w * Vs[j][lane + 32 * i];
            m = mnew;
        }
        __syncthreads();
    }
    float invl = 1.f / l;
    float* orow = O + (size_t)tq * Dd + h * DHh;
    #pragma unroll
    for (int i = 0; i < 4; i++) orow[lane + 32 * i] = o[i] * invl;
}

// ---------------- router: logits, top-2, softmax weights ----------------
__global__ void router_kernel(const float* __restrict__ xn, const float* __restrict__ wr,
                              const float* __restrict__ br) {
    int t = blockIdx.x;
    int warp = threadIdx.x >> 5, lane = threadIdx.x & 31;
    const float* xr = xn + (size_t)t * Dd;
    const float* w = wr + (size_t)warp * Dd;
    float s = 0.f;
    for (int i = lane; i < Dd; i += 32) s += xr[i] * w[i];
    #pragma unroll
    for (int o = 16; o; o >>= 1) s += __shfl_xor_sync(0xffffffffu, s, o);
    __shared__ float lg[Ee];
    if (lane == 0) lg[warp] = s + br[warp];
    __syncthreads();
    if (threadIdx.x == 0) {
        int i0 = 0; float v0 = lg[0];
        for (int e = 1; e < Ee; e++) if (lg[e] > v0) { v0 = lg[e]; i0 = e; }
        int i1 = -1; float v1 = -INFINITY;
        for (int e = 0; e < Ee; e++) if (e != i0 && lg[e] > v1) { v1 = lg[e]; i1 = e; }
        float e1 = expf(v1 - v0);
        float w0 = 1.f / (1.f + e1);
        g_tid2[t * 2] = i0; g_tid2[t * 2 + 1] = i1;
        g_twt[t * 2] = w0;  g_twt[t * 2 + 1] = e1 * w0;
    }
}

// ---------------- single-block expert grouping ----------------
__global__ void build_lists_kernel() {
    __shared__ int cnt[Ee], run[Ee];
    int tid = threadIdx.x;
    if (tid < Ee) cnt[tid] = 0;
    __syncthreads();
    for (int i = tid; i < NPAIR; i += 256) atomicAdd(&cnt[g_tid2[i]], 1);
    __syncthreads();
    if (tid == 0) {
        int acc = 0;
        for (int e = 0; e < Ee; e++) { g_cnt[e] = cnt[e]; g_off[e] = acc; run[e] = acc; acc += cnt[e]; }
    }
    __syncthreads();
    for (int i = tid; i < NPAIR; i += 256) {
        int e = g_tid2[i];
        int pos = atomicAdd(&run[e], 1);
        g_tok[pos] = i >> 1;
        g_prow[i] = pos;
    }
}

// ---------------- h = silu(g) * u (in place into g_gb) ----------------
__global__ void silu_kernel() {
    size_t i = ((size_t)blockIdx.x * 256 + threadIdx.x) * 4;
    float4 g = *(float4*)(g_gb + i);
    float4 u = *(float4*)(g_ub + i);
    g.x = g.x / (1.f + expf(-g.x)) * u.x;
    g.y = g.y / (1.f + expf(-g.y)) * u.y;
    g.z = g.z / (1.f + expf(-g.z)) * u.z;
    g.w = g.w / (1.f + expf(-g.w)) * u.w;
    *(float4*)(g_gb + i) = g;
}

// ---------------- final combine: out = x2 + w0*eo0 + w1*eo1 ----------------
__global__ void combine_kernel(float* __restrict__ out) {
    int t = blockIdx.x;
    int r0 = g_prow[t * 2], r1 = g_prow[t * 2 + 1];
    float w0 = g_twt[t * 2], w1 = g_twt[t * 2 + 1];
    const float* e0 = g_eo + (size_t)r0 * Dd;
    const float* e1 = g_eo + (size_t)r1 * Dd;
    const float* xr = g_x2 + (size_t)t * Dd;
    float* orow = out + (size_t)t * Dd;
    for (int i = threadIdx.x; i < Dd; i += 256)
        orow[i] = xr[i] + w0 * e0[i] + w1 * e1[i];
}

// ---------------- host launcher ----------------
extern "C" void kernel_launch(void* const* d_in, const int* in_sizes, int n_in,
                              void* d_out, int out_size) {
    const float* x   = (const float*)d_in[0];
    const float* wq  = (const float*)d_in[1];
    const float* bq  = (const float*)d_in[2];
    const float* wk  = (const float*)d_in[3];
    const float* bk  = (const float*)d_in[4];
    const float* wv  = (const float*)d_in[5];
    const float* bv  = (const float*)d_in[6];
    const float* wo  = (const float*)d_in[7];
    const float* bo  = (const float*)d_in[8];
    const float* wr  = (const float*)d_in[9];
    const float* br  = (const float*)d_in[10];
    const float* wg  = (const float*)d_in[11];
    const float* wu  = (const float*)d_in[12];
    const float* wd  = (const float*)d_in[13];
    const float* r1w = (const float*)d_in[14];
    const float* r2w = (const float*)d_in[15];
    float* out = (float*)d_out;

    float *xn1, *q, *k, *v, *att, *x2, *xn2, *gb, *ub, *eo;
    cudaGetSymbolAddress((void**)&xn1, g_xn1);
    cudaGetSymbolAddress((void**)&q,   g_q);
    cudaGetSymbolAddress((void**)&k,   g_k);
    cudaGetSymbolAddress((void**)&v,   g_v);
    cudaGetSymbolAddress((void**)&att, g_att);
    cudaGetSymbolAddress((void**)&x2,  g_x2);
    cudaGetSymbolAddress((void**)&xn2, g_xn2);
    cudaGetSymbolAddress((void**)&gb,  g_gb);
    cudaGetSymbolAddress((void**)&ub,  g_ub);
    cudaGetSymbolAddress((void**)&eo,  g_eo);

    // 1) rmsnorm1
    rmsnorm_kernel<<<Tt, 256>>>(x, r1w, xn1);
    // 2) QKV projections
    sgemm_kernel<<<dim3(Dd / BN, Tt / BM), 256>>>(xn1, wq, q, bq, nullptr, Dd, Dd);
    sgemm_kernel<<<dim3(Dd / BN, Tt / BM), 256>>>(xn1, wk, k, bk, nullptr, Dd, Dd);
    sgemm_kernel<<<dim3(Dd / BN, Tt / BM), 256>>>(xn1, wv, v, bv, nullptr, Dd, Dd);
    // 3) RoPE on q, k
    rope_kernel<<<(Tt * Hh * 64) / 256, 256>>>(q);
    rope_kernel<<<(Tt * Hh * 64) / 256, 256>>>(k);
    // 4) causal attention
    attn_kernel<<<dim3(Ss / 8, Hh, Bb), 256>>>(q, k, v, att);
    // 5) output projection + residual
    sgemm_kernel<<<dim3(Dd / BN, Tt / BM), 256>>>(att, wo, x2, bo, x, Dd, Dd);
    // 6) rmsnorm2
    rmsnorm_kernel<<<Tt, 256>>>(x2, r2w, xn2);
    // 7) router + expert grouping
    router_kernel<<<Tt, 256>>>(xn2, wr, br);
    build_lists_kernel<<<1, 256>>>();
    // 8) sparse MoE: gate, up (gathered), silu*mul, down
    moe_gemm_kernel<true><<<dim3(HIDh / BN, Tt / BM, Ee), 256>>>(xn2, wg, gb, HIDh, Dd);
    moe_gemm_kernel<true><<<dim3(HIDh / BN, Tt / BM, Ee), 256>>>(xn2, wu, ub, HIDh, Dd);
    silu_kernel<<<((size_t)NPAIR * HIDh / 4) / 256, 256>>>();
    moe_gemm_kernel<false><<<dim3(Dd / BN, Tt / BM, Ee), 256>>>(gb, wd, eo, Dd, HIDh);
    // 9) combine
    combine_kernel<<<Tt, 256>>>(out);
}

// round 9
// speedup vs baseline: 1.0017x; 1.0017x over previous
#include <cuda_runtime.h>
#include <math.h>

// ---------------- problem constants ----------------
#define Bb   2
#define Ss   1024
#define Dd   2048
#define Hh   16
#define DHh  128
#define Ee   8
#define HIDh 4096
#define Tt   (Bb * Ss)       // 2048 tokens
#define NPAIR (Tt * 2)       // 4096 (token, expert) pairs, always exactly this

// ---------------- device scratch (no allocations allowed) ----------------
__device__ float g_xn1[Tt * Dd];
__device__ float g_q  [Tt * Dd];
__device__ float g_k  [Tt * Dd];
__device__ float g_v  [Tt * Dd];
__device__ float g_att[Tt * Dd];
__device__ float g_x2 [Tt * Dd];
__device__ float g_xn2[Tt * Dd];
__device__ int   g_tid2[NPAIR];     // per (token,k) expert id
__device__ float g_twt [NPAIR];     // per (token,k) routing weight
__device__ int   g_cnt[Ee];
__device__ int   g_off[Ee];
__device__ int   g_tok[NPAIR];      // expert-grouped token ids
__device__ int   g_prow[NPAIR];     // (token,k) -> row in grouped buffers
__device__ float g_gb[(size_t)NPAIR * HIDh];   // gate -> h (in place)
__device__ float g_ub[(size_t)NPAIR * HIDh];   // up
__device__ float g_eo[(size_t)NPAIR * Dd];     // expert outputs

// ---------------- rmsnorm ----------------
__global__ void rmsnorm_kernel(const float* __restrict__ x,
                               const float* __restrict__ w,
                               float* __restrict__ out) {
    int t = blockIdx.x;
    const float* xr = x + (size_t)t * Dd;
    float ss = 0.f;
    for (int i = threadIdx.x; i < Dd; i += 256) { float vv = xr[i]; ss += vv * vv; }
    __shared__ float red[8];
    #pragma unroll
    for (int o = 16; o; o >>= 1) ss += __shfl_xor_sync(0xffffffffu, ss, o);
    if ((threadIdx.x & 31) == 0) red[threadIdx.x >> 5] = ss;
    __syncthreads();
    if (threadIdx.x < 8) {
        float v = red[threadIdx.x];
        #pragma unroll
        for (int o = 4; o; o >>= 1) v += __shfl_xor_sync(0xffu, v, o);
        if (threadIdx.x == 0) red[0] = v;
    }
    __syncthreads();
    float inv = 1.f / sqrtf(red[0] / (float)Dd + 1e-8f);
    float* orow = out + (size_t)t * Dd;
    for (int i = threadIdx.x; i < Dd; i += 256) orow[i] = xr[i] * inv * w[i];
}

// ---------------- generic sgemm: C[M,N] = A[M,K] @ B[N,K]^T (+bias)(+resid) ----------------
#define BM 128
#define BN 128
#define BK 8

__global__ __launch_bounds__(256, 2)
void sgemm_kernel(const float* __restrict__ A, const float* __restrict__ B,
                  float* __restrict__ C, const float* __restrict__ bias,
                  const float* __restrict__ resid, int N, int K) {
    __shared__ float As[BK][BM];
    __shared__ float Bs[BK][BN];
    const int tid = threadIdx.x;
    const int bm = blockIdx.y * BM;
    const int bn = blockIdx.x * BN;
    const int ty = tid >> 4;          // 0..15
    const int tx = tid & 15;          // 0..15
    const int lr = tid >> 1;          // 0..127
    const int lc = (tid & 1) * 4;     // 0 or 4

    const float* Ap = A + (size_t)(bm + lr) * K + lc;
    const float* Bp = B + (size_t)(bn + lr) * K + lc;

    float acc[8][8];
    #pragma unroll
    for (int i = 0; i < 8; i++)
        #pragma unroll
        for (int j = 0; j < 8; j++) acc[i][j] = 0.f;

    for (int k0 = 0; k0 < K; k0 += BK) {
        float4 a4 = *reinterpret_cast<const float4*>(Ap + k0);
        float4 b4 = *reinterpret_cast<const float4*>(Bp + k0);
        As[lc + 0][lr] = a4.x; As[lc + 1][lr] = a4.y; As[lc + 2][lr] = a4.z; As[lc + 3][lr] = a4.w;
        Bs[lc + 0][lr] = b4.x; Bs[lc + 1][lr] = b4.y; Bs[lc + 2][lr] = b4.z; Bs[lc + 3][lr] = b4.w;
        __syncthreads();
        #pragma unroll
        for (int k = 0; k < BK; k++) {
            float ra[8], rb[8];
            *(float4*)(ra)     = *(const float4*)&As[k][ty * 8];
            *(float4*)(ra + 4) = *(const float4*)&As[k][ty * 8 + 4];
            *(float4*)(rb)     = *(const float4*)&Bs[k][tx * 8];
            *(float4*)(rb + 4) = *(const float4*)&Bs[k][tx * 8 + 4];
            #pragma unroll
            for (int i = 0; i < 8; i++)
                #pragma unroll
                for (int j = 0; j < 8; j++)
                    acc[i][j] = fmaf(ra[i], rb[j], acc[i][j]);
        }
        __syncthreads();
    }
    #pragma unroll
    for (int i = 0; i < 8; i++) {
        int row = bm + ty * 8 + i;
        float* crow = C + (size_t)row * N + bn + tx * 8;
        #pragma unroll
        for (int j = 0; j < 8; j += 4) {
            float4 v;
            v.x = acc[i][j + 0]; v.y = acc[i][j + 1]; v.z = acc[i][j + 2]; v.w = acc[i][j + 3];
            if (bias) {
                int c = bn + tx * 8 + j;
                v.x += bias[c]; v.y += bias[c + 1]; v.z += bias[c + 2]; v.w += bias[c + 3];
            }
            if (resid) {
                float4 r = *(const float4*)(resid + (size_t)row * N + bn + tx * 8 + j);
                v.x += r.x; v.y += r.y; v.z += r.z; v.w += r.w;
            }
            *(float4*)(crow + j) = v;
        }
    }
}

// ---------------- MoE grouped gemm (per-expert segments, optional A gather) ----------------
template <bool GATHER>
__global__ __launch_bounds__(256, 2)
void moe_gemm_kernel(const float* __restrict__ Abase, const float* __restrict__ Bbase,
                     float* __restrict__ Cbase, int N, int K) {
    int e = blockIdx.z;
    int cnt = g_cnt[e];
    int bm = blockIdx.y * BM;
    if (bm >= cnt) return;
    int seg = g_off[e];
    int bn = blockIdx.x * BN;

    __shared__ float As[BK][BM];
    __shared__ float Bs[BK][BN];
    const int tid = threadIdx.x;
    const int ty = tid >> 4;
    const int tx = tid & 15;
    const int lr = tid >> 1;
    const int lc = (tid & 1) * 4;

    int gr = bm + lr;
    if (gr >= cnt) gr = cnt - 1;  // clamp (compute garbage, never stored)
    const float* Ap;
    if (GATHER) Ap = Abase + (size_t)g_tok[seg + gr] * K + lc;
    else        Ap = Abase + (size_t)(seg + gr) * K + lc;
    const float* Bp = Bbase + (size_t)e * N * K + (size_t)(bn + lr) * K + lc;

    float acc[8][8];
    #pragma unroll
    for (int i = 0; i < 8; i++)
        #pragma unroll
        for (int j = 0; j < 8; j++) acc[i][j] = 0.f;

    for (int k0 = 0; k0 < K; k0 += BK) {
        float4 a4 = *reinterpret_cast<const float4*>(Ap + k0);
        float4 b4 = *reinterpret_cast<const float4*>(Bp + k0);
        As[lc + 0][lr] = a4.x; As[lc + 1][lr] = a4.y; As[lc + 2][lr] = a4.z; As[lc + 3][lr] = a4.w;
        Bs[lc + 0][lr] = b4.x; Bs[lc + 1][lr] = b4.y; Bs[lc + 2][lr] = b4.z; Bs[lc + 3][lr] = b4.w;
        __syncthreads();
        #pragma unroll
        for (int k = 0; k < BK; k++) {
            float ra[8], rb[8];
            *(float4*)(ra)     = *(const float4*)&As[k][ty * 8];
            *(float4*)(ra + 4) = *(const float4*)&As[k][ty * 8 + 4];
            *(float4*)(rb)     = *(const float4*)&Bs[k][tx * 8];
            *(float4*)(rb + 4) = *(const float4*)&Bs[k][tx * 8 + 4];
            #pragma unroll
            for (int i = 0; i < 8; i++)
                #pragma unroll
                for (int j = 0; j < 8; j++)
                    acc[i][j] = fmaf(ra[i], rb[j], acc[i][j]);
        }
        __syncthreads();
    }
    #pragma unroll
    for (int i = 0; i < 8; i++) {
        int lrow = bm + ty * 8 + i;
        if (lrow >= cnt) continue;
        float* crow = Cbase + (size_t)(seg + lrow) * N + bn + tx * 8;
        #pragma unroll
        for (int j = 0; j < 8; j += 4) {
            float4 v;
            v.x = acc[i][j + 0]; v.y = acc[i][j + 1]; v.z = acc[i][j + 2]; v.w = acc[i][j + 3];
            *(float4*)(crow + j) = v;
        }
    }
}

// ---------------- RoPE (angle depends on HEAD index, per reference) ----------------
__global__ void rope_kernel(float* __restrict__ q) {
    int gid = blockIdx.x * 256 + threadIdx.x;   // over T * H * 64 pairs
    int t = gid >> 10;
    int r = gid & 1023;
    int h = r >> 6;
    int p = r & 63;
    // inv_freq = 10000^(-p/64); angle = h * inv_freq
    float ang = (float)h * expf(-(float)p * (9.210340371976184f / 64.f));
    float c = cosf(ang), s = sinf(ang);
    float* base = q + (size_t)t * Dd + h * DHh + 2 * p;
    float x1 = base[0], x2 = base[1];
    base[0] = x1 * c - x2 * s;
    base[1] = x1 * s + x2 * c;
}

// ---------------- flash-style causal attention ----------------
#define KT 32
__global__ void attn_kernel(const float* __restrict__ Q, const float* __restrict__ Kx,
                            const float* __restrict__ V, float* __restrict__ O) {
    __shared__ float Ks[KT][DHh];
    __shared__ float Vs[KT][DHh];
    int b = blockIdx.z, h = blockIdx.y, qg = blockIdx.x;
    int warp = threadIdx.x >> 5, lane = threadIdx.x & 31;
    int sq = qg * 8 + warp;
    int tq = b * Ss + sq;
    const float* qrow = Q + (size_t)tq * Dd + h * DHh;
    float qr[4];
    #pragma unroll
    for (int i = 0; i < 4; i++) qr[i] = qrow[lane + 32 * i];
    float m = -INFINITY, l = 0.f, o[4] = {0.f, 0.f, 0.f, 0.f};

    int ntiles = (qg * 8 + 8 + KT - 1) / KT;
    for (int kt = 0; kt < ntiles; kt++) {
        for (int idx = threadIdx.x; idx < KT * DHh; idx += 256) {
            int rr = idx >> 7, cc = idx & 127;
            size_t g = ((size_t)(b * Ss + kt * KT + rr)) * Dd + h * DHh + cc;
            Ks[rr][cc] = Kx[g];
            Vs[rr][cc] = V[g];
        }
        __syncthreads();
        int kmax = sq - kt * KT + 1;
        if (kmax > KT) kmax = KT;
        for (int j = 0; j < kmax; j++) {
            float p = qr[0] * Ks[j][lane] + qr[1] * Ks[j][lane + 32] +
                      qr[2] * Ks[j][lane + 64] + qr[3] * Ks[j][lane + 96];
            #pragma unroll
            for (int ofs = 16; ofs; ofs >>= 1) p += __shfl_xor_sync(0xffffffffu, p, ofs);
            p *= 0.08838834764831845f;  // 1/sqrt(128)
            float mnew = fmaxf(m, p);
            float corr = __expf(m - mnew);
            float w = __expf(p - mnew);
            l = l * corr + w;
            #pragma unroll
            for (int i = 0; i < 4; i++) o[i] = o[i] * corr + w * Vs[j][lane + 32 * i];
            m = mnew;
        }
        __syncthreads();
    }
    float invl = 1.f / l;
    float* orow = O + (size_t)tq * Dd + h * DHh;
    #pragma unroll
    for (int i = 0; i < 4; i++) orow[lane + 32 * i] = o[i] * invl;
}

// ---------------- router: logits, top-2, softmax weights ----------------
__global__ void router_kernel(const float* __restrict__ xn, const float* __restrict__ wr,
                              const float* __restrict__ br) {
    int t = blockIdx.x;
    int warp = threadIdx.x >> 5, lane = threadIdx.x & 31;
    const float* xr = xn + (size_t)t * Dd;
    const float* w = wr + (size_t)warp * Dd;
    float s = 0.f;
    for (int i = lane; i < Dd; i += 32) s += xr[i] * w[i];
    #pragma unroll
    for (int o = 16; o; o >>= 1) s += __shfl_xor_sync(0xffffffffu, s, o);
    __shared__ float lg[Ee];
    if (lane == 0) lg[warp] = s + br[warp];
    __syncthreads();
    if (threadIdx.x == 0) {
        int i0 = 0; float v0 = lg[0];
        for (int e = 1; e < Ee; e++) if (lg[e] > v0) { v0 = lg[e]; i0 = e; }
        int i1 = -1; float v1 = -INFINITY;
        for (int e = 0; e < Ee; e++) if (e != i0 && lg[e] > v1) { v1 = lg[e]; i1 = e; }
        float e1 = expf(v1 - v0);
        float w0 = 1.f / (1.f + e1);
        g_tid2[t * 2] = i0; g_tid2[t * 2 + 1] = i1;
        g_twt[t * 2] = w0;  g_twt[t * 2 + 1] = e1 * w0;
    }
}

// ---------------- single-block expert grouping ----------------
__global__ void build_lists_kernel() {
    __shared__ int cnt[Ee], run[Ee];
    int tid = threadIdx.x;
    if (tid < Ee) cnt[tid] = 0;
    __syncthreads();
    for (int i = tid; i < NPAIR; i += 256) atomicAdd(&cnt[g_tid2[i]], 1);
    __syncthreads();
    if (tid == 0) {
        int acc = 0;
        for (int e = 0; e < Ee; e++) { g_cnt[e] = cnt[e]; g_off[e] = acc; run[e] = acc; acc += cnt[e]; }
    }
    __syncthreads();
    for (int i = tid; i < NPAIR; i += 256) {
        int e = g_tid2[i];
        int pos = atomicAdd(&run[e], 1);
        g_tok[pos] = i >> 1;
        g_prow[i] = pos;
    }
}

// ---------------- h = silu(g) * u (in place into g_gb) ----------------
__global__ void silu_kernel() {
    size_t i = ((size_t)blockIdx.x * 256 + threadIdx.x) * 4;
    float4 g = *(float4*)(g_gb + i);
    float4 u = *(float4*)(g_ub + i);
    g.x = g.x / (1.f + expf(-g.x)) * u.x;
    g.y = g.y / (1.f + expf(-g.y)) * u.y;
    g.z = g.z / (1.f + expf(-g.z)) * u.z;
    g.w = g.w / (1.f + expf(-g.w)) * u.w;
    *(float4*)(g_gb + i) = g;
}

// ---------------- final combine: out = x2 + w0*eo0 + w1*eo1 ----------------
__global__ void combine_kernel(float* __restrict__ out) {
    int t = blockIdx.x;
    int r0 = g_prow[t * 2], r1 = g_prow[t * 2 + 1];
    float w0 = g_twt[t * 2], w1 = g_twt[t * 2 + 1];
    const float* e0 = g_eo + (size_t)r0 * Dd;
    const float* e1 = g_eo + (size_t)r1 * Dd;
    const float* xr = g_x2 + (size_t)t * Dd;
    float* orow = out + (size_t)t * Dd;
    for (int i = threadIdx.x; i < Dd; i += 256)
        orow[i] = xr[i] + w0 * e0[i] + w1 * e1[i];
}

// ---------------- host launcher ----------------
extern "C" void kernel_launch(void* const* d_in, const int* in_sizes, int n_in,
                              void* d_out, int out_size) {
    const float* x   = (const float*)d_in[0];
    const float* wq  = (const float*)d_in[1];
    const float* bq  = (const float*)d_in[2];
    const float* wk  = (const float*)d_in[3];
    const float* bk  = (const float*)d_in[4];
    const float* wv  = (const float*)d_in[5];
    const float* bv  = (const float*)d_in[6];
    const float* wo  = (const float*)d_in[7];
    const float* bo  = (const float*)d_in[8];
    const float* wr  = (const float*)d_in[9];
    const float* br  = (const float*)d_in[10];
    const float* wg  = (const float*)d_in[11];
    const float* wu  = (const float*)d_in[12];
    const float* wd  = (const float*)d_in[13];
    const float* r1w = (const float*)d_in[14];
    const float* r2w = (const float*)d_in[15];
    float* out = (float*)d_out;

    float *xn1, *q, *k, *v, *att, *x2, *xn2, *gb, *ub, *eo;
    cudaGetSymbolAddress((void**)&xn1, g_xn1);
    cudaGetSymbolAddress((void**)&q,   g_q);
    cudaGetSymbolAddress((void**)&k,   g_k);
    cudaGetSymbolAddress((void**)&v,   g_v);
    cudaGetSymbolAddress((void**)&att, g_att);
    cudaGetSymbolAddress((void**)&x2,  g_x2);
    cudaGetSymbolAddress((void**)&xn2, g_xn2);
    cudaGetSymbolAddress((void**)&gb,  g_gb);
    cudaGetSymbolAddress((void**)&ub,  g_ub);
    cudaGetSymbolAddress((void**)&eo,  g_eo);

    // 1) rmsnorm1
    rmsnorm_kernel<<<Tt, 256>>>(x, r1w, xn1);
    // 2) QKV projections
    sgemm_kernel<<<dim3(Dd / BN, Tt / BM), 256>>>(xn1, wq, q, bq, nullptr, Dd, Dd);
    sgemm_kernel<<<dim3(Dd / BN, Tt / BM), 256>>>(xn1, wk, k, bk, nullptr, Dd, Dd);
    sgemm_kernel<<<dim3(Dd / BN, Tt / BM), 256>>>(xn1, wv, v, bv, nullptr, Dd, Dd);
    // 3) RoPE on q, k
    rope_kernel<<<(Tt * Hh * 64) / 256, 256>>>(q);
    rope_kernel<<<(Tt * Hh * 64) / 256, 256>>>(k);
    // 4) causal attention
    attn_kernel<<<dim3(Ss / 8, Hh, Bb), 256>>>(q, k, v, att);
    // 5) output projection + residual
    sgemm_kernel<<<dim3(Dd / BN, Tt / BM), 256>>>(att, wo, x2, bo, x, Dd, Dd);
    // 6) rmsnorm2
    rmsnorm_kernel<<<Tt, 256>>>(x2, r2w, xn2);
    // 7) router + expert grouping
    router_kernel<<<Tt, 256>>>(xn2, wr, br);
    build_lists_kernel<<<1, 256>>>();
    // 8) sparse MoE: gate, up (gathered), silu*mul, down
    moe_gemm_kernel<true><<<dim3(HIDh / BN, Tt / BM, Ee), 256>>>(xn2, wg, gb, HIDh, Dd);
    moe_gemm_kernel<true><<<dim3(HIDh / BN, Tt / BM, Ee), 256>>>(xn2, wu, ub, HIDh, Dd);
    silu_kernel<<<((size_t)NPAIR * HIDh / 4) / 256, 256>>>();
    moe_gemm_kernel<false><<<dim3(Dd / BN, Tt / BM, Ee), 256>>>(gb, wd, eo, Dd, HIDh);
    // 9) combine
    combine_kernel<<<Tt, 256>>>(out);
}

// round 11
// speedup vs baseline: 1.6153x; 1.6125x over previous
#include <cuda_runtime.h>
#include <cuda_bf16.h>
#include <math.h>
#include <stdint.h>

// ---------------- problem constants ----------------
#define Bb   2
#define Ss   1024
#define Dd   2048
#define Hh   16
#define DHh  128
#define Ee   8
#define HIDh 4096
#define Tt   (Bb * Ss)       // 2048 tokens
#define NPAIR (Tt * 2)       // 4096 (token, expert) pairs

// ---------------- device scratch ----------------
__device__ float g_xn1[Tt * Dd];
__device__ float g_q  [Tt * Dd];
__device__ float g_k  [Tt * Dd];
__device__ float g_v  [Tt * Dd];
__device__ float g_att[Tt * Dd];
__device__ float g_x2 [Tt * Dd];
__device__ float g_xn2[Tt * Dd];
__device__ int   g_tid2[NPAIR];
__device__ float g_twt [NPAIR];
__device__ int   g_cnt[Ee];
__device__ int   g_off[Ee];
__device__ int   g_tok[NPAIR];
__device__ int   g_prow[NPAIR];
__device__ float g_gb[(size_t)NPAIR * HIDh];
__device__ float g_ub[(size_t)NPAIR * HIDh];
__device__ float g_eo[(size_t)NPAIR * Dd];

// ---------------- helpers ----------------
__device__ __forceinline__ uint32_t smem_u32(const void* p) {
    uint32_t a;
    asm("{ .reg .u64 t; cvta.to.shared.u64 t, %1; cvt.u32.u64 %0, t; }" : "=r"(a) : "l"(p));
    return a;
}
__device__ __forceinline__ uint32_t swz128(uint32_t off) {
    return off ^ ((off >> 3) & 0x70);
}
__device__ __forceinline__ void ldsm_x4(uint32_t* r, uint32_t addr) {
    asm volatile("ldmatrix.sync.aligned.m8n8.x4.shared.b16 {%0,%1,%2,%3}, [%4];"
                 : "=r"(r[0]), "=r"(r[1]), "=r"(r[2]), "=r"(r[3]) : "r"(addr));
}
__device__ __forceinline__ void mma_bf16(float* c, const uint32_t* a, uint32_t b0, uint32_t b1) {
    asm volatile("mma.sync.aligned.m16n8k16.row.col.f32.bf16.bf16.f32 "
                 "{%0,%1,%2,%3}, {%4,%5,%6,%7}, {%8,%9}, {%0,%1,%2,%3};"
                 : "+f"(c[0]), "+f"(c[1]), "+f"(c[2]), "+f"(c[3])
                 : "r"(a[0]), "r"(a[1]), "r"(a[2]), "r"(a[3]), "r"(b0), "r"(b1));
}
// split 8 fp32 -> 8 bf16 hi (uint4) + 8 bf16 lo (uint4)
__device__ __forceinline__ void split8(float4 v0, float4 v1, uint4& h, uint4& l) {
    float f[8] = {v0.x, v0.y, v0.z, v0.w, v1.x, v1.y, v1.z, v1.w};
    uint32_t hh[4], ll[4];
    #pragma unroll
    for (int i = 0; i < 4; i++) {
        __nv_bfloat16 h0 = __float2bfloat16(f[2*i]);
        __nv_bfloat16 h1 = __float2bfloat16(f[2*i+1]);
        float l0 = f[2*i]   - __bfloat162float(h0);
        float l1 = f[2*i+1] - __bfloat162float(h1);
        __nv_bfloat16 g0 = __float2bfloat16(l0);
        __nv_bfloat16 g1 = __float2bfloat16(l1);
        hh[i] = (uint32_t)(*(uint16_t*)&h0) | ((uint32_t)(*(uint16_t*)&h1) << 16);
        ll[i] = (uint32_t)(*(uint16_t*)&g0) | ((uint32_t)(*(uint16_t*)&g1) << 16);
    }
    h = make_uint4(hh[0], hh[1], hh[2], hh[3]);
    l = make_uint4(ll[0], ll[1], ll[2], ll[3]);
}

// ---------------- 3x-bf16 mma.sync GEMM: C[M,N] = A[M,K] @ B[N,K]^T ----------------
// CTA tile 128x128, K-tile = 32 fp32. Smem row layout (128B, SW128 swizzled):
//   row r: bytes [0,64) = hi bf16 k0..31, bytes [64,128) = lo bf16 k0..31.
// A tile 16KB + B tile 16KB per stage, double buffered.
#define STAGE_B  32768
#define TC_SMEM  (1024 + 2 * STAGE_B)

template <bool EXPERT, bool GATHER>
__global__ __launch_bounds__(256, 1)
void tc_gemm(const float* __restrict__ A, const float* __restrict__ Bw,
             float* __restrict__ C, const float* __restrict__ bias,
             const float* __restrict__ resid, int N, int K) {
    extern __shared__ float sm[];
    const int tid = threadIdx.x;

    int bm, bn, cnt = 0, seg = 0, e = 0;
    if (EXPERT) {
        e = blockIdx.z; cnt = g_cnt[e]; seg = g_off[e];
        bm = blockIdx.y * 128;
        if (bm >= cnt) return;
    } else {
        bm = blockIdx.y * 128;
    }
    bn = blockIdx.x * 128;

    const uint32_t sbase = smem_u32(sm);
    const uint32_t tbase = (sbase + 1023) & ~1023u;
    char* tp = (char*)sm + (tbase - sbase);

    // ---- global load mapping: 2 threads per row, 16 floats each ----
    const int arow = tid >> 1;
    const int asub = (tid & 1) << 4;     // 0 or 16 floats
    int grow = bm + arow;
    const float* Arow;
    if (EXPERT) {
        int cl = (grow < cnt) ? grow : (cnt - 1);
        if (GATHER) Arow = A + (size_t)g_tok[seg + cl] * K;
        else        Arow = A + (size_t)(seg + cl) * K;
    } else {
        Arow = A + (size_t)grow * K;
    }
    const float* Brow = (EXPERT ? Bw + (size_t)e * N * K : Bw) + (size_t)(bn + arow) * K;
    // byte offsets inside tile for this thread's stores
    const uint32_t hi_off = (uint32_t)arow * 128 + 2 * asub;   // 0 or 32

    // ---- warp tiling: 8 warps = 2 (m) x 4 (n), each 64x32 ----
    const int wid = tid >> 5, lane = tid & 31;
    const int wm = wid >> 2, wn = wid & 3;
    const int lrow = lane & 15;
    const int lcolb = (lane >> 4) * 16;

    float acc[4][4][4];
    #pragma unroll
    for (int i = 0; i < 4; i++)
        #pragma unroll
        for (int j = 0; j < 4; j++)
            #pragma unroll
            for (int q = 0; q < 4; q++) acc[i][j][q] = 0.f;

    const int NT = K >> 5;
    float4 pa[4], pb[4];

    // prologue: load tile 0, store to buf0
    {
        const float* Ap = Arow + asub;
        const float* Bp = Brow + asub;
        #pragma unroll
        for (int i = 0; i < 2; i++) {
            pa[2*i]   = *(const float4*)(Ap + i*8);
            pa[2*i+1] = *(const float4*)(Ap + i*8 + 4);
            pb[2*i]   = *(const float4*)(Bp + i*8);
            pb[2*i+1] = *(const float4*)(Bp + i*8 + 4);
        }
        char* ab = tp;
        char* bb = tp + 16384;
        #pragma unroll
        for (int i = 0; i < 2; i++) {
            uint4 h, l;
            split8(pa[2*i], pa[2*i+1], h, l);
            *(uint4*)(ab + swz128(hi_off + i*16))      = h;
            *(uint4*)(ab + swz128(hi_off + i*16 + 64)) = l;
            split8(pb[2*i], pb[2*i+1], h, l);
            *(uint4*)(bb + swz128(hi_off + i*16))      = h;
            *(uint4*)(bb + swz128(hi_off + i*16 + 64)) = l;
        }
    }
    __syncthreads();

    for (int t = 0; t < NT; ++t) {
        const int buf = t & 1;
        if (t + 1 < NT) {
            const float* Ap = Arow + (t+1)*32 + asub;
            const float* Bp = Brow + (t+1)*32 + asub;
            #pragma unroll
            for (int i = 0; i < 2; i++) {
                pa[2*i]   = *(const float4*)(Ap + i*8);
                pa[2*i+1] = *(const float4*)(Ap + i*8 + 4);
                pb[2*i]   = *(const float4*)(Bp + i*8);
                pb[2*i+1] = *(const float4*)(Bp + i*8 + 4);
            }
        }
        // ---- compute current buffer ----
        const uint32_t aB = tbase + buf * STAGE_B;
        const uint32_t bB = aB + 16384;
        #pragma unroll
        for (int s = 0; s < 2; s++) {
            uint32_t ah[4][4], al[4][4];
            #pragma unroll
            for (int i = 0; i < 4; i++) {
                uint32_t ro = (uint32_t)(wm*64 + i*16 + lrow) * 128 + s*32 + lcolb;
                ldsm_x4(ah[i], aB + swz128(ro));
                ldsm_x4(al[i], aB + swz128(ro + 64));
            }
            uint32_t bh[2][4], bl[2][4];
            #pragma unroll
            for (int p = 0; p < 2; p++) {
                uint32_t ro = (uint32_t)(wn*32 + p*16 + lrow) * 128 + s*32 + lcolb;
                ldsm_x4(bh[p], bB + swz128(ro));
                ldsm_x4(bl[p], bB + swz128(ro + 64));
            }
            #pragma unroll
            for (int i = 0; i < 4; i++)
                #pragma unroll
                for (int j = 0; j < 4; j++) {
                    const int p = j >> 1, o = j & 1;
                    mma_bf16(acc[i][j], ah[i], bh[p][o], bh[p][o + 2]);
                    mma_bf16(acc[i][j], ah[i], bl[p][o], bl[p][o + 2]);
                    mma_bf16(acc[i][j], al[i], bh[p][o], bh[p][o + 2]);
                }
        }
        // ---- store next tile into the other buffer ----
        if (t + 1 < NT) {
            char* ab = tp + ((t+1) & 1) * STAGE_B;
            char* bb = ab + 16384;
            #pragma unroll
            for (int i = 0; i < 2; i++) {
                uint4 h, l;
                split8(pa[2*i], pa[2*i+1], h, l);
                *(uint4*)(ab + swz128(hi_off + i*16))      = h;
                *(uint4*)(ab + swz128(hi_off + i*16 + 64)) = l;
                split8(pb[2*i], pb[2*i+1], h, l);
                *(uint4*)(bb + swz128(hi_off + i*16))      = h;
                *(uint4*)(bb + swz128(hi_off + i*16 + 64)) = l;
            }
        }
        __syncthreads();
    }

    // ---- epilogue: accumulators -> C (+bias)(+resid) ----
    const int qr = lane >> 2;           // row within 8
    const int qc = (lane & 3) * 2;      // col within 8
    #pragma unroll
    for (int i = 0; i < 4; i++) {
        const int lm0 = wm*64 + i*16 + qr;      // local m of c0/c1
        #pragma unroll
        for (int j = 0; j < 4; j++) {
            const int c = bn + wn*32 + j*8 + qc;
            float2 v0 = make_float2(acc[i][j][0], acc[i][j][1]);
            float2 v1 = make_float2(acc[i][j][2], acc[i][j][3]);
            if (bias) {
                float2 bv = *(const float2*)(bias + c);
                v0.x += bv.x; v0.y += bv.y;
                v1.x += bv.x; v1.y += bv.y;
            }
            if (EXPERT) {
                if (bm + lm0 < cnt) {
                    float* p0 = C + (size_t)(seg + bm + lm0) * N + c;
                    *(float2*)p0 = v0;
                }
                if (bm + lm0 + 8 < cnt) {
                    float* p1 = C + (size_t)(seg + bm + lm0 + 8) * N + c;
                    *(float2*)p1 = v1;
                }
            } else {
                const int r0 = bm + lm0;
                if (resid) {
                    float2 rv0 = *(const float2*)(resid + (size_t)r0 * N + c);
                    float2 rv1 = *(const float2*)(resid + (size_t)(r0 + 8) * N + c);
                    v0.x += rv0.x; v0.y += rv0.y;
                    v1.x += rv1.x; v1.y += rv1.y;
                }
                *(float2*)(C + (size_t)r0 * N + c)       = v0;
                *(float2*)(C + (size_t)(r0 + 8) * N + c) = v1;
            }
        }
    }
}

// ---------------- rmsnorm ----------------
__global__ void rmsnorm_kernel(const float* __restrict__ x,
                               const float* __restrict__ w,
                               float* __restrict__ out) {
    int t = blockIdx.x;
    const float* xr = x + (size_t)t * Dd;
    float ss = 0.f;
    for (int i = threadIdx.x; i < Dd; i += 256) { float vv = xr[i]; ss += vv * vv; }
    __shared__ float red[8];
    #pragma unroll
    for (int o = 16; o; o >>= 1) ss += __shfl_xor_sync(0xffffffffu, ss, o);
    if ((threadIdx.x & 31) == 0) red[threadIdx.x >> 5] = ss;
    __syncthreads();
    if (threadIdx.x < 8) {
        float v = red[threadIdx.x];
        #pragma unroll
        for (int o = 4; o; o >>= 1) v += __shfl_xor_sync(0xffu, v, o);
        if (threadIdx.x == 0) red[0] = v;
    }
    __syncthreads();
    float inv = 1.f / sqrtf(red[0] / (float)Dd + 1e-8f);
    float* orow = out + (size_t)t * Dd;
    for (int i = threadIdx.x; i < Dd; i += 256) orow[i] = xr[i] * inv * w[i];
}

// ---------------- RoPE (angle depends on HEAD index, per reference) ----------------
__global__ void rope_kernel(float* __restrict__ q) {
    int gid = blockIdx.x * 256 + threadIdx.x;
    int t = gid >> 10;
    int r = gid & 1023;
    int h = r >> 6;
    int p = r & 63;
    float ang = (float)h * expf(-(float)p * (9.210340371976184f / 64.f));
    float c = cosf(ang), s = sinf(ang);
    float* base = q + (size_t)t * Dd + h * DHh + 2 * p;
    float x1 = base[0], x2 = base[1];
    base[0] = x1 * c - x2 * s;
    base[1] = x1 * s + x2 * c;
}

// ---------------- flash-style causal attention ----------------
#define KT 32
__global__ void attn_kernel(const float* __restrict__ Q, const float* __restrict__ Kx,
                            const float* __restrict__ V, float* __restrict__ O) {
    __shared__ float Ks[KT][DHh];
    __shared__ float Vs[KT][DHh];
    int b = blockIdx.z, h = blockIdx.y, qg = blockIdx.x;
    int warp = threadIdx.x >> 5, lane = threadIdx.x & 31;
    int sq = qg * 8 + warp;
    int tq = b * Ss + sq;
    const float* qrow = Q + (size_t)tq * Dd + h * DHh;
    float qr[4];
    #pragma unroll
    for (int i = 0; i < 4; i++) qr[i] = qrow[lane + 32 * i];
    float m = -INFINITY, l = 0.f, o[4] = {0.f, 0.f, 0.f, 0.f};

    int ntiles = (qg * 8 + 8 + KT - 1) / KT;
    for (int kt = 0; kt < ntiles; kt++) {
        for (int idx = threadIdx.x; idx < KT * DHh; idx += 256) {
            int rr = idx >> 7, cc = idx & 127;
            size_t g = ((size_t)(b * Ss + kt * KT + rr)) * Dd + h * DHh + cc;
            Ks[rr][cc] = Kx[g];
            Vs[rr][cc] = V[g];
        }
        __syncthreads();
        int kmax = sq - kt * KT + 1;
        if (kmax > KT) kmax = KT;
        for (int j = 0; j < kmax; j++) {
            float p = qr[0] * Ks[j][lane] + qr[1] * Ks[j][lane + 32] +
                      qr[2] * Ks[j][lane + 64] + qr[3] * Ks[j][lane + 96];
            #pragma unroll
            for (int ofs = 16; ofs; ofs >>= 1) p += __shfl_xor_sync(0xffffffffu, p, ofs);
            p *= 0.08838834764831845f;
            float mnew = fmaxf(m, p);
            float corr = __expf(m - mnew);
            float w = __expf(p - mnew);
            l = l * corr + w;
            #pragma unroll
            for (int i = 0; i < 4; i++) o[i] = o[i] * corr + w * Vs[j][lane + 32 * i];
            m = mnew;
        }
        __syncthreads();
    }
    float invl = 1.f / l;
    float* orow = O + (size_t)tq * Dd + h * DHh;
    #pragma unroll
    for (int i = 0; i < 4; i++) orow[lane + 32 * i] = o[i] * invl;
}

// ---------------- router ----------------
__global__ void router_kernel(const float* __restrict__ xn, const float* __restrict__ wr,
                              const float* __restrict__ br) {
    int t = blockIdx.x;
    int warp = threadIdx.x >> 5, lane = threadIdx.x & 31;
    const float* xr = xn + (size_t)t * Dd;
    const float* w = wr + (size_t)warp * Dd;
    float s = 0.f;
    for (int i = lane; i < Dd; i += 32) s += xr[i] * w[i];
    #pragma unroll
    for (int o = 16; o; o >>= 1) s += __shfl_xor_sync(0xffffffffu, s, o);
    __shared__ float lg[Ee];
    if (lane == 0) lg[warp] = s + br[warp];
    __syncthreads();
    if (threadIdx.x == 0) {
        int i0 = 0; float v0 = lg[0];
        for (int e = 1; e < Ee; e++) if (lg[e] > v0) { v0 = lg[e]; i0 = e; }
        int i1 = -1; float v1 = -INFINITY;
        for (int e = 0; e < Ee; e++) if (e != i0 && lg[e] > v1) { v1 = lg[e]; i1 = e; }
        float e1 = expf(v1 - v0);
        float w0 = 1.f / (1.f + e1);
        g_tid2[t * 2] = i0; g_tid2[t * 2 + 1] = i1;
        g_twt[t * 2] = w0;  g_twt[t * 2 + 1] = e1 * w0;
    }
}

// ---------------- expert grouping ----------------
__global__ void build_lists_kernel() {
    __shared__ int cnt[Ee], run[Ee];
    int tid = threadIdx.x;
    if (tid < Ee) cnt[tid] = 0;
    __syncthreads();
    for (int i = tid; i < NPAIR; i += 256) atomicAdd(&cnt[g_tid2[i]], 1);
    __syncthreads();
    if (tid == 0) {
        int acc = 0;
        for (int e = 0; e < Ee; e++) { g_cnt[e] = cnt[e]; g_off[e] = acc; run[e] = acc; acc += cnt[e]; }
    }
    __syncthreads();
    for (int i = tid; i < NPAIR; i += 256) {
        int e = g_tid2[i];
        int pos = atomicAdd(&run[e], 1);
        g_tok[pos] = i >> 1;
        g_prow[i] = pos;
    }
}

// ---------------- silu * up ----------------
__global__ void silu_kernel() {
    size_t i = ((size_t)blockIdx.x * 256 + threadIdx.x) * 4;
    float4 g = *(float4*)(g_gb + i);
    float4 u = *(float4*)(g_ub + i);
    g.x = g.x / (1.f + expf(-g.x)) * u.x;
    g.y = g.y / (1.f + expf(-g.y)) * u.y;
    g.z = g.z / (1.f + expf(-g.z)) * u.z;
    g.w = g.w / (1.f + expf(-g.w)) * u.w;
    *(float4*)(g_gb + i) = g;
}

// ---------------- combine ----------------
__global__ void combine_kernel(float* __restrict__ out) {
    int t = blockIdx.x;
    int r0 = g_prow[t * 2], r1 = g_prow[t * 2 + 1];
    float w0 = g_twt[t * 2], w1 = g_twt[t * 2 + 1];
    const float* e0 = g_eo + (size_t)r0 * Dd;
    const float* e1 = g_eo + (size_t)r1 * Dd;
    const float* xr = g_x2 + (size_t)t * Dd;
    float* orow = out + (size_t)t * Dd;
    for (int i = threadIdx.x; i < Dd; i += 256)
        orow[i] = xr[i] + w0 * e0[i] + w1 * e1[i];
}

// ---------------- host launcher ----------------
extern "C" void kernel_launch(void* const* d_in, const int* in_sizes, int n_in,
                              void* d_out, int out_size) {
    const float* x   = (const float*)d_in[0];
    const float* wq  = (const float*)d_in[1];
    const float* bq  = (const float*)d_in[2];
    const float* wk  = (const float*)d_in[3];
    const float* bk  = (const float*)d_in[4];
    const float* wv  = (const float*)d_in[5];
    const float* bv  = (const float*)d_in[6];
    const float* wo  = (const float*)d_in[7];
    const float* bo  = (const float*)d_in[8];
    const float* wr  = (const float*)d_in[9];
    const float* br  = (const float*)d_in[10];
    const float* wg  = (const float*)d_in[11];
    const float* wu  = (const float*)d_in[12];
    const float* wd  = (const float*)d_in[13];
    const float* r1w = (const float*)d_in[14];
    const float* r2w = (const float*)d_in[15];
    float* out = (float*)d_out;

    float *xn1, *q, *k, *v, *att, *x2, *xn2, *gb, *ub, *eo;
    cudaGetSymbolAddress((void**)&xn1, g_xn1);
    cudaGetSymbolAddress((void**)&q,   g_q);
    cudaGetSymbolAddress((void**)&k,   g_k);
    cudaGetSymbolAddress((void**)&v,   g_v);
    cudaGetSymbolAddress((void**)&att, g_att);
    cudaGetSymbolAddress((void**)&x2,  g_x2);
    cudaGetSymbolAddress((void**)&xn2, g_xn2);
    cudaGetSymbolAddress((void**)&gb,  g_gb);
    cudaGetSymbolAddress((void**)&ub,  g_ub);
    cudaGetSymbolAddress((void**)&eo,  g_eo);

    cudaFuncSetAttribute((const void*)tc_gemm<false, false>,
                         cudaFuncAttributeMaxDynamicSharedMemorySize, TC_SMEM);
    cudaFuncSetAttribute((const void*)tc_gemm<true, true>,
                         cudaFuncAttributeMaxDynamicSharedMemorySize, TC_SMEM);
    cudaFuncSetAttribute((const void*)tc_gemm<true, false>,
                         cudaFuncAttributeMaxDynamicSharedMemorySize, TC_SMEM);

    // 1) rmsnorm1
    rmsnorm_kernel<<<Tt, 256>>>(x, r1w, xn1);
    // 2) QKV projections (3x-bf16 mma.sync)
    tc_gemm<false, false><<<dim3(Dd / 128, Tt / 128), 256, TC_SMEM>>>(xn1, wq, q, bq, nullptr, Dd, Dd);
    tc_gemm<false, false><<<dim3(Dd / 128, Tt / 128), 256, TC_SMEM>>>(xn1, wk, k, bk, nullptr, Dd, Dd);
    tc_gemm<false, false><<<dim3(Dd / 128, Tt / 128), 256, TC_SMEM>>>(xn1, wv, v, bv, nullptr, Dd, Dd);
    // 3) RoPE
    rope_kernel<<<(Tt * Hh * 64) / 256, 256>>>(q);
    rope_kernel<<<(Tt * Hh * 64) / 256, 256>>>(k);
    // 4) attention
    attn_kernel<<<dim3(Ss / 8, Hh, Bb), 256>>>(q, k, v, att);
    // 5) output projection + residual
    tc_gemm<false, false><<<dim3(Dd / 128, Tt / 128), 256, TC_SMEM>>>(att, wo, x2, bo, x, Dd, Dd);
    // 6) rmsnorm2
    rmsnorm_kernel<<<Tt, 256>>>(x2, r2w, xn2);
    // 7) router + grouping
    router_kernel<<<Tt, 256>>>(xn2, wr, br);
    build_lists_kernel<<<1, 256>>>();
    // 8) MoE: gate, up (gathered), silu*mul, down
    tc_gemm<true, true ><<<dim3(HIDh / 128, NPAIR / 128, Ee), 256, TC_SMEM>>>(xn2, wg, gb, nullptr, nullptr, HIDh, Dd);
    tc_gemm<true, true ><<<dim3(HIDh / 128, NPAIR / 128, Ee), 256, TC_SMEM>>>(xn2, wu, ub, nullptr, nullptr, HIDh, Dd);
    silu_kernel<<<((size_t)NPAIR * HIDh / 4) / 256, 256>>>();
    tc_gemm<true, false><<<dim3(Dd / 128, NPAIR / 128, Ee), 256, TC_SMEM>>>(gb, wd, eo, nullptr, nullptr, Dd, HIDh);
    // 9) combine
    combine_kernel<<<Tt, 256>>>(out);
}

// round 12
// speedup vs baseline: 1.9303x; 1.1950x over previous
#include <cuda_runtime.h>
#include <cuda_bf16.h>
#include <math.h>
#include <stdint.h>

// ---------------- problem constants ----------------
#define Bb   2
#define Ss   1024
#define Dd   2048
#define Hh   16
#define DHh  128
#define Ee   8
#define HIDh 4096
#define Tt   (Bb * Ss)       // 2048 tokens
#define NPAIR (Tt * 2)       // 4096 (token, expert) pairs

// ---------------- device scratch ----------------
// fp32
__device__ float g_q  [Tt * Dd];
__device__ float g_k  [Tt * Dd];
__device__ float g_v  [Tt * Dd];
__device__ float g_x2 [Tt * Dd];
__device__ float g_xn2[Tt * Dd];
__device__ float g_gb [(size_t)NPAIR * HIDh];
__device__ float g_ub [(size_t)NPAIR * HIDh];
__device__ float g_eo [(size_t)NPAIR * Dd];
// packed (bf16 hi << 16 | bf16 lo) per fp32 element
__device__ uint32_t g_pxn1[Tt * Dd];
__device__ uint32_t g_patt[Tt * Dd];
__device__ uint32_t g_pxn2[Tt * Dd];
__device__ uint32_t g_pgb [(size_t)NPAIR * HIDh];
__device__ uint32_t g_pwq [Dd * Dd];
__device__ uint32_t g_pwk [Dd * Dd];
__device__ uint32_t g_pwv [Dd * Dd];
__device__ uint32_t g_pwo [Dd * Dd];
__device__ uint32_t g_pwg [(size_t)Ee * HIDh * Dd];
__device__ uint32_t g_pwu [(size_t)Ee * HIDh * Dd];
__device__ uint32_t g_pwd [(size_t)Ee * Dd * HIDh];
// routing
__device__ int   g_tid2[NPAIR];
__device__ float g_twt [NPAIR];
__device__ int   g_cnt[Ee];
__device__ int   g_off[Ee];
__device__ int   g_tok[NPAIR];
__device__ int   g_prow[NPAIR];

// ---------------- helpers ----------------
__device__ __forceinline__ uint32_t smem_u32(const void* p) {
    uint32_t a;
    asm("{ .reg .u64 t; cvta.to.shared.u64 t, %1; cvt.u32.u64 %0, t; }" : "=r"(a) : "l"(p));
    return a;
}
__device__ __forceinline__ uint32_t swz128(uint32_t off) {
    return off ^ ((off >> 3) & 0x70);
}
__device__ __forceinline__ void ldsm_x4(uint32_t* r, uint32_t addr) {
    asm volatile("ldmatrix.sync.aligned.m8n8.x4.shared.b16 {%0,%1,%2,%3}, [%4];"
                 : "=r"(r[0]), "=r"(r[1]), "=r"(r[2]), "=r"(r[3]) : "r"(addr));
}
__device__ __forceinline__ void mma_bf16(float* c, const uint32_t* a, uint32_t b0, uint32_t b1) {
    asm volatile("mma.sync.aligned.m16n8k16.row.col.f32.bf16.bf16.f32 "
                 "{%0,%1,%2,%3}, {%4,%5,%6,%7}, {%8,%9}, {%0,%1,%2,%3};"
                 : "+f"(c[0]), "+f"(c[1]), "+f"(c[2]), "+f"(c[3])
                 : "r"(a[0]), "r"(a[1]), "r"(a[2]), "r"(a[3]), "r"(b0), "r"(b1));
}
__device__ __forceinline__ uint32_t packsplit1(float f) {
    __nv_bfloat16 h = __float2bfloat16(f);
    float r = f - __bfloat162float(h);
    __nv_bfloat16 lo = __float2bfloat16(r);
    return ((uint32_t)(*(uint16_t*)&h) << 16) | (uint32_t)(*(uint16_t*)&lo);
}

// ---------------- pack conversion (fp32 -> packed u32) ----------------
__global__ void pack_kernel(const float* __restrict__ in, uint32_t* __restrict__ out) {
    size_t i = ((size_t)blockIdx.x * 256 + threadIdx.x) * 4;
    float4 v = *(const float4*)(in + i);
    uint4 r;
    r.x = packsplit1(v.x); r.y = packsplit1(v.y);
    r.z = packsplit1(v.z); r.w = packsplit1(v.w);
    *(uint4*)(out + i) = r;
}

// ---------------- 3x-bf16 mma.sync GEMM on packed inputs ----------------
// C[M,N] = A[M,K] @ B[N,K]^T. CTA tile 128x128, K-tile 32 elems.
// Smem row (128B, swz128): [0,64) hi bf16 k0..31, [64,128) lo bf16 k0..31.
#define STAGE_B  32768
#define TC_SMEM  (1024 + 2 * STAGE_B)

template <bool EXPERT, bool GATHER>
__global__ __launch_bounds__(256, 1)
void tc_gemm(const uint32_t* __restrict__ A, const uint32_t* __restrict__ Bw,
             float* __restrict__ C, const float* __restrict__ bias,
             const float* __restrict__ resid, int N, int K) {
    extern __shared__ float sm[];
    const int tid = threadIdx.x;

    int bm, bn, cnt = 0, seg = 0, e = 0;
    if (EXPERT) {
        e = blockIdx.z; cnt = g_cnt[e]; seg = g_off[e];
        bm = blockIdx.y * 128;
        if (bm >= cnt) return;
    } else {
        bm = blockIdx.y * 128;
    }
    bn = blockIdx.x * 128;

    const uint32_t sbase = smem_u32(sm);
    const uint32_t tbase = (sbase + 1023) & ~1023u;
    char* tp = (char*)sm + (tbase - sbase);

    // ---- global load mapping: 2 threads per row, 16 u32 each ----
    const int arow = tid >> 1;
    const int asub = (tid & 1) << 4;     // 0 or 16 elems
    int grow = bm + arow;
    const uint32_t* Arow;
    if (EXPERT) {
        int cl = (grow < cnt) ? grow : (cnt - 1);
        if (GATHER) Arow = A + (size_t)g_tok[seg + cl] * K;
        else        Arow = A + (size_t)(seg + cl) * K;
    } else {
        Arow = A + (size_t)grow * K;
    }
    const uint32_t* Brow = (EXPERT ? Bw + (size_t)e * N * K : Bw) + (size_t)(bn + arow) * K;
    const uint32_t hi_off = (uint32_t)arow * 128 + 2 * asub;   // byte off: 0 or 32

    // ---- warp tiling: 8 warps = 2(m) x 4(n), each 64x32 ----
    const int wid = tid >> 5, lane = tid & 31;
    const int wm = wid >> 2, wn = wid & 3;
    const int lrow = lane & 15;
    const int lcolb = (lane >> 4) * 16;

    float acc[4][4][4];
    #pragma unroll
    for (int i = 0; i < 4; i++)
        #pragma unroll
        for (int j = 0; j < 4; j++)
            #pragma unroll
            for (int q = 0; q < 4; q++) acc[i][j][q] = 0.f;

    const int NT = K >> 5;
    uint4 ra[4], rb[4];

    // store 16 packed elems -> hi/lo halves via PRMT
    auto stash = [&](char* base, const uint4* r) {
        uint32_t h0 = __byte_perm(r[0].x, r[0].y, 0x7632);
        uint32_t h1 = __byte_perm(r[0].z, r[0].w, 0x7632);
        uint32_t h2 = __byte_perm(r[1].x, r[1].y, 0x7632);
        uint32_t h3 = __byte_perm(r[1].z, r[1].w, 0x7632);
        uint32_t h4 = __byte_perm(r[2].x, r[2].y, 0x7632);
        uint32_t h5 = __byte_perm(r[2].z, r[2].w, 0x7632);
        uint32_t h6 = __byte_perm(r[3].x, r[3].y, 0x7632);
        uint32_t h7 = __byte_perm(r[3].z, r[3].w, 0x7632);
        uint32_t l0 = __byte_perm(r[0].x, r[0].y, 0x5410);
        uint32_t l1 = __byte_perm(r[0].z, r[0].w, 0x5410);
        uint32_t l2 = __byte_perm(r[1].x, r[1].y, 0x5410);
        uint32_t l3 = __byte_perm(r[1].z, r[1].w, 0x5410);
        uint32_t l4 = __byte_perm(r[2].x, r[2].y, 0x5410);
        uint32_t l5 = __byte_perm(r[2].z, r[2].w, 0x5410);
        uint32_t l6 = __byte_perm(r[3].x, r[3].y, 0x5410);
        uint32_t l7 = __byte_perm(r[3].z, r[3].w, 0x5410);
        *(uint4*)(base + swz128(hi_off))       = make_uint4(h0, h1, h2, h3);
        *(uint4*)(base + swz128(hi_off + 16))  = make_uint4(h4, h5, h6, h7);
        *(uint4*)(base + swz128(hi_off + 64))  = make_uint4(l0, l1, l2, l3);
        *(uint4*)(base + swz128(hi_off + 80))  = make_uint4(l4, l5, l6, l7);
    };

    // prologue: tile 0 -> buf0
    {
        const uint32_t* Ap = Arow + asub;
        const uint32_t* Bp = Brow + asub;
        #pragma unroll
        for (int i = 0; i < 4; i++) {
            ra[i] = *(const uint4*)(Ap + i * 4);
            rb[i] = *(const uint4*)(Bp + i * 4);
        }
        stash(tp, ra);
        stash(tp + 16384, rb);
    }
    __syncthreads();

    for (int t = 0; t < NT; ++t) {
        const int buf = t & 1;
        if (t + 1 < NT) {
            const uint32_t* Ap = Arow + (t + 1) * 32 + asub;
            const uint32_t* Bp = Brow + (t + 1) * 32 + asub;
            #pragma unroll
            for (int i = 0; i < 4; i++) {
                ra[i] = *(const uint4*)(Ap + i * 4);
                rb[i] = *(const uint4*)(Bp + i * 4);
            }
        }
        // ---- compute current buffer ----
        const uint32_t aB = tbase + buf * STAGE_B;
        const uint32_t bB = aB + 16384;
        #pragma unroll
        for (int s = 0; s < 2; s++) {
            uint32_t ah[4][4], al[4][4];
            #pragma unroll
            for (int i = 0; i < 4; i++) {
                uint32_t ro = (uint32_t)(wm * 64 + i * 16 + lrow) * 128 + s * 32 + lcolb;
                ldsm_x4(ah[i], aB + swz128(ro));
                ldsm_x4(al[i], aB + swz128(ro + 64));
            }
            uint32_t bh[2][4], bl[2][4];
            #pragma unroll
            for (int p = 0; p < 2; p++) {
                uint32_t ro = (uint32_t)(wn * 32 + p * 16 + lrow) * 128 + s * 32 + lcolb;
                ldsm_x4(bh[p], bB + swz128(ro));
                ldsm_x4(bl[p], bB + swz128(ro + 64));
            }
            #pragma unroll
            for (int i = 0; i < 4; i++)
                #pragma unroll
                for (int j = 0; j < 4; j++) {
                    const int p = j >> 1, o = j & 1;
                    mma_bf16(acc[i][j], ah[i], bh[p][o], bh[p][o + 2]);
                    mma_bf16(acc[i][j], ah[i], bl[p][o], bl[p][o + 2]);
                    mma_bf16(acc[i][j], al[i], bh[p][o], bh[p][o + 2]);
                }
        }
        // ---- store next tile ----
        if (t + 1 < NT) {
            char* ab = tp + ((t + 1) & 1) * STAGE_B;
            stash(ab, ra);
            stash(ab + 16384, rb);
        }
        __syncthreads();
    }

    // ---- epilogue ----
    const int qr = lane >> 2;
    const int qc = (lane & 3) * 2;
    #pragma unroll
    for (int i = 0; i < 4; i++) {
        const int lm0 = wm * 64 + i * 16 + qr;
        #pragma unroll
        for (int j = 0; j < 4; j++) {
            const int c = bn + wn * 32 + j * 8 + qc;
            float2 v0 = make_float2(acc[i][j][0], acc[i][j][1]);
            float2 v1 = make_float2(acc[i][j][2], acc[i][j][3]);
            if (bias) {
                float2 bv = *(const float2*)(bias + c);
                v0.x += bv.x; v0.y += bv.y;
                v1.x += bv.x; v1.y += bv.y;
            }
            if (EXPERT) {
                if (bm + lm0 < cnt)
                    *(float2*)(C + (size_t)(seg + bm + lm0) * N + c) = v0;
                if (bm + lm0 + 8 < cnt)
                    *(float2*)(C + (size_t)(seg + bm + lm0 + 8) * N + c) = v1;
            } else {
                const int r0 = bm + lm0;
                if (resid) {
                    float2 rv0 = *(const float2*)(resid + (size_t)r0 * N + c);
                    float2 rv1 = *(const float2*)(resid + (size_t)(r0 + 8) * N + c);
                    v0.x += rv0.x; v0.y += rv0.y;
                    v1.x += rv1.x; v1.y += rv1.y;
                }
                *(float2*)(C + (size_t)r0 * N + c)       = v0;
                *(float2*)(C + (size_t)(r0 + 8) * N + c) = v1;
            }
        }
    }
}

// ---------------- rmsnorm (optional fp32 + packed outputs) ----------------
__global__ void rmsnorm_kernel(const float* __restrict__ x,
                               const float* __restrict__ w,
                               float* __restrict__ out_f32,
                               uint32_t* __restrict__ out_pk) {
    int t = blockIdx.x;
    const float* xr = x + (size_t)t * Dd;
    float ss = 0.f;
    for (int i = threadIdx.x; i < Dd; i += 256) { float vv = xr[i]; ss += vv * vv; }
    __shared__ float red[8];
    #pragma unroll
    for (int o = 16; o; o >>= 1) ss += __shfl_xor_sync(0xffffffffu, ss, o);
    if ((threadIdx.x & 31) == 0) red[threadIdx.x >> 5] = ss;
    __syncthreads();
    if (threadIdx.x < 8) {
        float v = red[threadIdx.x];
        #pragma unroll
        for (int o = 4; o; o >>= 1) v += __shfl_xor_sync(0xffu, v, o);
        if (threadIdx.x == 0) red[0] = v;
    }
    __syncthreads();
    float inv = 1.f / sqrtf(red[0] / (float)Dd + 1e-8f);
    for (int i = threadIdx.x; i < Dd; i += 256) {
        float v = xr[i] * inv * w[i];
        if (out_f32) out_f32[(size_t)t * Dd + i] = v;
        if (out_pk)  out_pk [(size_t)t * Dd + i] = packsplit1(v);
    }
}

// ---------------- RoPE (angle depends on HEAD index, per reference) ----------------
__global__ void rope_kernel(float* __restrict__ q) {
    int gid = blockIdx.x * 256 + threadIdx.x;
    int t = gid >> 10;
    int r = gid & 1023;
    int h = r >> 6;
    int p = r & 63;
    float ang = (float)h * expf(-(float)p * (9.210340371976184f / 64.f));
    float c = cosf(ang), s = sinf(ang);
    float* base = q + (size_t)t * Dd + h * DHh + 2 * p;
    float x1 = base[0], x2 = base[1];
    base[0] = x1 * c - x2 * s;
    base[1] = x1 * s + x2 * c;
}

// ---------------- attention: 32 q/block, 4 q/warp, lane-per-key ----------------
// dyn smem: Qs[32][128] | Ks[32][132] | Vs[32][132]  (floats)
#define AQS 0
#define AKS 4096
#define AVS (4096 + 32 * 132)
#define ATT_SMEM ((4096 + 2 * 32 * 132) * 4)

__global__ __launch_bounds__(256)
void attn_kernel(const float* __restrict__ Q, const float* __restrict__ Kx,
                 const float* __restrict__ V, uint32_t* __restrict__ O) {
    extern __shared__ float smf[];
    const int b = blockIdx.z, h = blockIdx.y, qg = blockIdx.x;
    const int tid = threadIdx.x;
    const int warp = tid >> 5, lane = tid & 31;

    // load Q block (32 rows x 128)
    for (int c = tid; c < 1024; c += 256) {
        int rr = c >> 5, c4 = (c & 31) * 4;
        *(float4*)&smf[AQS + rr * 128 + c4] =
            *(const float4*)&Q[((size_t)(b * Ss + qg * 32 + rr)) * Dd + h * DHh + c4];
    }

    const int q0 = qg * 32 + warp * 4;          // first q row of this warp
    float m[4], l[4];
    float4 o[4];
    #pragma unroll
    for (int q = 0; q < 4; q++) {
        m[q] = -INFINITY; l[q] = 0.f;
        o[q] = make_float4(0.f, 0.f, 0.f, 0.f);
    }

    const int ntiles = qg + 1;
    for (int kt = 0; kt < ntiles; kt++) {
        __syncthreads();
        for (int c = tid; c < 1024; c += 256) {
            int rr = c >> 5, c4 = (c & 31) * 4;
            size_t g = ((size_t)(b * Ss + kt * 32 + rr)) * Dd + h * DHh + c4;
            *(float4*)&smf[AKS + rr * 132 + c4] = *(const float4*)&Kx[g];
            *(float4*)&smf[AVS + rr * 132 + c4] = *(const float4*)&V[g];
        }
        __syncthreads();

        // ---- scores: lane owns key (kt*32 + lane), full dot for 4 q ----
        const int kj = kt * 32 + lane;
        float4 s4[4];
        #pragma unroll
        for (int q = 0; q < 4; q++) s4[q] = make_float4(0.f, 0.f, 0.f, 0.f);
        const float* krow = &smf[AKS + lane * 132];
        #pragma unroll 8
        for (int c4 = 0; c4 < 32; c4++) {
            float4 kv = *(const float4*)&krow[c4 * 4];
            #pragma unroll
            for (int q = 0; q < 4; q++) {
                float4 qv = *(const float4*)&smf[AQS + (warp * 4 + q) * 128 + c4 * 4];
                s4[q].x = fmaf(qv.x, kv.x, s4[q].x);
                s4[q].y = fmaf(qv.y, kv.y, s4[q].y);
                s4[q].z = fmaf(qv.z, kv.z, s4[q].z);
                s4[q].w = fmaf(qv.w, kv.w, s4[q].w);
            }
        }
        float s[4], w[4];
        #pragma unroll
        for (int q = 0; q < 4; q++) {
            float v = (s4[q].x + s4[q].y) + (s4[q].z + s4[q].w);
            s[q] = (kj <= q0 + q) ? v * 0.08838834764831845f : -INFINITY;
        }
        // tile max per q (butterfly; 4 independent chains)
        float tm[4];
        #pragma unroll
        for (int q = 0; q < 4; q++) tm[q] = s[q];
        #pragma unroll
        for (int ofs = 16; ofs; ofs >>= 1)
            #pragma unroll
            for (int q = 0; q < 4; q++)
                tm[q] = fmaxf(tm[q], __shfl_xor_sync(0xffffffffu, tm[q], ofs));
        float ts[4];
        #pragma unroll
        for (int q = 0; q < 4; q++) {
            float mnew = fmaxf(m[q], tm[q]);
            float corr = __expf(m[q] - mnew);       // m=-inf first tile -> 0
            w[q] = __expf(s[q] - mnew);             // masked -> exp(-inf)=0
            m[q] = mnew;
            l[q] *= corr;
            o[q].x *= corr; o[q].y *= corr; o[q].z *= corr; o[q].w *= corr;
            ts[q] = w[q];
        }
        #pragma unroll
        for (int ofs = 16; ofs; ofs >>= 1)
            #pragma unroll
            for (int q = 0; q < 4; q++)
                ts[q] += __shfl_xor_sync(0xffffffffu, ts[q], ofs);
        #pragma unroll
        for (int q = 0; q < 4; q++) l[q] += ts[q];

        // ---- V accumulate: o[q][d4] += w_j * V[j][d4], d4 = lane*4.. ----
        const float* vcol = &smf[AVS + lane * 4];
        #pragma unroll 4
        for (int j = 0; j < 32; j++) {
            float4 vv = *(const float4*)&vcol[j * 132];
            #pragma unroll
            for (int q = 0; q < 4; q++) {
                float wq = __shfl_sync(0xffffffffu, w[q], j);
                o[q].x = fmaf(wq, vv.x, o[q].x);
                o[q].y = fmaf(wq, vv.y, o[q].y);
                o[q].z = fmaf(wq, vv.z, o[q].z);
                o[q].w = fmaf(wq, vv.w, o[q].w);
            }
        }
    }

    // write packed output; lane owns d = lane*4..lane*4+3
    #pragma unroll
    for (int q = 0; q < 4; q++) {
        float inv = 1.f / l[q];
        uint4 pv;
        pv.x = packsplit1(o[q].x * inv);
        pv.y = packsplit1(o[q].y * inv);
        pv.z = packsplit1(o[q].z * inv);
        pv.w = packsplit1(o[q].w * inv);
        uint32_t* orow = O + ((size_t)(b * Ss + q0 + q)) * Dd + h * DHh + lane * 4;
        *(uint4*)orow = pv;
    }
}

// ---------------- router ----------------
__global__ void router_kernel(const float* __restrict__ xn, const float* __restrict__ wr,
                              const float* __restrict__ br) {
    int t = blockIdx.x;
    int warp = threadIdx.x >> 5, lane = threadIdx.x & 31;
    const float* xr = xn + (size_t)t * Dd;
    const float* w = wr + (size_t)warp * Dd;
    float s = 0.f;
    for (int i = lane; i < Dd; i += 32) s += xr[i] * w[i];
    #pragma unroll
    for (int o = 16; o; o >>= 1) s += __shfl_xor_sync(0xffffffffu, s, o);
    __shared__ float lg[Ee];
    if (lane == 0) lg[warp] = s + br[warp];
    __syncthreads();
    if (threadIdx.x == 0) {
        int i0 = 0; float v0 = lg[0];
        for (int e = 1; e < Ee; e++) if (lg[e] > v0) { v0 = lg[e]; i0 = e; }
        int i1 = -1; float v1 = -INFINITY;
        for (int e = 0; e < Ee; e++) if (e != i0 && lg[e] > v1) { v1 = lg[e]; i1 = e; }
        float e1 = expf(v1 - v0);
        float w0 = 1.f / (1.f + e1);
        g_tid2[t * 2] = i0; g_tid2[t * 2 + 1] = i1;
        g_twt[t * 2] = w0;  g_twt[t * 2 + 1] = e1 * w0;
    }
}

// ---------------- expert grouping ----------------
__global__ void build_lists_kernel() {
    __shared__ int cnt[Ee], run[Ee];
    int tid = threadIdx.x;
    if (tid < Ee) cnt[tid] = 0;
    __syncthreads();
    for (int i = tid; i < NPAIR; i += 256) atomicAdd(&cnt[g_tid2[i]], 1);
    __syncthreads();
    if (tid == 0) {
        int acc = 0;
        for (int e = 0; e < Ee; e++) { g_cnt[e] = cnt[e]; g_off[e] = acc; run[e] = acc; acc += cnt[e]; }
    }
    __syncthreads();
    for (int i = tid; i < NPAIR; i += 256) {
        int e = g_tid2[i];
        int pos = atomicAdd(&run[e], 1);
        g_tok[pos] = i >> 1;
        g_prow[i] = pos;
    }
}

// ---------------- silu * up -> packed ----------------
__global__ void silu_kernel() {
    size_t i = ((size_t)blockIdx.x * 256 + threadIdx.x) * 4;
    float4 g = *(float4*)(g_gb + i);
    float4 u = *(float4*)(g_ub + i);
    g.x = g.x / (1.f + __expf(-g.x)) * u.x;
    g.y = g.y / (1.f + __expf(-g.y)) * u.y;
    g.z = g.z / (1.f + __expf(-g.z)) * u.z;
    g.w = g.w / (1.f + __expf(-g.w)) * u.w;
    uint4 p;
    p.x = packsplit1(g.x); p.y = packsplit1(g.y);
    p.z = packsplit1(g.z); p.w = packsplit1(g.w);
    *(uint4*)(g_pgb + i) = p;
}

// ---------------- combine ----------------
__global__ void combine_kernel(float* __restrict__ out) {
    int t = blockIdx.x;
    int r0 = g_prow[t * 2], r1 = g_prow[t * 2 + 1];
    float w0 = g_twt[t * 2], w1 = g_twt[t * 2 + 1];
    const float* e0 = g_eo + (size_t)r0 * Dd;
    const float* e1 = g_eo + (size_t)r1 * Dd;
    const float* xr = g_x2 + (size_t)t * Dd;
    float* orow = out + (size_t)t * Dd;
    for (int i = threadIdx.x; i < Dd; i += 256)
        orow[i] = xr[i] + w0 * e0[i] + w1 * e1[i];
}

// ---------------- host launcher ----------------
extern "C" void kernel_launch(void* const* d_in, const int* in_sizes, int n_in,
                              void* d_out, int out_size) {
    const float* x   = (const float*)d_in[0];
    const float* wq  = (const float*)d_in[1];
    const float* bq  = (const float*)d_in[2];
    const float* wk  = (const float*)d_in[3];
    const float* bk  = (const float*)d_in[4];
    const float* wv  = (const float*)d_in[5];
    const float* bv  = (const float*)d_in[6];
    const float* wo  = (const float*)d_in[7];
    const float* bo  = (const float*)d_in[8];
    const float* wr  = (const float*)d_in[9];
    const float* br  = (const float*)d_in[10];
    const float* wg  = (const float*)d_in[11];
    const float* wu  = (const float*)d_in[12];
    const float* wd  = (const float*)d_in[13];
    const float* r1w = (const float*)d_in[14];
    const float* r2w = (const float*)d_in[15];
    float* out = (float*)d_out;

    float *q, *k, *v, *x2, *xn2, *gb, *ub, *eo;
    uint32_t *pxn1, *patt, *pxn2, *pgb;
    uint32_t *pwq, *pwk, *pwv, *pwo, *pwg, *pwu, *pwd;
    cudaGetSymbolAddress((void**)&q,    g_q);
    cudaGetSymbolAddress((void**)&k,    g_k);
    cudaGetSymbolAddress((void**)&v,    g_v);
    cudaGetSymbolAddress((void**)&x2,   g_x2);
    cudaGetSymbolAddress((void**)&xn2,  g_xn2);
    cudaGetSymbolAddress((void**)&gb,   g_gb);
    cudaGetSymbolAddress((void**)&ub,   g_ub);
    cudaGetSymbolAddress((void**)&eo,   g_eo);
    cudaGetSymbolAddress((void**)&pxn1, g_pxn1);
    cudaGetSymbolAddress((void**)&patt, g_patt);
    cudaGetSymbolAddress((void**)&pxn2, g_pxn2);
    cudaGetSymbolAddress((void**)&pgb,  g_pgb);
    cudaGetSymbolAddress((void**)&pwq,  g_pwq);
    cudaGetSymbolAddress((void**)&pwk,  g_pwk);
    cudaGetSymbolAddress((void**)&pwv,  g_pwv);
    cudaGetSymbolAddress((void**)&pwo,  g_pwo);
    cudaGetSymbolAddress((void**)&pwg,  g_pwg);
    cudaGetSymbolAddress((void**)&pwu,  g_pwu);
    cudaGetSymbolAddress((void**)&pwd,  g_pwd);

    cudaFuncSetAttribute((const void*)tc_gemm<false, false>,
                         cudaFuncAttributeMaxDynamicSharedMemorySize, TC_SMEM);
    cudaFuncSetAttribute((const void*)tc_gemm<true, true>,
                         cudaFuncAttributeMaxDynamicSharedMemorySize, TC_SMEM);
    cudaFuncSetAttribute((const void*)tc_gemm<true, false>,
                         cudaFuncAttributeMaxDynamicSharedMemorySize, TC_SMEM);
    cudaFuncSetAttribute((const void*)attn_kernel,
                         cudaFuncAttributeMaxDynamicSharedMemorySize, ATT_SMEM);

    // 0) pack weights (hi/lo bf16 split, one u32 per fp32 elem)
    pack_kernel<<<Dd * Dd / 1024, 256>>>(wq, pwq);
    pack_kernel<<<Dd * Dd / 1024, 256>>>(wk, pwk);
    pack_kernel<<<Dd * Dd / 1024, 256>>>(wv, pwv);
    pack_kernel<<<Dd * Dd / 1024, 256>>>(wo, pwo);
    pack_kernel<<<Ee * HIDh * Dd / 1024, 256>>>(wg, pwg);
    pack_kernel<<<Ee * HIDh * Dd / 1024, 256>>>(wu, pwu);
    pack_kernel<<<Ee * Dd * HIDh / 1024, 256>>>(wd, pwd);

    // 1) rmsnorm1 -> packed only
    rmsnorm_kernel<<<Tt, 256>>>(x, r1w, nullptr, pxn1);
    // 2) QKV projections
    tc_gemm<false, false><<<dim3(Dd / 128, Tt / 128), 256, TC_SMEM>>>(pxn1, pwq, q, bq, nullptr, Dd, Dd);
    tc_gemm<false, false><<<dim3(Dd / 128, Tt / 128), 256, TC_SMEM>>>(pxn1, pwk, k, bk, nullptr, Dd, Dd);
    tc_gemm<false, false><<<dim3(Dd / 128, Tt / 128), 256, TC_SMEM>>>(pxn1, pwv, v, bv, nullptr, Dd, Dd);
    // 3) RoPE
    rope_kernel<<<(Tt * Hh * 64) / 256, 256>>>(q);
    rope_kernel<<<(Tt * Hh * 64) / 256, 256>>>(k);
    // 4) attention -> packed att
    attn_kernel<<<dim3(Ss / 32, Hh, Bb), 256, ATT_SMEM>>>(q, k, v, patt);
    // 5) output projection + residual
    tc_gemm<false, false><<<dim3(Dd / 128, Tt / 128), 256, TC_SMEM>>>(patt, pwo, x2, bo, x, Dd, Dd);
    // 6) rmsnorm2 -> fp32 (router) + packed (MoE)
    rmsnorm_kernel<<<Tt, 256>>>(x2, r2w, xn2, pxn2);
    // 7) router + grouping
    router_kernel<<<Tt, 256>>>(xn2, wr, br);
    build_lists_kernel<<<1, 256>>>();
    // 8) MoE
    tc_gemm<true, true ><<<dim3(HIDh / 128, NPAIR / 128, Ee), 256, TC_SMEM>>>(pxn2, pwg, gb, nullptr, nullptr, HIDh, Dd);
    tc_gemm<true, true ><<<dim3(HIDh / 128, NPAIR / 128, Ee), 256, TC_SMEM>>>(pxn2, pwu, ub, nullptr, nullptr, HIDh, Dd);
    silu_kernel<<<((size_t)NPAIR * HIDh / 4) / 256, 256>>>();
    tc_gemm<true, false><<<dim3(Dd / 128, NPAIR / 128, Ee), 256, TC_SMEM>>>(pgb, pwd, eo, nullptr, nullptr, Dd, HIDh);
    // 9) combine
    combine_kernel<<<Tt, 256>>>(out);
}

// round 13
// speedup vs baseline: 2.2187x; 1.1494x over previous
#include <cuda_runtime.h>
#include <cuda_bf16.h>
#include <math.h>
#include <stdint.h>

// ---------------- problem constants ----------------
#define Bb   2
#define Ss   1024
#define Dd   2048
#define Hh   16
#define DHh  128
#define Ee   8
#define HIDh 4096
#define Tt   (Bb * Ss)       // 2048 tokens
#define NPAIR (Tt * 2)       // 4096 (token, expert) pairs

// ---------------- device scratch ----------------
// fp32
__device__ float g_q  [Tt * Dd];
__device__ float g_k  [Tt * Dd];
__device__ float g_v  [Tt * Dd];
__device__ float g_x2 [Tt * Dd];
__device__ float g_xn2[Tt * Dd];
__device__ float g_gb [(size_t)NPAIR * HIDh];
__device__ float g_ub [(size_t)NPAIR * HIDh];
__device__ float g_eo [(size_t)NPAIR * Dd];
// bf16 hi/lo planes (x = hi + lo split)
__device__ __nv_bfloat16 g_hxn1[Tt * Dd], g_lxn1[Tt * Dd];
__device__ __nv_bfloat16 g_hatt[Tt * Dd], g_latt[Tt * Dd];
__device__ __nv_bfloat16 g_hxn2[Tt * Dd], g_lxn2[Tt * Dd];
__device__ __nv_bfloat16 g_hgb [(size_t)NPAIR * HIDh], g_lgb[(size_t)NPAIR * HIDh];
__device__ __nv_bfloat16 g_hwq [Dd * Dd], g_lwq[Dd * Dd];
__device__ __nv_bfloat16 g_hwk [Dd * Dd], g_lwk[Dd * Dd];
__device__ __nv_bfloat16 g_hwv [Dd * Dd], g_lwv[Dd * Dd];
__device__ __nv_bfloat16 g_hwo [Dd * Dd], g_lwo[Dd * Dd];
__device__ __nv_bfloat16 g_hwg [(size_t)Ee * HIDh * Dd], g_lwg[(size_t)Ee * HIDh * Dd];
__device__ __nv_bfloat16 g_hwu [(size_t)Ee * HIDh * Dd], g_lwu[(size_t)Ee * HIDh * Dd];
__device__ __nv_bfloat16 g_hwd [(size_t)Ee * Dd * HIDh], g_lwd[(size_t)Ee * Dd * HIDh];
// routing
__device__ int   g_tid2[NPAIR];
__device__ float g_twt [NPAIR];
__device__ int   g_cnt[Ee];
__device__ int   g_off[Ee];
__device__ int   g_tok[NPAIR];
__device__ int   g_prow[NPAIR];

// ---------------- helpers ----------------
__device__ __forceinline__ uint32_t smem_u32(const void* p) {
    uint32_t a;
    asm("{ .reg .u64 t; cvta.to.shared.u64 t, %1; cvt.u32.u64 %0, t; }" : "=r"(a) : "l"(p));
    return a;
}
__device__ __forceinline__ uint32_t swz128(uint32_t off) {
    return off ^ ((off >> 3) & 0x70);
}
__device__ __forceinline__ void ldsm_x4(uint32_t* r, uint32_t addr) {
    asm volatile("ldmatrix.sync.aligned.m8n8.x4.shared.b16 {%0,%1,%2,%3}, [%4];"
                 : "=r"(r[0]), "=r"(r[1]), "=r"(r[2]), "=r"(r[3]) : "r"(addr));
}
__device__ __forceinline__ void mma_bf16(float* c, const uint32_t* a, uint32_t b0, uint32_t b1) {
    asm volatile("mma.sync.aligned.m16n8k16.row.col.f32.bf16.bf16.f32 "
                 "{%0,%1,%2,%3}, {%4,%5,%6,%7}, {%8,%9}, {%0,%1,%2,%3};"
                 : "+f"(c[0]), "+f"(c[1]), "+f"(c[2]), "+f"(c[3])
                 : "r"(a[0]), "r"(a[1]), "r"(a[2]), "r"(a[3]), "r"(b0), "r"(b1));
}
__device__ __forceinline__ void cpa16(uint32_t dst, const void* src) {
    asm volatile("cp.async.cg.shared.global [%0], [%1], 16;" :: "r"(dst), "l"(src) : "memory");
}
__device__ __forceinline__ void split2(float f, __nv_bfloat16& h, __nv_bfloat16& l) {
    h = __float2bfloat16(f);
    l = __float2bfloat16(f - __bfloat162float(h));
}

// ---------------- pack conversion (fp32 -> hi/lo bf16 planes) ----------------
__global__ void pack_kernel(const float* __restrict__ in,
                            __nv_bfloat16* __restrict__ oh,
                            __nv_bfloat16* __restrict__ ol) {
    size_t i = ((size_t)blockIdx.x * 256 + threadIdx.x) * 4;
    float4 v = *(const float4*)(in + i);
    __nv_bfloat16 h[4], l[4];
    split2(v.x, h[0], l[0]); split2(v.y, h[1], l[1]);
    split2(v.z, h[2], l[2]); split2(v.w, h[3], l[3]);
    *(ushort4*)(oh + i) = make_ushort4(*(uint16_t*)&h[0], *(uint16_t*)&h[1],
                                       *(uint16_t*)&h[2], *(uint16_t*)&h[3]);
    *(ushort4*)(ol + i) = make_ushort4(*(uint16_t*)&l[0], *(uint16_t*)&l[1],
                                       *(uint16_t*)&l[2], *(uint16_t*)&l[3]);
}

// ---------------- 3x-bf16 mma.sync GEMM, cp.async pipeline ----------------
// C[M,N] = A[M,K] @ B[N,K]^T. CTA tile 128x128, K-tile 32 elems.
// Smem row (128B, swz128): [0,64) hi bf16 k0..31, [64,128) lo bf16 k0..31.
#define STAGE_B  32768
#define TC_SMEM  (1024 + 2 * STAGE_B)

template <bool EXPERT, bool GATHER>
__global__ __launch_bounds__(256, 2)
void tc_gemm(const __nv_bfloat16* __restrict__ Ahi, const __nv_bfloat16* __restrict__ Alo,
             const __nv_bfloat16* __restrict__ Bhi, const __nv_bfloat16* __restrict__ Blo,
             float* __restrict__ C, const float* __restrict__ bias,
             const float* __restrict__ resid, int N, int K) {
    extern __shared__ float sm[];
    const int tid = threadIdx.x;

    int bm, bn, cnt = 0, seg = 0, e = 0;
    if (EXPERT) {
        e = blockIdx.z; cnt = g_cnt[e]; seg = g_off[e];
        bm = blockIdx.y * 128;
        if (bm >= cnt) return;
    } else {
        bm = blockIdx.y * 128;
    }
    bn = blockIdx.x * 128;

    const uint32_t sbase = smem_u32(sm);
    const uint32_t tbase = (sbase + 1023) & ~1023u;

    // ---- global source mapping: 2 threads/row, 16 bf16 (32B) each ----
    const int arow = tid >> 1;
    const int half = tid & 1;
    int grow = bm + arow;
    size_t aoff;
    if (EXPERT) {
        int cl = (grow < cnt) ? grow : (cnt - 1);
        aoff = (size_t)(GATHER ? g_tok[seg + cl] : (seg + cl)) * K;
    } else {
        aoff = (size_t)grow * K;
    }
    const __nv_bfloat16* pAh = Ahi + aoff + half * 16;
    const __nv_bfloat16* pAl = Alo + aoff + half * 16;
    const size_t boff = (EXPERT ? (size_t)e * N * K : 0) + (size_t)(bn + arow) * K + half * 16;
    const __nv_bfloat16* pBh = Bhi + boff;
    const __nv_bfloat16* pBl = Blo + boff;

    const uint32_t d0 = swz128((uint32_t)arow * 128 + half * 32);
    const uint32_t d1 = swz128((uint32_t)arow * 128 + half * 32 + 16);
    const uint32_t d2 = swz128((uint32_t)arow * 128 + 64 + half * 32);
    const uint32_t d3 = swz128((uint32_t)arow * 128 + 64 + half * 32 + 16);

    auto issue = [&](int buf, int t) {
        const uint32_t aB = tbase + buf * STAGE_B;
        const uint32_t bB = aB + 16384;
        const int k0 = t * 32;
        cpa16(aB + d0, pAh + k0);
        cpa16(aB + d1, pAh + k0 + 8);
        cpa16(aB + d2, pAl + k0);
        cpa16(aB + d3, pAl + k0 + 8);
        cpa16(bB + d0, pBh + k0);
        cpa16(bB + d1, pBh + k0 + 8);
        cpa16(bB + d2, pBl + k0);
        cpa16(bB + d3, pBl + k0 + 8);
        asm volatile("cp.async.commit_group;" ::: "memory");
    };

    // ---- warp tiling: 8 warps = 2(m) x 4(n), each 64x32 ----
    const int wid = tid >> 5, lane = tid & 31;
    const int wm = wid >> 2, wn = wid & 3;
    const int lrow = lane & 15;
    const int lcolb = (lane >> 4) * 16;

    float acc[4][4][4];
    #pragma unroll
    for (int i = 0; i < 4; i++)
        #pragma unroll
        for (int j = 0; j < 4; j++)
            #pragma unroll
            for (int q = 0; q < 4; q++) acc[i][j][q] = 0.f;

    const int NT = K >> 5;

    issue(0, 0);
    for (int t = 0; t < NT; ++t) {
        if (t + 1 < NT) {
            issue((t + 1) & 1, t + 1);
            asm volatile("cp.async.wait_group 1;" ::: "memory");
        } else {
            asm volatile("cp.async.wait_group 0;" ::: "memory");
        }
        __syncthreads();

        const uint32_t aB = tbase + (t & 1) * STAGE_B;
        const uint32_t bB = aB + 16384;
        #pragma unroll
        for (int s = 0; s < 2; s++) {
            uint32_t bh[2][4], bl[2][4];
            #pragma unroll
            for (int p = 0; p < 2; p++) {
                uint32_t ro = (uint32_t)(wn * 32 + p * 16 + lrow) * 128 + s * 32 + lcolb;
                ldsm_x4(bh[p], bB + swz128(ro));
                ldsm_x4(bl[p], bB + swz128(ro + 64));
            }
            #pragma unroll
            for (int i = 0; i < 4; i++) {
                uint32_t ah[4], al[4];
                uint32_t ro = (uint32_t)(wm * 64 + i * 16 + lrow) * 128 + s * 32 + lcolb;
                ldsm_x4(ah, aB + swz128(ro));
                ldsm_x4(al, aB + swz128(ro + 64));
                #pragma unroll
                for (int j = 0; j < 4; j++) {
                    const int p = j >> 1, o = j & 1;
                    mma_bf16(acc[i][j], ah, bh[p][o], bh[p][o + 2]);
                    mma_bf16(acc[i][j], ah, bl[p][o], bl[p][o + 2]);
                    mma_bf16(acc[i][j], al, bh[p][o], bh[p][o + 2]);
                }
            }
        }
        __syncthreads();
    }

    // ---- epilogue ----
    const int qr = lane >> 2;
    const int qc = (lane & 3) * 2;
    #pragma unroll
    for (int i = 0; i < 4; i++) {
        const int lm0 = wm * 64 + i * 16 + qr;
        #pragma unroll
        for (int j = 0; j < 4; j++) {
            const int c = bn + wn * 32 + j * 8 + qc;
            float2 v0 = make_float2(acc[i][j][0], acc[i][j][1]);
            float2 v1 = make_float2(acc[i][j][2], acc[i][j][3]);
            if (bias) {
                float2 bv = *(const float2*)(bias + c);
                v0.x += bv.x; v0.y += bv.y;
                v1.x += bv.x; v1.y += bv.y;
            }
            if (EXPERT) {
                if (bm + lm0 < cnt)
                    *(float2*)(C + (size_t)(seg + bm + lm0) * N + c) = v0;
                if (bm + lm0 + 8 < cnt)
                    *(float2*)(C + (size_t)(seg + bm + lm0 + 8) * N + c) = v1;
            } else {
                const int r0 = bm + lm0;
                if (resid) {
                    float2 rv0 = *(const float2*)(resid + (size_t)r0 * N + c);
                    float2 rv1 = *(const float2*)(resid + (size_t)(r0 + 8) * N + c);
                    v0.x += rv0.x; v0.y += rv0.y;
                    v1.x += rv1.x; v1.y += rv1.y;
                }
                *(float2*)(C + (size_t)r0 * N + c)       = v0;
                *(float2*)(C + (size_t)(r0 + 8) * N + c) = v1;
            }
        }
    }
}

// ---------------- rmsnorm (optional fp32 + hi/lo plane outputs) ----------------
__global__ void rmsnorm_kernel(const float* __restrict__ x,
                               const float* __restrict__ w,
                               float* __restrict__ out_f32,
                               __nv_bfloat16* __restrict__ oh,
                               __nv_bfloat16* __restrict__ ol) {
    int t = blockIdx.x;
    const float* xr = x + (size_t)t * Dd;
    float ss = 0.f;
    for (int i = threadIdx.x; i < Dd; i += 256) { float vv = xr[i]; ss += vv * vv; }
    __shared__ float red[8];
    #pragma unroll
    for (int o = 16; o; o >>= 1) ss += __shfl_xor_sync(0xffffffffu, ss, o);
    if ((threadIdx.x & 31) == 0) red[threadIdx.x >> 5] = ss;
    __syncthreads();
    if (threadIdx.x < 8) {
        float v = red[threadIdx.x];
        #pragma unroll
        for (int o = 4; o; o >>= 1) v += __shfl_xor_sync(0xffu, v, o);
        if (threadIdx.x == 0) red[0] = v;
    }
    __syncthreads();
    float inv = 1.f / sqrtf(red[0] / (float)Dd + 1e-8f);
    for (int i = threadIdx.x; i < Dd; i += 256) {
        float v = xr[i] * inv * w[i];
        if (out_f32) out_f32[(size_t)t * Dd + i] = v;
        __nv_bfloat16 h, l;
        split2(v, h, l);
        oh[(size_t)t * Dd + i] = h;
        ol[(size_t)t * Dd + i] = l;
    }
}

// ---------------- RoPE (angle depends on HEAD index, per reference) ----------------
__global__ void rope_kernel(float* __restrict__ q) {
    int gid = blockIdx.x * 256 + threadIdx.x;
    int t = gid >> 10;
    int r = gid & 1023;
    int h = r >> 6;
    int p = r & 63;
    float ang = (float)h * expf(-(float)p * (9.210340371976184f / 64.f));
    float c = cosf(ang), s = sinf(ang);
    float* base = q + (size_t)t * Dd + h * DHh + 2 * p;
    float x1 = base[0], x2 = base[1];
    base[0] = x1 * c - x2 * s;
    base[1] = x1 * s + x2 * c;
}

// ---------------- attention: 32 q/block, 4 q/warp, lane-per-key ----------------
// dyn smem: Qs[32][128] | Ks[32][132] | Vs[32][132]  (floats)
#define AQS 0
#define AKS 4096
#define AVS (4096 + 32 * 132)
#define ATT_SMEM ((4096 + 2 * 32 * 132) * 4)

__global__ __launch_bounds__(256)
void attn_kernel(const float* __restrict__ Q, const float* __restrict__ Kx,
                 const float* __restrict__ V,
                 __nv_bfloat16* __restrict__ Oh, __nv_bfloat16* __restrict__ Ol) {
    extern __shared__ float smf[];
    const int b = blockIdx.z, h = blockIdx.y, qg = blockIdx.x;
    const int tid = threadIdx.x;
    const int warp = tid >> 5, lane = tid & 31;

    for (int c = tid; c < 1024; c += 256) {
        int rr = c >> 5, c4 = (c & 31) * 4;
        *(float4*)&smf[AQS + rr * 128 + c4] =
            *(const float4*)&Q[((size_t)(b * Ss + qg * 32 + rr)) * Dd + h * DHh + c4];
    }

    const int q0 = qg * 32 + warp * 4;
    float m[4], l[4];
    float4 o[4];
    #pragma unroll
    for (int q = 0; q < 4; q++) {
        m[q] = -INFINITY; l[q] = 0.f;
        o[q] = make_float4(0.f, 0.f, 0.f, 0.f);
    }

    const int ntiles = qg + 1;
    for (int kt = 0; kt < ntiles; kt++) {
        __syncthreads();
        for (int c = tid; c < 1024; c += 256) {
            int rr = c >> 5, c4 = (c & 31) * 4;
            size_t g = ((size_t)(b * Ss + kt * 32 + rr)) * Dd + h * DHh + c4;
            *(float4*)&smf[AKS + rr * 132 + c4] = *(const float4*)&Kx[g];
            *(float4*)&smf[AVS + rr * 132 + c4] = *(const float4*)&V[g];
        }
        __syncthreads();

        const int kj = kt * 32 + lane;
        float4 s4[4];
        #pragma unroll
        for (int q = 0; q < 4; q++) s4[q] = make_float4(0.f, 0.f, 0.f, 0.f);
        const float* krow = &smf[AKS + lane * 132];
        #pragma unroll 8
        for (int c4 = 0; c4 < 32; c4++) {
            float4 kv = *(const float4*)&krow[c4 * 4];
            #pragma unroll
            for (int q = 0; q < 4; q++) {
                float4 qv = *(const float4*)&smf[AQS + (warp * 4 + q) * 128 + c4 * 4];
                s4[q].x = fmaf(qv.x, kv.x, s4[q].x);
                s4[q].y = fmaf(qv.y, kv.y, s4[q].y);
                s4[q].z = fmaf(qv.z, kv.z, s4[q].z);
                s4[q].w = fmaf(qv.w, kv.w, s4[q].w);
            }
        }
        float s[4], w[4];
        #pragma unroll
        for (int q = 0; q < 4; q++) {
            float v = (s4[q].x + s4[q].y) + (s4[q].z + s4[q].w);
            s[q] = (kj <= q0 + q) ? v * 0.08838834764831845f : -INFINITY;
        }
        float tm[4];
        #pragma unroll
        for (int q = 0; q < 4; q++) tm[q] = s[q];
        #pragma unroll
        for (int ofs = 16; ofs; ofs >>= 1)
            #pragma unroll
            for (int q = 0; q < 4; q++)
                tm[q] = fmaxf(tm[q], __shfl_xor_sync(0xffffffffu, tm[q], ofs));
        float ts[4];
        #pragma unroll
        for (int q = 0; q < 4; q++) {
            float mnew = fmaxf(m[q], tm[q]);
            float corr = __expf(m[q] - mnew);
            w[q] = __expf(s[q] - mnew);
            m[q] = mnew;
            l[q] *= corr;
            o[q].x *= corr; o[q].y *= corr; o[q].z *= corr; o[q].w *= corr;
            ts[q] = w[q];
        }
        #pragma unroll
        for (int ofs = 16; ofs; ofs >>= 1)
            #pragma unroll
            for (int q = 0; q < 4; q++)
                ts[q] += __shfl_xor_sync(0xffffffffu, ts[q], ofs);
        #pragma unroll
        for (int q = 0; q < 4; q++) l[q] += ts[q];

        const float* vcol = &smf[AVS + lane * 4];
        #pragma unroll 4
        for (int j = 0; j < 32; j++) {
            float4 vv = *(const float4*)&vcol[j * 132];
            #pragma unroll
            for (int q = 0; q < 4; q++) {
                float wq = __shfl_sync(0xffffffffu, w[q], j);
                o[q].x = fmaf(wq, vv.x, o[q].x);
                o[q].y = fmaf(wq, vv.y, o[q].y);
                o[q].z = fmaf(wq, vv.z, o[q].z);
                o[q].w = fmaf(wq, vv.w, o[q].w);
            }
        }
    }

    #pragma unroll
    for (int q = 0; q < 4; q++) {
        float inv = 1.f / l[q];
        float f[4] = {o[q].x * inv, o[q].y * inv, o[q].z * inv, o[q].w * inv};
        __nv_bfloat16 hh[4], ll[4];
        #pragma unroll
        for (int d = 0; d < 4; d++) split2(f[d], hh[d], ll[d]);
        size_t base = ((size_t)(b * Ss + q0 + q)) * Dd + h * DHh + lane * 4;
        *(ushort4*)(Oh + base) = make_ushort4(*(uint16_t*)&hh[0], *(uint16_t*)&hh[1],
                                              *(uint16_t*)&hh[2], *(uint16_t*)&hh[3]);
        *(ushort4*)(Ol + base) = make_ushort4(*(uint16_t*)&ll[0], *(uint16_t*)&ll[1],
                                              *(uint16_t*)&ll[2], *(uint16_t*)&ll[3]);
    }
}

// ---------------- router ----------------
__global__ void router_kernel(const float* __restrict__ xn, const float* __restrict__ wr,
                              const float* __restrict__ br) {
    int t = blockIdx.x;
    int warp = threadIdx.x >> 5, lane = threadIdx.x & 31;
    const float* xr = xn + (size_t)t * Dd;
    const float* w = wr + (size_t)warp * Dd;
    float s = 0.f;
    for (int i = lane; i < Dd; i += 32) s += xr[i] * w[i];
    #pragma unroll
    for (int o = 16; o; o >>= 1) s += __shfl_xor_sync(0xffffffffu, s, o);
    __shared__ float lg[Ee];
    if (lane == 0) lg[warp] = s + br[warp];
    __syncthreads();
    if (threadIdx.x == 0) {
        int i0 = 0; float v0 = lg[0];
        for (int e = 1; e < Ee; e++) if (lg[e] > v0) { v0 = lg[e]; i0 = e; }
        int i1 = -1; float v1 = -INFINITY;
        for (int e = 0; e < Ee; e++) if (e != i0 && lg[e] > v1) { v1 = lg[e]; i1 = e; }
        float e1 = expf(v1 - v0);
        float w0 = 1.f / (1.f + e1);
        g_tid2[t * 2] = i0; g_tid2[t * 2 + 1] = i1;
        g_twt[t * 2] = w0;  g_twt[t * 2 + 1] = e1 * w0;
    }
}

// ---------------- expert grouping ----------------
__global__ void build_lists_kernel() {
    __shared__ int cnt[Ee], run[Ee];
    int tid = threadIdx.x;
    if (tid < Ee) cnt[tid] = 0;
    __syncthreads();
    for (int i = tid; i < NPAIR; i += 256) atomicAdd(&cnt[g_tid2[i]], 1);
    __syncthreads();
    if (tid == 0) {
        int acc = 0;
        for (int e = 0; e < Ee; e++) { g_cnt[e] = cnt[e]; g_off[e] = acc; run[e] = acc; acc += cnt[e]; }
    }
    __syncthreads();
    for (int i = tid; i < NPAIR; i += 256) {
        int e = g_tid2[i];
        int pos = atomicAdd(&run[e], 1);
        g_tok[pos] = i >> 1;
        g_prow[i] = pos;
    }
}

// ---------------- silu * up -> hi/lo planes ----------------
__global__ void silu_kernel() {
    size_t i = ((size_t)blockIdx.x * 256 + threadIdx.x) * 4;
    float4 g = *(float4*)(g_gb + i);
    float4 u = *(float4*)(g_ub + i);
    g.x = g.x / (1.f + __expf(-g.x)) * u.x;
    g.y = g.y / (1.f + __expf(-g.y)) * u.y;
    g.z = g.z / (1.f + __expf(-g.z)) * u.z;
    g.w = g.w / (1.f + __expf(-g.w)) * u.w;
    __nv_bfloat16 h[4], l[4];
    split2(g.x, h[0], l[0]); split2(g.y, h[1], l[1]);
    split2(g.z, h[2], l[2]); split2(g.w, h[3], l[3]);
    *(ushort4*)(g_hgb + i) = make_ushort4(*(uint16_t*)&h[0], *(uint16_t*)&h[1],
                                          *(uint16_t*)&h[2], *(uint16_t*)&h[3]);
    *(ushort4*)(g_lgb + i) = make_ushort4(*(uint16_t*)&l[0], *(uint16_t*)&l[1],
                                          *(uint16_t*)&l[2], *(uint16_t*)&l[3]);
}

// ---------------- combine ----------------
__global__ void combine_kernel(float* __restrict__ out) {
    int t = blockIdx.x;
    int r0 = g_prow[t * 2], r1 = g_prow[t * 2 + 1];
    float w0 = g_twt[t * 2], w1 = g_twt[t * 2 + 1];
    const float* e0 = g_eo + (size_t)r0 * Dd;
    const float* e1 = g_eo + (size_t)r1 * Dd;
    const float* xr = g_x2 + (size_t)t * Dd;
    float* orow = out + (size_t)t * Dd;
    for (int i = threadIdx.x; i < Dd; i += 256)
        orow[i] = xr[i] + w0 * e0[i] + w1 * e1[i];
}

// ---------------- host launcher ----------------
extern "C" void kernel_launch(void* const* d_in, const int* in_sizes, int n_in,
                              void* d_out, int out_size) {
    const float* x   = (const float*)d_in[0];
    const float* wq  = (const float*)d_in[1];
    const float* bq  = (const float*)d_in[2];
    const float* wk  = (const float*)d_in[3];
    const float* bk  = (const float*)d_in[4];
    const float* wv  = (const float*)d_in[5];
    const float* bv  = (const float*)d_in[6];
    const float* wo  = (const float*)d_in[7];
    const float* bo  = (const float*)d_in[8];
    const float* wr  = (const float*)d_in[9];
    const float* br  = (const float*)d_in[10];
    const float* wg  = (const float*)d_in[11];
    const float* wu  = (const float*)d_in[12];
    const float* wd  = (const float*)d_in[13];
    const float* r1w = (const float*)d_in[14];
    const float* r2w = (const float*)d_in[15];
    float* out = (float*)d_out;

    float *q, *k, *v, *x2, *xn2, *gb, *ub, *eo;
    __nv_bfloat16 *hxn1, *lxn1, *hatt, *latt, *hxn2, *lxn2, *hgb, *lgb;
    __nv_bfloat16 *hwq, *lwq, *hwk, *lwk, *hwv, *lwv, *hwo, *lwo;
    __nv_bfloat16 *hwg, *lwg, *hwu, *lwu, *hwd, *lwd;
    cudaGetSymbolAddress((void**)&q,    g_q);
    cudaGetSymbolAddress((void**)&k,    g_k);
    cudaGetSymbolAddress((void**)&v,    g_v);
    cudaGetSymbolAddress((void**)&x2,   g_x2);
    cudaGetSymbolAddress((void**)&xn2,  g_xn2);
    cudaGetSymbolAddress((void**)&gb,   g_gb);
    cudaGetSymbolAddress((void**)&ub,   g_ub);
    cudaGetSymbolAddress((void**)&eo,   g_eo);
    cudaGetSymbolAddress((void**)&hxn1, g_hxn1);  cudaGetSymbolAddress((void**)&lxn1, g_lxn1);
    cudaGetSymbolAddress((void**)&hatt, g_hatt);  cudaGetSymbolAddress((void**)&latt, g_latt);
    cudaGetSymbolAddress((void**)&hxn2, g_hxn2);  cudaGetSymbolAddress((void**)&lxn2, g_lxn2);
    cudaGetSymbolAddress((void**)&hgb,  g_hgb);   cudaGetSymbolAddress((void**)&lgb,  g_lgb);
    cudaGetSymbolAddress((void**)&hwq,  g_hwq);   cudaGetSymbolAddress((void**)&lwq,  g_lwq);
    cudaGetSymbolAddress((void**)&hwk,  g_hwk);   cudaGetSymbolAddress((void**)&lwk,  g_lwk);
    cudaGetSymbolAddress((void**)&hwv,  g_hwv);   cudaGetSymbolAddress((void**)&lwv,  g_lwv);
    cudaGetSymbolAddress((void**)&hwo,  g_hwo);   cudaGetSymbolAddress((void**)&lwo,  g_lwo);
    cudaGetSymbolAddress((void**)&hwg,  g_hwg);   cudaGetSymbolAddress((void**)&lwg,  g_lwg);
    cudaGetSymbolAddress((void**)&hwu,  g_hwu);   cudaGetSymbolAddress((void**)&lwu,  g_lwu);
    cudaGetSymbolAddress((void**)&hwd,  g_hwd);   cudaGetSymbolAddress((void**)&lwd,  g_lwd);

    cudaFuncSetAttribute((const void*)tc_gemm<false, false>,
                         cudaFuncAttributeMaxDynamicSharedMemorySize, TC_SMEM);
    cudaFuncSetAttribute((const void*)tc_gemm<true, true>,
                         cudaFuncAttributeMaxDynamicSharedMemorySize, TC_SMEM);
    cudaFuncSetAttribute((const void*)tc_gemm<true, false>,
                         cudaFuncAttributeMaxDynamicSharedMemorySize, TC_SMEM);
    cudaFuncSetAttribute((const void*)attn_kernel,
                         cudaFuncAttributeMaxDynamicSharedMemorySize, ATT_SMEM);

    // 0) pack weights into hi/lo bf16 planes
    pack_kernel<<<Dd * Dd / 1024, 256>>>(wq, hwq, lwq);
    pack_kernel<<<Dd * Dd / 1024, 256>>>(wk, hwk, lwk);
    pack_kernel<<<Dd * Dd / 1024, 256>>>(wv, hwv, lwv);
    pack_kernel<<<Dd * Dd / 1024, 256>>>(wo, hwo, lwo);
    pack_kernel<<<Ee * HIDh * Dd / 1024, 256>>>(wg, hwg, lwg);
    pack_kernel<<<Ee * HIDh * Dd / 1024, 256>>>(wu, hwu, lwu);
    pack_kernel<<<Ee * Dd * HIDh / 1024, 256>>>(wd, hwd, lwd);

    // 1) rmsnorm1 -> planes only
    rmsnorm_kernel<<<Tt, 256>>>(x, r1w, nullptr, hxn1, lxn1);
    // 2) QKV projections
    tc_gemm<false, false><<<dim3(Dd / 128, Tt / 128), 256, TC_SMEM>>>(hxn1, lxn1, hwq, lwq, q, bq, nullptr, Dd, Dd);
    tc_gemm<false, false><<<dim3(Dd / 128, Tt / 128), 256, TC_SMEM>>>(hxn1, lxn1, hwk, lwk, k, bk, nullptr, Dd, Dd);
    tc_gemm<false, false><<<dim3(Dd / 128, Tt / 128), 256, TC_SMEM>>>(hxn1, lxn1, hwv, lwv, v, bv, nullptr, Dd, Dd);
    // 3) RoPE
    rope_kernel<<<(Tt * Hh * 64) / 256, 256>>>(q);
    rope_kernel<<<(Tt * Hh * 64) / 256, 256>>>(k);
    // 4) attention -> att planes
    attn_kernel<<<dim3(Ss / 32, Hh, Bb), 256, ATT_SMEM>>>(q, k, v, hatt, latt);
    // 5) output projection + residual
    tc_gemm<false, false><<<dim3(Dd / 128, Tt / 128), 256, TC_SMEM>>>(hatt, latt, hwo, lwo, x2, bo, x, Dd, Dd);
    // 6) rmsnorm2 -> fp32 (router) + planes (MoE)
    rmsnorm_kernel<<<Tt, 256>>>(x2, r2w, xn2, hxn2, lxn2);
    // 7) router + grouping
    router_kernel<<<Tt, 256>>>(xn2, wr, br);
    build_lists_kernel<<<1, 256>>>();
    // 8) MoE
    tc_gemm<true, true ><<<dim3(HIDh / 128, NPAIR / 128, Ee), 256, TC_SMEM>>>(hxn2, lxn2, hwg, lwg, gb, nullptr, nullptr, HIDh, Dd);
    tc_gemm<true, true ><<<dim3(HIDh / 128, NPAIR / 128, Ee), 256, TC_SMEM>>>(hxn2, lxn2, hwu, lwu, ub, nullptr, nullptr, HIDh, Dd);
    silu_kernel<<<((size_t)NPAIR * HIDh / 4) / 256, 256>>>();
    tc_gemm<true, false><<<dim3(Dd / 128, NPAIR / 128, Ee), 256, TC_SMEM>>>(hgb, lgb, hwd, lwd, eo, nullptr, nullptr, Dd, HIDh);
    // 9) combine
    combine_kernel<<<Tt, 256>>>(out);
}

// round 14
// speedup vs baseline: 2.2461x; 1.0124x over previous
#include <cuda_runtime.h>
#include <cuda_bf16.h>
#include <math.h>
#include <stdint.h>

// ---------------- problem constants ----------------
#define Bb   2
#define Ss   1024
#define Dd   2048
#define Hh   16
#define DHh  128
#define Ee   8
#define HIDh 4096
#define Tt   (Bb * Ss)       // 2048 tokens
#define NPAIR (Tt * 2)       // 4096 (token, expert) pairs
#define QKVN (3 * Dd)        // 6144
#define GUN  (2 * HIDh)      // 8192

// ---------------- device scratch ----------------
// fp32
__device__ float g_qkv[(size_t)Tt * QKVN];
__device__ float g_x2 [Tt * Dd];
__device__ float g_xn2[Tt * Dd];
__device__ float g_gu [(size_t)NPAIR * GUN];
__device__ float g_eo [(size_t)NPAIR * Dd];
__device__ float g_bqkv[QKVN];
// bf16 hi/lo planes (x = hi + lo split)
__device__ __nv_bfloat16 g_hxn1[Tt * Dd], g_lxn1[Tt * Dd];
__device__ __nv_bfloat16 g_hatt[Tt * Dd], g_latt[Tt * Dd];
__device__ __nv_bfloat16 g_hxn2[Tt * Dd], g_lxn2[Tt * Dd];
__device__ __nv_bfloat16 g_hgb [(size_t)NPAIR * HIDh], g_lgb[(size_t)NPAIR * HIDh];
__device__ __nv_bfloat16 g_hwqkv[(size_t)QKVN * Dd], g_lwqkv[(size_t)QKVN * Dd];
__device__ __nv_bfloat16 g_hwo [Dd * Dd], g_lwo[Dd * Dd];
__device__ __nv_bfloat16 g_hwgu[(size_t)Ee * GUN * Dd], g_lwgu[(size_t)Ee * GUN * Dd];
__device__ __nv_bfloat16 g_hwd [(size_t)Ee * Dd * HIDh], g_lwd[(size_t)Ee * Dd * HIDh];
// routing
__device__ int   g_tid2[NPAIR];
__device__ float g_twt [NPAIR];
__device__ int   g_cnt[Ee];
__device__ int   g_off[Ee];
__device__ int   g_tok[NPAIR];
__device__ int   g_prow[NPAIR];

// ---------------- helpers ----------------
__device__ __forceinline__ uint32_t smem_u32(const void* p) {
    uint32_t a;
    asm("{ .reg .u64 t; cvta.to.shared.u64 t, %1; cvt.u32.u64 %0, t; }" : "=r"(a) : "l"(p));
    return a;
}
__device__ __forceinline__ uint32_t swz128(uint32_t off) {
    return off ^ ((off >> 3) & 0x70);
}
__device__ __forceinline__ void ldsm_x4(uint32_t* r, uint32_t addr) {
    asm volatile("ldmatrix.sync.aligned.m8n8.x4.shared.b16 {%0,%1,%2,%3}, [%4];"
                 : "=r"(r[0]), "=r"(r[1]), "=r"(r[2]), "=r"(r[3]) : "r"(addr));
}
__device__ __forceinline__ void mma_bf16(float* c, const uint32_t* a, uint32_t b0, uint32_t b1) {
    asm volatile("mma.sync.aligned.m16n8k16.row.col.f32.bf16.bf16.f32 "
                 "{%0,%1,%2,%3}, {%4,%5,%6,%7}, {%8,%9}, {%0,%1,%2,%3};"
                 : "+f"(c[0]), "+f"(c[1]), "+f"(c[2]), "+f"(c[3])
                 : "r"(a[0]), "r"(a[1]), "r"(a[2]), "r"(a[3]), "r"(b0), "r"(b1));
}
__device__ __forceinline__ void cpa16(uint32_t dst, const void* src) {
    asm volatile("cp.async.cg.shared.global [%0], [%1], 16;" :: "r"(dst), "l"(src) : "memory");
}
__device__ __forceinline__ void split2(float f, __nv_bfloat16& h, __nv_bfloat16& l) {
    h = __float2bfloat16(f);
    l = __float2bfloat16(f - __bfloat162float(h));
}

// ---------------- pack conversion (fp32 -> hi/lo bf16 planes) ----------------
__global__ void pack_kernel(const float* __restrict__ in,
                            __nv_bfloat16* __restrict__ oh,
                            __nv_bfloat16* __restrict__ ol) {
    size_t i = ((size_t)blockIdx.x * 256 + threadIdx.x) * 4;
    float4 v = *(const float4*)(in + i);
    __nv_bfloat16 h[4], l[4];
    split2(v.x, h[0], l[0]); split2(v.y, h[1], l[1]);
    split2(v.z, h[2], l[2]); split2(v.w, h[3], l[3]);
    *(ushort4*)(oh + i) = make_ushort4(*(uint16_t*)&h[0], *(uint16_t*)&h[1],
                                       *(uint16_t*)&h[2], *(uint16_t*)&h[3]);
    *(ushort4*)(ol + i) = make_ushort4(*(uint16_t*)&l[0], *(uint16_t*)&l[1],
                                       *(uint16_t*)&l[2], *(uint16_t*)&l[3]);
}

// pack [E][HID][D] src into [E][2*HID][D] dst at row-offset base (gate: 0, up: HID)
__global__ void pack_moe_kernel(const float* __restrict__ in,
                                __nv_bfloat16* __restrict__ oh,
                                __nv_bfloat16* __restrict__ ol, size_t base) {
    size_t i = ((size_t)blockIdx.x * 256 + threadIdx.x) * 4;
    const size_t chunk = (size_t)HIDh * Dd;
    size_t e = i / chunk, r = i % chunk;
    size_t o = e * (2 * chunk) + base * Dd + r;
    float4 v = *(const float4*)(in + i);
    __nv_bfloat16 h[4], l[4];
    split2(v.x, h[0], l[0]); split2(v.y, h[1], l[1]);
    split2(v.z, h[2], l[2]); split2(v.w, h[3], l[3]);
    *(ushort4*)(oh + o) = make_ushort4(*(uint16_t*)&h[0], *(uint16_t*)&h[1],
                                       *(uint16_t*)&h[2], *(uint16_t*)&h[3]);
    *(ushort4*)(ol + o) = make_ushort4(*(uint16_t*)&l[0], *(uint16_t*)&l[1],
                                       *(uint16_t*)&l[2], *(uint16_t*)&l[3]);
}

__global__ void bias_cat_kernel(const float* __restrict__ bq, const float* __restrict__ bk,
                                const float* __restrict__ bv) {
    int i = blockIdx.x * 256 + threadIdx.x;
    float v = (i < Dd) ? bq[i] : (i < 2 * Dd) ? bk[i - Dd] : bv[i - 2 * Dd];
    g_bqkv[i] = v;
}

// ---------------- 3x-bf16 mma.sync GEMM, 3-stage cp.async pipeline ----------------
// C[M,N] = A[M,K] @ B[N,K]^T. CTA tile 128x128, K-tile 32 elems.
// Smem row (128B, swz128): [0,64) hi bf16 k0..31, [64,128) lo bf16 k0..31.
#define STAGE_B  32768
#define TC_SMEM  (1024 + 3 * STAGE_B)

template <bool EXPERT, bool GATHER>
__global__ __launch_bounds__(256, 2)
void tc_gemm(const __nv_bfloat16* __restrict__ Ahi, const __nv_bfloat16* __restrict__ Alo,
             const __nv_bfloat16* __restrict__ Bhi, const __nv_bfloat16* __restrict__ Blo,
             float* __restrict__ C, const float* __restrict__ bias,
             const float* __restrict__ resid, int N, int K) {
    extern __shared__ float sm[];
    const int tid = threadIdx.x;

    int bm, bn, cnt = 0, seg = 0, e = 0;
    if (EXPERT) {
        e = blockIdx.z; cnt = g_cnt[e]; seg = g_off[e];
        bm = blockIdx.y * 128;
        if (bm >= cnt) return;
    } else {
        bm = blockIdx.y * 128;
    }
    bn = blockIdx.x * 128;

    const uint32_t sbase = smem_u32(sm);
    const uint32_t tbase = (sbase + 1023) & ~1023u;

    // ---- global source mapping: 2 threads/row, 16 bf16 (32B) each ----
    const int arow = tid >> 1;
    const int half = tid & 1;
    int grow = bm + arow;
    size_t aoff;
    if (EXPERT) {
        int cl = (grow < cnt) ? grow : (cnt - 1);
        aoff = (size_t)(GATHER ? g_tok[seg + cl] : (seg + cl)) * K;
    } else {
        aoff = (size_t)grow * K;
    }
    const __nv_bfloat16* pAh = Ahi + aoff + half * 16;
    const __nv_bfloat16* pAl = Alo + aoff + half * 16;
    const size_t boff = (EXPERT ? (size_t)e * N * K : 0) + (size_t)(bn + arow) * K + half * 16;
    const __nv_bfloat16* pBh = Bhi + boff;
    const __nv_bfloat16* pBl = Blo + boff;

    const uint32_t d0 = swz128((uint32_t)arow * 128 + half * 32);
    const uint32_t d1 = swz128((uint32_t)arow * 128 + half * 32 + 16);
    const uint32_t d2 = swz128((uint32_t)arow * 128 + 64 + half * 32);
    const uint32_t d3 = swz128((uint32_t)arow * 128 + 64 + half * 32 + 16);

    auto issue = [&](int buf, int t) {
        const uint32_t aB = tbase + buf * STAGE_B;
        const uint32_t bB = aB + 16384;
        const int k0 = t * 32;
        cpa16(aB + d0, pAh + k0);
        cpa16(aB + d1, pAh + k0 + 8);
        cpa16(aB + d2, pAl + k0);
        cpa16(aB + d3, pAl + k0 + 8);
        cpa16(bB + d0, pBh + k0);
        cpa16(bB + d1, pBh + k0 + 8);
        cpa16(bB + d2, pBl + k0);
        cpa16(bB + d3, pBl + k0 + 8);
        asm volatile("cp.async.commit_group;" ::: "memory");
    };

    // ---- warp tiling: 8 warps = 2(m) x 4(n), each 64x32 ----
    const int wid = tid >> 5, lane = tid & 31;
    const int wm = wid >> 2, wn = wid & 3;
    const int lrow = lane & 15;
    const int lcolb = (lane >> 4) * 16;

    float acc[4][4][4];
    #pragma unroll
    for (int i = 0; i < 4; i++)
        #pragma unroll
        for (int j = 0; j < 4; j++)
            #pragma unroll
            for (int q = 0; q < 4; q++) acc[i][j][q] = 0.f;

    const int NT = K >> 5;

    issue(0, 0);
    issue(1, 1);
    int buf = 0;
    for (int t = 0; t < NT; ++t) {
        if (t + 2 < NT) {
            asm volatile("cp.async.wait_group 1;" ::: "memory");
        } else {
            asm volatile("cp.async.wait_group 0;" ::: "memory");
        }
        __syncthreads();
        if (t + 2 < NT) {
            int nb = buf + 2; if (nb >= 3) nb -= 3;
            issue(nb, t + 2);
        }

        const uint32_t aB = tbase + buf * STAGE_B;
        const uint32_t bB = aB + 16384;
        #pragma unroll
        for (int s = 0; s < 2; s++) {
            uint32_t bh[2][4], bl[2][4];
            #pragma unroll
            for (int p = 0; p < 2; p++) {
                uint32_t ro = (uint32_t)(wn * 32 + p * 16 + lrow) * 128 + s * 32 + lcolb;
                ldsm_x4(bh[p], bB + swz128(ro));
                ldsm_x4(bl[p], bB + swz128(ro + 64));
            }
            #pragma unroll
            for (int i = 0; i < 4; i++) {
                uint32_t ah[4], al[4];
                uint32_t ro = (uint32_t)(wm * 64 + i * 16 + lrow) * 128 + s * 32 + lcolb;
                ldsm_x4(ah, aB + swz128(ro));
                ldsm_x4(al, aB + swz128(ro + 64));
                #pragma unroll
                for (int j = 0; j < 4; j++) {
                    const int p = j >> 1, o = j & 1;
                    mma_bf16(acc[i][j], ah, bh[p][o], bh[p][o + 2]);
                    mma_bf16(acc[i][j], ah, bl[p][o], bl[p][o + 2]);
                    mma_bf16(acc[i][j], al, bh[p][o], bh[p][o + 2]);
                }
            }
        }
        if (++buf == 3) buf = 0;
    }

    // ---- epilogue ----
    const int qr = lane >> 2;
    const int qc = (lane & 3) * 2;
    #pragma unroll
    for (int i = 0; i < 4; i++) {
        const int lm0 = wm * 64 + i * 16 + qr;
        #pragma unroll
        for (int j = 0; j < 4; j++) {
            const int c = bn + wn * 32 + j * 8 + qc;
            float2 v0 = make_float2(acc[i][j][0], acc[i][j][1]);
            float2 v1 = make_float2(acc[i][j][2], acc[i][j][3]);
            if (bias) {
                float2 bv = *(const float2*)(bias + c);
                v0.x += bv.x; v0.y += bv.y;
                v1.x += bv.x; v1.y += bv.y;
            }
            if (EXPERT) {
                if (bm + lm0 < cnt)
                    *(float2*)(C + (size_t)(seg + bm + lm0) * N + c) = v0;
                if (bm + lm0 + 8 < cnt)
                    *(float2*)(C + (size_t)(seg + bm + lm0 + 8) * N + c) = v1;
            } else {
                const int r0 = bm + lm0;
                if (resid) {
                    float2 rv0 = *(const float2*)(resid + (size_t)r0 * Dd + c);
                    float2 rv1 = *(const float2*)(resid + (size_t)(r0 + 8) * Dd + c);
                    v0.x += rv0.x; v0.y += rv0.y;
                    v1.x += rv1.x; v1.y += rv1.y;
                }
                *(float2*)(C + (size_t)r0 * N + c)       = v0;
                *(float2*)(C + (size_t)(r0 + 8) * N + c) = v1;
            }
        }
    }
}

// ---------------- rmsnorm (optional fp32 + hi/lo plane outputs) ----------------
__global__ void rmsnorm_kernel(const float* __restrict__ x,
                               const float* __restrict__ w,
                               float* __restrict__ out_f32,
                               __nv_bfloat16* __restrict__ oh,
                               __nv_bfloat16* __restrict__ ol) {
    int t = blockIdx.x;
    const float* xr = x + (size_t)t * Dd;
    float ss = 0.f;
    for (int i = threadIdx.x; i < Dd; i += 256) { float vv = xr[i]; ss += vv * vv; }
    __shared__ float red[8];
    #pragma unroll
    for (int o = 16; o; o >>= 1) ss += __shfl_xor_sync(0xffffffffu, ss, o);
    if ((threadIdx.x & 31) == 0) red[threadIdx.x >> 5] = ss;
    __syncthreads();
    if (threadIdx.x < 8) {
        float v = red[threadIdx.x];
        #pragma unroll
        for (int o = 4; o; o >>= 1) v += __shfl_xor_sync(0xffu, v, o);
        if (threadIdx.x == 0) red[0] = v;
    }
    __syncthreads();
    float inv = 1.f / sqrtf(red[0] / (float)Dd + 1e-8f);
    for (int i = threadIdx.x; i < Dd; i += 256) {
        float v = xr[i] * inv * w[i];
        if (out_f32) out_f32[(size_t)t * Dd + i] = v;
        __nv_bfloat16 h, l;
        split2(v, h, l);
        oh[(size_t)t * Dd + i] = h;
        ol[(size_t)t * Dd + i] = l;
    }
}

// ---------------- RoPE on qkv buffer (row stride QKVN) ----------------
__global__ void rope_kernel(float* __restrict__ qkv, int coloff) {
    int gid = blockIdx.x * 256 + threadIdx.x;
    int t = gid >> 10;
    int r = gid & 1023;
    int h = r >> 6;
    int p = r & 63;
    float ang = (float)h * expf(-(float)p * (9.210340371976184f / 64.f));
    float c = cosf(ang), s = sinf(ang);
    float* base = qkv + (size_t)t * QKVN + coloff + h * DHh + 2 * p;
    float x1 = base[0], x2 = base[1];
    base[0] = x1 * c - x2 * s;
    base[1] = x1 * s + x2 * c;
}

// ---------------- attention: 32 q/block, 4 q/warp, lane-per-key ----------------
// dyn smem: Qs[32][128] | Ks[32][132] | Vs[32][132]  (floats)
#define AQS 0
#define AKS 4096
#define AVS (4096 + 32 * 132)
#define ATT_SMEM ((4096 + 2 * 32 * 132) * 4)

__global__ __launch_bounds__(256)
void attn_kernel(const float* __restrict__ QKV,
                 __nv_bfloat16* __restrict__ Oh, __nv_bfloat16* __restrict__ Ol) {
    extern __shared__ float smf[];
    const int b = blockIdx.z, h = blockIdx.y, qg = blockIdx.x;
    const int tid = threadIdx.x;
    const int warp = tid >> 5, lane = tid & 31;

    for (int c = tid; c < 1024; c += 256) {
        int rr = c >> 5, c4 = (c & 31) * 4;
        *(float4*)&smf[AQS + rr * 128 + c4] =
            *(const float4*)&QKV[((size_t)(b * Ss + qg * 32 + rr)) * QKVN + h * DHh + c4];
    }

    const int q0 = qg * 32 + warp * 4;
    float m[4], l[4];
    float4 o[4];
    #pragma unroll
    for (int q = 0; q < 4; q++) {
        m[q] = -INFINITY; l[q] = 0.f;
        o[q] = make_float4(0.f, 0.f, 0.f, 0.f);
    }

    const int ntiles = qg + 1;
    for (int kt = 0; kt < ntiles; kt++) {
        __syncthreads();
        for (int c = tid; c < 1024; c += 256) {
            int rr = c >> 5, c4 = (c & 31) * 4;
            size_t g = ((size_t)(b * Ss + kt * 32 + rr)) * QKVN + h * DHh + c4;
            *(float4*)&smf[AKS + rr * 132 + c4] = *(const float4*)&QKV[g + Dd];
            *(float4*)&smf[AVS + rr * 132 + c4] = *(const float4*)&QKV[g + 2 * Dd];
        }
        __syncthreads();

        const int kj = kt * 32 + lane;
        float4 s4[4];
        #pragma unroll
        for (int q = 0; q < 4; q++) s4[q] = make_float4(0.f, 0.f, 0.f, 0.f);
        const float* krow = &smf[AKS + lane * 132];
        #pragma unroll 8
        for (int c4 = 0; c4 < 32; c4++) {
            float4 kv = *(const float4*)&krow[c4 * 4];
            #pragma unroll
            for (int q = 0; q < 4; q++) {
                float4 qv = *(const float4*)&smf[AQS + (warp * 4 + q) * 128 + c4 * 4];
                s4[q].x = fmaf(qv.x, kv.x, s4[q].x);
                s4[q].y = fmaf(qv.y, kv.y, s4[q].y);
                s4[q].z = fmaf(qv.z, kv.z, s4[q].z);
                s4[q].w = fmaf(qv.w, kv.w, s4[q].w);
            }
        }
        float s[4], w[4];
        #pragma unroll
        for (int q = 0; q < 4; q++) {
            float v = (s4[q].x + s4[q].y) + (s4[q].z + s4[q].w);
            s[q] = (kj <= q0 + q) ? v * 0.08838834764831845f : -INFINITY;
        }
        float tm[4];
        #pragma unroll
        for (int q = 0; q < 4; q++) tm[q] = s[q];
        #pragma unroll
        for (int ofs = 16; ofs; ofs >>= 1)
            #pragma unroll
            for (int q = 0; q < 4; q++)
                tm[q] = fmaxf(tm[q], __shfl_xor_sync(0xffffffffu, tm[q], ofs));
        float ts[4];
        #pragma unroll
        for (int q = 0; q < 4; q++) {
            float mnew = fmaxf(m[q], tm[q]);
            float corr = __expf(m[q] - mnew);
            w[q] = __expf(s[q] - mnew);
            m[q] = mnew;
            l[q] *= corr;
            o[q].x *= corr; o[q].y *= corr; o[q].z *= corr; o[q].w *= corr;
            ts[q] = w[q];
        }
        #pragma unroll
        for (int ofs = 16; ofs; ofs >>= 1)
            #pragma unroll
            for (int q = 0; q < 4; q++)
                ts[q] += __shfl_xor_sync(0xffffffffu, ts[q], ofs);
        #pragma unroll
        for (int q = 0; q < 4; q++) l[q] += ts[q];

        const float* vcol = &smf[AVS + lane * 4];
        #pragma unroll 4
        for (int j = 0; j < 32; j++) {
            float4 vv = *(const float4*)&vcol[j * 132];
            #pragma unroll
            for (int q = 0; q < 4; q++) {
                float wq = __shfl_sync(0xffffffffu, w[q], j);
                o[q].x = fmaf(wq, vv.x, o[q].x);
                o[q].y = fmaf(wq, vv.y, o[q].y);
                o[q].z = fmaf(wq, vv.z, o[q].z);
                o[q].w = fmaf(wq, vv.w, o[q].w);
            }
        }
    }

    #pragma unroll
    for (int q = 0; q < 4; q++) {
        float inv = 1.f / l[q];
        float f[4] = {o[q].x * inv, o[q].y * inv, o[q].z * inv, o[q].w * inv};
        __nv_bfloat16 hh[4], ll[4];
        #pragma unroll
        for (int d = 0; d < 4; d++) split2(f[d], hh[d], ll[d]);
        size_t base = ((size_t)(b * Ss + q0 + q)) * Dd + h * DHh + lane * 4;
        *(ushort4*)(Oh + base) = make_ushort4(*(uint16_t*)&hh[0], *(uint16_t*)&hh[1],
                                              *(uint16_t*)&hh[2], *(uint16_t*)&hh[3]);
        *(ushort4*)(Ol + base) = make_ushort4(*(uint16_t*)&ll[0], *(uint16_t*)&ll[1],
                                              *(uint16_t*)&ll[2], *(uint16_t*)&ll[3]);
    }
}

// ---------------- router ----------------
__global__ void router_kernel(const float* __restrict__ xn, const float* __restrict__ wr,
                              const float* __restrict__ br) {
    int t = blockIdx.x;
    int warp = threadIdx.x >> 5, lane = threadIdx.x & 31;
    const float* xr = xn + (size_t)t * Dd;
    const float* w = wr + (size_t)warp * Dd;
    float s = 0.f;
    for (int i = lane; i < Dd; i += 32) s += xr[i] * w[i];
    #pragma unroll
    for (int o = 16; o; o >>= 1) s += __shfl_xor_sync(0xffffffffu, s, o);
    __shared__ float lg[Ee];
    if (lane == 0) lg[warp] = s + br[warp];
    __syncthreads();
    if (threadIdx.x == 0) {
        int i0 = 0; float v0 = lg[0];
        for (int e = 1; e < Ee; e++) if (lg[e] > v0) { v0 = lg[e]; i0 = e; }
        int i1 = -1; float v1 = -INFINITY;
        for (int e = 0; e < Ee; e++) if (e != i0 && lg[e] > v1) { v1 = lg[e]; i1 = e; }
        float e1 = expf(v1 - v0);
        float w0 = 1.f / (1.f + e1);
        g_tid2[t * 2] = i0; g_tid2[t * 2 + 1] = i1;
        g_twt[t * 2] = w0;  g_twt[t * 2 + 1] = e1 * w0;
    }
}

// ---------------- expert grouping ----------------
__global__ void build_lists_kernel() {
    __shared__ int cnt[Ee], run[Ee];
    int tid = threadIdx.x;
    if (tid < Ee) cnt[tid] = 0;
    __syncthreads();
    for (int i = tid; i < NPAIR; i += 256) atomicAdd(&cnt[g_tid2[i]], 1);
    __syncthreads();
    if (tid == 0) {
        int acc = 0;
        for (int e = 0; e < Ee; e++) { g_cnt[e] = cnt[e]; g_off[e] = acc; run[e] = acc; acc += cnt[e]; }
    }
    __syncthreads();
    for (int i = tid; i < NPAIR; i += 256) {
        int e = g_tid2[i];
        int pos = atomicAdd(&run[e], 1);
        g_tok[pos] = i >> 1;
        g_prow[i] = pos;
    }
}

// ---------------- silu(gate) * up from fused gu buffer -> hi/lo planes ----------------
__global__ void silu_kernel() {
    size_t i4 = ((size_t)blockIdx.x * 256 + threadIdx.x) * 4;   // over NPAIR*HIDh
    size_t row = i4 / HIDh;
    size_t col = i4 % HIDh;
    float4 g = *(float4*)(g_gu + row * GUN + col);
    float4 u = *(float4*)(g_gu + row * GUN + HIDh + col);
    g.x = g.x / (1.f + __expf(-g.x)) * u.x;
    g.y = g.y / (1.f + __expf(-g.y)) * u.y;
    g.z = g.z / (1.f + __expf(-g.z)) * u.z;
    g.w = g.w / (1.f + __expf(-g.w)) * u.w;
    __nv_bfloat16 h[4], l[4];
    split2(g.x, h[0], l[0]); split2(g.y, h[1], l[1]);
    split2(g.z, h[2], l[2]); split2(g.w, h[3], l[3]);
    *(ushort4*)(g_hgb + i4) = make_ushort4(*(uint16_t*)&h[0], *(uint16_t*)&h[1],
                                           *(uint16_t*)&h[2], *(uint16_t*)&h[3]);
    *(ushort4*)(g_lgb + i4) = make_ushort4(*(uint16_t*)&l[0], *(uint16_t*)&l[1],
                                           *(uint16_t*)&l[2], *(uint16_t*)&l[3]);
}

// ---------------- combine ----------------
__global__ void combine_kernel(float* __restrict__ out) {
    int t = blockIdx.x;
    int r0 = g_prow[t * 2], r1 = g_prow[t * 2 + 1];
    float w0 = g_twt[t * 2], w1 = g_twt[t * 2 + 1];
    const float* e0 = g_eo + (size_t)r0 * Dd;
    const float* e1 = g_eo + (size_t)r1 * Dd;
    const float* xr = g_x2 + (size_t)t * Dd;
    float* orow = out + (size_t)t * Dd;
    for (int i = threadIdx.x; i < Dd; i += 256)
        orow[i] = xr[i] + w0 * e0[i] + w1 * e1[i];
}

// ---------------- host launcher ----------------
extern "C" void kernel_launch(void* const* d_in, const int* in_sizes, int n_in,
                              void* d_out, int out_size) {
    const float* x   = (const float*)d_in[0];
    const float* wq  = (const float*)d_in[1];
    const float* bq  = (const float*)d_in[2];
    const float* wk  = (const float*)d_in[3];
    const float* bk  = (const float*)d_in[4];
    const float* wv  = (const float*)d_in[5];
    const float* bv  = (const float*)d_in[6];
    const float* wo  = (const float*)d_in[7];
    const float* bo  = (const float*)d_in[8];
    const float* wr  = (const float*)d_in[9];
    const float* br  = (const float*)d_in[10];
    const float* wg  = (const float*)d_in[11];
    const float* wu  = (const float*)d_in[12];
    const float* wd  = (const float*)d_in[13];
    const float* r1w = (const float*)d_in[14];
    const float* r2w = (const float*)d_in[15];
    float* out = (float*)d_out;

    float *qkv, *x2, *xn2, *gu, *eo, *bqkv;
    __nv_bfloat16 *hxn1, *lxn1, *hatt, *latt, *hxn2, *lxn2, *hgb, *lgb;
    __nv_bfloat16 *hwqkv, *lwqkv, *hwo, *lwo, *hwgu, *lwgu, *hwd, *lwd;
    cudaGetSymbolAddress((void**)&qkv,  g_qkv);
    cudaGetSymbolAddress((void**)&x2,   g_x2);
    cudaGetSymbolAddress((void**)&xn2,  g_xn2);
    cudaGetSymbolAddress((void**)&gu,   g_gu);
    cudaGetSymbolAddress((void**)&eo,   g_eo);
    cudaGetSymbolAddress((void**)&bqkv, g_bqkv);
    cudaGetSymbolAddress((void**)&hxn1, g_hxn1);   cudaGetSymbolAddress((void**)&lxn1, g_lxn1);
    cudaGetSymbolAddress((void**)&hatt, g_hatt);   cudaGetSymbolAddress((void**)&latt, g_latt);
    cudaGetSymbolAddress((void**)&hxn2, g_hxn2);   cudaGetSymbolAddress((void**)&lxn2, g_lxn2);
    cudaGetSymbolAddress((void**)&hgb,  g_hgb);    cudaGetSymbolAddress((void**)&lgb,  g_lgb);
    cudaGetSymbolAddress((void**)&hwqkv, g_hwqkv); cudaGetSymbolAddress((void**)&lwqkv, g_lwqkv);
    cudaGetSymbolAddress((void**)&hwo,  g_hwo);    cudaGetSymbolAddress((void**)&lwo,  g_lwo);
    cudaGetSymbolAddress((void**)&hwgu, g_hwgu);   cudaGetSymbolAddress((void**)&lwgu, g_lwgu);
    cudaGetSymbolAddress((void**)&hwd,  g_hwd);    cudaGetSymbolAddress((void**)&lwd,  g_lwd);

    cudaFuncSetAttribute((const void*)tc_gemm<false, false>,
                         cudaFuncAttributeMaxDynamicSharedMemorySize, TC_SMEM);
    cudaFuncSetAttribute((const void*)tc_gemm<true, true>,
                         cudaFuncAttributeMaxDynamicSharedMemorySize, TC_SMEM);
    cudaFuncSetAttribute((const void*)tc_gemm<true, false>,
                         cudaFuncAttributeMaxDynamicSharedMemorySize, TC_SMEM);
    cudaFuncSetAttribute((const void*)attn_kernel,
                         cudaFuncAttributeMaxDynamicSharedMemorySize, ATT_SMEM);

    // 0) pack weights into hi/lo planes (wq/wk/wv concatenated along N; wg/wu interleaved per expert)
    pack_kernel<<<Dd * Dd / 1024, 256>>>(wq, hwqkv, lwqkv);
    pack_kernel<<<Dd * Dd / 1024, 256>>>(wk, hwqkv + (size_t)Dd * Dd, lwqkv + (size_t)Dd * Dd);
    pack_kernel<<<Dd * Dd / 1024, 256>>>(wv, hwqkv + (size_t)2 * Dd * Dd, lwqkv + (size_t)2 * Dd * Dd);
    pack_kernel<<<Dd * Dd / 1024, 256>>>(wo, hwo, lwo);
    pack_moe_kernel<<<Ee * HIDh * Dd / 1024, 256>>>(wg, hwgu, lwgu, 0);
    pack_moe_kernel<<<Ee * HIDh * Dd / 1024, 256>>>(wu, hwgu, lwgu, HIDh);
    pack_kernel<<<Ee * Dd * HIDh / 1024, 256>>>(wd, hwd, lwd);
    bias_cat_kernel<<<QKVN / 256, 256>>>(bq, bk, bv);

    // 1) rmsnorm1 -> planes only
    rmsnorm_kernel<<<Tt, 256>>>(x, r1w, nullptr, hxn1, lxn1);
    // 2) fused QKV projection (N = 6144)
    tc_gemm<false, false><<<dim3(QKVN / 128, Tt / 128), 256, TC_SMEM>>>(hxn1, lxn1, hwqkv, lwqkv, qkv, bqkv, nullptr, QKVN, Dd);
    // 3) RoPE on q and k slices
    rope_kernel<<<(Tt * Hh * 64) / 256, 256>>>(qkv, 0);
    rope_kernel<<<(Tt * Hh * 64) / 256, 256>>>(qkv, Dd);
    // 4) attention -> att planes
    attn_kernel<<<dim3(Ss / 32, Hh, Bb), 256, ATT_SMEM>>>(qkv, hatt, latt);
    // 5) output projection + residual
    tc_gemm<false, false><<<dim3(Dd / 128, Tt / 128), 256, TC_SMEM>>>(hatt, latt, hwo, lwo, x2, bo, x, Dd, Dd);
    // 6) rmsnorm2 -> fp32 (router) + planes (MoE)
    rmsnorm_kernel<<<Tt, 256>>>(x2, r2w, xn2, hxn2, lxn2);
    // 7) router + grouping
    router_kernel<<<Tt, 256>>>(xn2, wr, br);
    build_lists_kernel<<<1, 256>>>();
    // 8) MoE: fused gate+up (N = 8192), silu, down
    tc_gemm<true, true ><<<dim3(GUN / 128, NPAIR / 128, Ee), 256, TC_SMEM>>>(hxn2, lxn2, hwgu, lwgu, gu, nullptr, nullptr, GUN, Dd);
    silu_kernel<<<((size_t)NPAIR * HIDh / 4) / 256, 256>>>();
    tc_gemm<true, false><<<dim3(Dd / 128, NPAIR / 128, Ee), 256, TC_SMEM>>>(hgb, lgb, hwd, lwd, eo, nullptr, nullptr, Dd, HIDh);
    // 9) combine
    combine_kernel<<<Tt, 256>>>(out);
}

// round 15
// speedup vs baseline: 2.2623x; 1.0072x over previous
#include <cuda_runtime.h>
#include <cuda_bf16.h>
#include <math.h>
#include <stdint.h>

// ---------------- problem constants ----------------
#define Bb   2
#define Ss   1024
#define Dd   2048
#define Hh   16
#define DHh  128
#define Ee   8
#define HIDh 4096
#define Tt   (Bb * Ss)       // 2048 tokens
#define NPAIR (Tt * 2)       // 4096 (token, expert) pairs
#define QKVN (3 * Dd)        // 6144
#define GUN  (2 * HIDh)      // 8192

// ---------------- device scratch ----------------
// fp32
__device__ float g_qkv[(size_t)Tt * QKVN];
__device__ float g_x2 [Tt * Dd];
__device__ float g_xn2[Tt * Dd];
__device__ float g_eo [(size_t)NPAIR * Dd];
__device__ float g_bqkv[QKVN];
// bf16 hi/lo planes (x = hi + lo split)
__device__ __nv_bfloat16 g_hxn1[Tt * Dd], g_lxn1[Tt * Dd];
__device__ __nv_bfloat16 g_hatt[Tt * Dd], g_latt[Tt * Dd];
__device__ __nv_bfloat16 g_hxn2[Tt * Dd], g_lxn2[Tt * Dd];
__device__ __nv_bfloat16 g_hgb [(size_t)NPAIR * HIDh], g_lgb[(size_t)NPAIR * HIDh];
__device__ __nv_bfloat16 g_hwqkv[(size_t)QKVN * Dd], g_lwqkv[(size_t)QKVN * Dd];
__device__ __nv_bfloat16 g_hwo [Dd * Dd], g_lwo[Dd * Dd];
__device__ __nv_bfloat16 g_hwgu[(size_t)Ee * GUN * Dd], g_lwgu[(size_t)Ee * GUN * Dd];
__device__ __nv_bfloat16 g_hwd [(size_t)Ee * Dd * HIDh], g_lwd[(size_t)Ee * Dd * HIDh];
// routing
__device__ int   g_tid2[NPAIR];
__device__ float g_twt [NPAIR];
__device__ int   g_cnt[Ee];
__device__ int   g_off[Ee];
__device__ int   g_tok[NPAIR];
__device__ int   g_prow[NPAIR];

// ---------------- helpers ----------------
__device__ __forceinline__ uint32_t smem_u32(const void* p) {
    uint32_t a;
    asm("{ .reg .u64 t; cvta.to.shared.u64 t, %1; cvt.u32.u64 %0, t; }" : "=r"(a) : "l"(p));
    return a;
}
__device__ __forceinline__ uint32_t swz128(uint32_t off) {
    return off ^ ((off >> 3) & 0x70);
}
__device__ __forceinline__ void ldsm_x4(uint32_t* r, uint32_t addr) {
    asm volatile("ldmatrix.sync.aligned.m8n8.x4.shared.b16 {%0,%1,%2,%3}, [%4];"
                 : "=r"(r[0]), "=r"(r[1]), "=r"(r[2]), "=r"(r[3]) : "r"(addr));
}
__device__ __forceinline__ void mma_bf16(float* c, const uint32_t* a, uint32_t b0, uint32_t b1) {
    asm volatile("mma.sync.aligned.m16n8k16.row.col.f32.bf16.bf16.f32 "
                 "{%0,%1,%2,%3}, {%4,%5,%6,%7}, {%8,%9}, {%0,%1,%2,%3};"
                 : "+f"(c[0]), "+f"(c[1]), "+f"(c[2]), "+f"(c[3])
                 : "r"(a[0]), "r"(a[1]), "r"(a[2]), "r"(a[3]), "r"(b0), "r"(b1));
}
__device__ __forceinline__ void cpa16(uint32_t dst, const void* src) {
    asm volatile("cp.async.cg.shared.global [%0], [%1], 16;" :: "r"(dst), "l"(src) : "memory");
}
__device__ __forceinline__ void split2(float f, __nv_bfloat16& h, __nv_bfloat16& l) {
    h = __float2bfloat16(f);
    l = __float2bfloat16(f - __bfloat162float(h));
}
__device__ __forceinline__ void store_split4(__nv_bfloat16* oh, __nv_bfloat16* ol,
                                             size_t o, float4 v) {
    __nv_bfloat16 h[4], l[4];
    split2(v.x, h[0], l[0]); split2(v.y, h[1], l[1]);
    split2(v.z, h[2], l[2]); split2(v.w, h[3], l[3]);
    *(ushort4*)(oh + o) = make_ushort4(*(uint16_t*)&h[0], *(uint16_t*)&h[1],
                                       *(uint16_t*)&h[2], *(uint16_t*)&h[3]);
    *(ushort4*)(ol + o) = make_ushort4(*(uint16_t*)&l[0], *(uint16_t*)&l[1],
                                       *(uint16_t*)&l[2], *(uint16_t*)&l[3]);
}

// ---------------- pack conversion, MLP=4 (4 quarter-strided float4/thread) ----------------
// nf4q = n_elems / 16 (quarter size in float4 units)
__global__ void pack_kernel(const float* __restrict__ in,
                            __nv_bfloat16* __restrict__ oh,
                            __nv_bfloat16* __restrict__ ol, size_t nf4q) {
    size_t t = (size_t)blockIdx.x * 256 + threadIdx.x;
    float4 v[4];
    #pragma unroll
    for (int q = 0; q < 4; q++) v[q] = ((const float4*)in)[t + q * nf4q];
    #pragma unroll
    for (int q = 0; q < 4; q++) store_split4(oh, ol, (t + q * nf4q) * 4, v[q]);
}

// pack [E][HID][D] src into [E][2*HID][D] with gate rows at 2h, up rows at 2h+1
__global__ void pack_moe_kernel(const float* __restrict__ in,
                                __nv_bfloat16* __restrict__ oh,
                                __nv_bfloat16* __restrict__ ol, int which, size_t nf4q) {
    size_t t = (size_t)blockIdx.x * 256 + threadIdx.x;
    float4 v[4]; size_t off[4];
    #pragma unroll
    for (int q = 0; q < 4; q++) {
        size_t i4 = t + q * nf4q;
        v[q] = ((const float4*)in)[i4];
        size_t d4  = i4 & (Dd / 4 - 1);
        size_t row = i4 >> 9;                 // / (Dd/4)
        size_t h   = row & (HIDh - 1);
        size_t e   = row >> 12;               // / HIDh
        off[q] = ((e * 2 * HIDh + 2 * h + which) * (size_t)Dd) + d4 * 4;
    }
    #pragma unroll
    for (int q = 0; q < 4; q++) store_split4(oh, ol, off[q], v[q]);
}

__global__ void bias_cat_kernel(const float* __restrict__ bq, const float* __restrict__ bk,
                                const float* __restrict__ bv) {
    int i = blockIdx.x * 256 + threadIdx.x;
    float v = (i < Dd) ? bq[i] : (i < 2 * Dd) ? bk[i - Dd] : bv[i - 2 * Dd];
    g_bqkv[i] = v;
}

// ---------------- 3x-bf16 mma.sync GEMM, 3-stage cp.async pipeline ----------------
// C[M,N] = A[M,K] @ B[N,K]^T. CTA tile 128x128, K-tile 32 elems.
// Smem row (128B, swz128): [0,64) hi bf16 k0..31, [64,128) lo bf16 k0..31.
// SILU variant: N-cols are interleaved (gate,up) pairs; epilogue computes
// silu(gate)*up and writes hi/lo planes to g_hgb/g_lgb directly.
#define STAGE_B  32768
#define TC_SMEM  (1024 + 3 * STAGE_B)

template <bool EXPERT, bool GATHER, bool SILU>
__global__ __launch_bounds__(256, 2)
void tc_gemm(const __nv_bfloat16* __restrict__ Ahi, const __nv_bfloat16* __restrict__ Alo,
             const __nv_bfloat16* __restrict__ Bhi, const __nv_bfloat16* __restrict__ Blo,
             float* __restrict__ C, const float* __restrict__ bias,
             const float* __restrict__ resid, int N, int K) {
    extern __shared__ float sm[];
    const int tid = threadIdx.x;

    int bm, bn, cnt = 0, seg = 0, e = 0;
    if (EXPERT) {
        e = blockIdx.z; cnt = g_cnt[e]; seg = g_off[e];
        bm = blockIdx.y * 128;
        if (bm >= cnt) return;
    } else {
        bm = blockIdx.y * 128;
    }
    bn = blockIdx.x * 128;

    const uint32_t sbase = smem_u32(sm);
    const uint32_t tbase = (sbase + 1023) & ~1023u;

    // ---- global source mapping: 2 threads/row, 16 bf16 (32B) each ----
    const int arow = tid >> 1;
    const int half = tid & 1;
    int grow = bm + arow;
    size_t aoff;
    if (EXPERT) {
        int cl = (grow < cnt) ? grow : (cnt - 1);
        aoff = (size_t)(GATHER ? g_tok[seg + cl] : (seg + cl)) * K;
    } else {
        aoff = (size_t)grow * K;
    }
    const __nv_bfloat16* pAh = Ahi + aoff + half * 16;
    const __nv_bfloat16* pAl = Alo + aoff + half * 16;
    const size_t boff = (EXPERT ? (size_t)e * N * K : 0) + (size_t)(bn + arow) * K + half * 16;
    const __nv_bfloat16* pBh = Bhi + boff;
    const __nv_bfloat16* pBl = Blo + boff;

    const uint32_t d0 = swz128((uint32_t)arow * 128 + half * 32);
    const uint32_t d1 = swz128((uint32_t)arow * 128 + half * 32 + 16);
    const uint32_t d2 = swz128((uint32_t)arow * 128 + 64 + half * 32);
    const uint32_t d3 = swz128((uint32_t)arow * 128 + 64 + half * 32 + 16);

    auto issue = [&](int buf, int t) {
        const uint32_t aB = tbase + buf * STAGE_B;
        const uint32_t bB = aB + 16384;
        const int k0 = t * 32;
        cpa16(aB + d0, pAh + k0);
        cpa16(aB + d1, pAh + k0 + 8);
        cpa16(aB + d2, pAl + k0);
        cpa16(aB + d3, pAl + k0 + 8);
        cpa16(bB + d0, pBh + k0);
        cpa16(bB + d1, pBh + k0 + 8);
        cpa16(bB + d2, pBl + k0);
        cpa16(bB + d3, pBl + k0 + 8);
        asm volatile("cp.async.commit_group;" ::: "memory");
    };

    // ---- warp tiling: 8 warps = 2(m) x 4(n), each 64x32 ----
    const int wid = tid >> 5, lane = tid & 31;
    const int wm = wid >> 2, wn = wid & 3;
    const int lrow = lane & 15;
    const int lcolb = (lane >> 4) * 16;

    float acc[4][4][4];
    #pragma unroll
    for (int i = 0; i < 4; i++)
        #pragma unroll
        for (int j = 0; j < 4; j++)
            #pragma unroll
            for (int q = 0; q < 4; q++) acc[i][j][q] = 0.f;

    const int NT = K >> 5;

    issue(0, 0);
    issue(1, 1);
    int buf = 0;
    for (int t = 0; t < NT; ++t) {
        if (t + 2 < NT) {
            asm volatile("cp.async.wait_group 1;" ::: "memory");
        } else {
            asm volatile("cp.async.wait_group 0;" ::: "memory");
        }
        __syncthreads();
        if (t + 2 < NT) {
            int nb = buf + 2; if (nb >= 3) nb -= 3;
            issue(nb, t + 2);
        }

        const uint32_t aB = tbase + buf * STAGE_B;
        const uint32_t bB = aB + 16384;
        #pragma unroll
        for (int s = 0; s < 2; s++) {
            uint32_t bh[2][4], bl[2][4];
            #pragma unroll
            for (int p = 0; p < 2; p++) {
                uint32_t ro = (uint32_t)(wn * 32 + p * 16 + lrow) * 128 + s * 32 + lcolb;
                ldsm_x4(bh[p], bB + swz128(ro));
                ldsm_x4(bl[p], bB + swz128(ro + 64));
            }
            #pragma unroll
            for (int i = 0; i < 4; i++) {
                uint32_t ah[4], al[4];
                uint32_t ro = (uint32_t)(wm * 64 + i * 16 + lrow) * 128 + s * 32 + lcolb;
                ldsm_x4(ah, aB + swz128(ro));
                ldsm_x4(al, aB + swz128(ro + 64));
                #pragma unroll
                for (int j = 0; j < 4; j++) {
                    const int p = j >> 1, o = j & 1;
                    mma_bf16(acc[i][j], ah, bh[p][o], bh[p][o + 2]);
                    mma_bf16(acc[i][j], ah, bl[p][o], bl[p][o + 2]);
                    mma_bf16(acc[i][j], al, bh[p][o], bh[p][o + 2]);
                }
            }
        }
        if (++buf == 3) buf = 0;
    }

    // ---- epilogue ----
    const int qr = lane >> 2;
    const int qc = (lane & 3) * 2;
    #pragma unroll
    for (int i = 0; i < 4; i++) {
        const int lm0 = wm * 64 + i * 16 + qr;
        #pragma unroll
        for (int j = 0; j < 4; j++) {
            const int c = bn + wn * 32 + j * 8 + qc;
            if (SILU) {
                // cols (c, c+1) = (gate_h, up_h), h = c/2
                const int h = c >> 1;
                float g0 = acc[i][j][0], u0 = acc[i][j][1];
                float g1 = acc[i][j][2], u1 = acc[i][j][3];
                float s0 = g0 / (1.f + __expf(-g0)) * u0;
                float s1 = g1 / (1.f + __expf(-g1)) * u1;
                if (bm + lm0 < cnt) {
                    __nv_bfloat16 hh, ll;
                    split2(s0, hh, ll);
                    size_t o = (size_t)(seg + bm + lm0) * HIDh + h;
                    g_hgb[o] = hh; g_lgb[o] = ll;
                }
                if (bm + lm0 + 8 < cnt) {
                    __nv_bfloat16 hh, ll;
                    split2(s1, hh, ll);
                    size_t o = (size_t)(seg + bm + lm0 + 8) * HIDh + h;
                    g_hgb[o] = hh; g_lgb[o] = ll;
                }
            } else {
                float2 v0 = make_float2(acc[i][j][0], acc[i][j][1]);
                float2 v1 = make_float2(acc[i][j][2], acc[i][j][3]);
                if (bias) {
                    float2 bv = *(const float2*)(bias + c);
                    v0.x += bv.x; v0.y += bv.y;
                    v1.x += bv.x; v1.y += bv.y;
                }
                if (EXPERT) {
                    if (bm + lm0 < cnt)
                        *(float2*)(C + (size_t)(seg + bm + lm0) * N + c) = v0;
                    if (bm + lm0 + 8 < cnt)
                        *(float2*)(C + (size_t)(seg + bm + lm0 + 8) * N + c) = v1;
                } else {
                    const int r0 = bm + lm0;
                    if (resid) {
                        float2 rv0 = *(const float2*)(resid + (size_t)r0 * Dd + c);
                        float2 rv1 = *(const float2*)(resid + (size_t)(r0 + 8) * Dd + c);
                        v0.x += rv0.x; v0.y += rv0.y;
                        v1.x += rv1.x; v1.y += rv1.y;
                    }
                    *(float2*)(C + (size_t)r0 * N + c)       = v0;
                    *(float2*)(C + (size_t)(r0 + 8) * N + c) = v1;
                }
            }
        }
    }
}

// ---------------- rmsnorm (optional fp32 + hi/lo plane outputs) ----------------
__global__ void rmsnorm_kernel(const float* __restrict__ x,
                               const float* __restrict__ w,
                               float* __restrict__ out_f32,
                               __nv_bfloat16* __restrict__ oh,
                               __nv_bfloat16* __restrict__ ol) {
    int t = blockIdx.x;
    const float* xr = x + (size_t)t * Dd;
    float ss = 0.f;
    for (int i = threadIdx.x; i < Dd; i += 256) { float vv = xr[i]; ss += vv * vv; }
    __shared__ float red[8];
    #pragma unroll
    for (int o = 16; o; o >>= 1) ss += __shfl_xor_sync(0xffffffffu, ss, o);
    if ((threadIdx.x & 31) == 0) red[threadIdx.x >> 5] = ss;
    __syncthreads();
    if (threadIdx.x < 8) {
        float v = red[threadIdx.x];
        #pragma unroll
        for (int o = 4; o; o >>= 1) v += __shfl_xor_sync(0xffu, v, o);
        if (threadIdx.x == 0) red[0] = v;
    }
    __syncthreads();
    float inv = 1.f / sqrtf(red[0] / (float)Dd + 1e-8f);
    for (int i = threadIdx.x; i < Dd; i += 256) {
        float v = xr[i] * inv * w[i];
        if (out_f32) out_f32[(size_t)t * Dd + i] = v;
        __nv_bfloat16 h, l;
        split2(v, h, l);
        oh[(size_t)t * Dd + i] = h;
        ol[(size_t)t * Dd + i] = l;
    }
}

// ---------------- RoPE on q and k slices in one launch ----------------
__global__ void rope_kernel(float* __restrict__ qkv) {
    int gid = blockIdx.x * 256 + threadIdx.x;          // 2 * Tt*Hh*64
    int coloff = (gid >= Tt * Hh * 64) ? Dd : 0;
    int g = gid & (Tt * Hh * 64 - 1);
    int t = g >> 10;
    int r = g & 1023;
    int h = r >> 6;
    int p = r & 63;
    float ang = (float)h * expf(-(float)p * (9.210340371976184f / 64.f));
    float c = cosf(ang), s = sinf(ang);
    float* base = qkv + (size_t)t * QKVN + coloff + h * DHh + 2 * p;
    float x1 = base[0], x2 = base[1];
    base[0] = x1 * c - x2 * s;
    base[1] = x1 * s + x2 * c;
}

// ---------------- attention: 32 q/block, 4 q/warp, lane-per-key ----------------
// dyn smem: Qs[32][128] | Ks[32][132] | Vs[32][132]  (floats)
#define AQS 0
#define AKS 4096
#define AVS (4096 + 32 * 132)
#define ATT_SMEM ((4096 + 2 * 32 * 132) * 4)

__global__ __launch_bounds__(256)
void attn_kernel(const float* __restrict__ QKV,
                 __nv_bfloat16* __restrict__ Oh, __nv_bfloat16* __restrict__ Ol) {
    extern __shared__ float smf[];
    const int b = blockIdx.z, h = blockIdx.y, qg = blockIdx.x;
    const int tid = threadIdx.x;
    const int warp = tid >> 5, lane = tid & 31;

    for (int c = tid; c < 1024; c += 256) {
        int rr = c >> 5, c4 = (c & 31) * 4;
        *(float4*)&smf[AQS + rr * 128 + c4] =
            *(const float4*)&QKV[((size_t)(b * Ss + qg * 32 + rr)) * QKVN + h * DHh + c4];
    }

    const int q0 = qg * 32 + warp * 4;
    float m[4], l[4];
    float4 o[4];
    #pragma unroll
    for (int q = 0; q < 4; q++) {
        m[q] = -INFINITY; l[q] = 0.f;
        o[q] = make_float4(0.f, 0.f, 0.f, 0.f);
    }

    const int ntiles = qg + 1;
    for (int kt = 0; kt < ntiles; kt++) {
        __syncthreads();
        for (int c = tid; c < 1024; c += 256) {
            int rr = c >> 5, c4 = (c & 31) * 4;
            size_t g = ((size_t)(b * Ss + kt * 32 + rr)) * QKVN + h * DHh + c4;
            *(float4*)&smf[AKS + rr * 132 + c4] = *(const float4*)&QKV[g + Dd];
            *(float4*)&smf[AVS + rr * 132 + c4] = *(const float4*)&QKV[g + 2 * Dd];
        }
        __syncthreads();

        const int kj = kt * 32 + lane;
        float4 s4[4];
        #pragma unroll
        for (int q = 0; q < 4; q++) s4[q] = make_float4(0.f, 0.f, 0.f, 0.f);
        const float* krow = &smf[AKS + lane * 132];
        #pragma unroll 8
        for (int c4 = 0; c4 < 32; c4++) {
            float4 kv = *(const float4*)&krow[c4 * 4];
            #pragma unroll
            for (int q = 0; q < 4; q++) {
                float4 qv = *(const float4*)&smf[AQS + (warp * 4 + q) * 128 + c4 * 4];
                s4[q].x = fmaf(qv.x, kv.x, s4[q].x);
                s4[q].y = fmaf(qv.y, kv.y, s4[q].y);
                s4[q].z = fmaf(qv.z, kv.z, s4[q].z);
                s4[q].w = fmaf(qv.w, kv.w, s4[q].w);
            }
        }
        float s[4], w[4];
        #pragma unroll
        for (int q = 0; q < 4; q++) {
            float v = (s4[q].x + s4[q].y) + (s4[q].z + s4[q].w);
            s[q] = (kj <= q0 + q) ? v * 0.08838834764831845f : -INFINITY;
        }
        float tm[4];
        #pragma unroll
        for (int q = 0; q < 4; q++) tm[q] = s[q];
        #pragma unroll
        for (int ofs = 16; ofs; ofs >>= 1)
            #pragma unroll
            for (int q = 0; q < 4; q++)
                tm[q] = fmaxf(tm[q], __shfl_xor_sync(0xffffffffu, tm[q], ofs));
        float ts[4];
        #pragma unroll
        for (int q = 0; q < 4; q++) {
            float mnew = fmaxf(m[q], tm[q]);
            float corr = __expf(m[q] - mnew);
            w[q] = __expf(s[q] - mnew);
            m[q] = mnew;
            l[q] *= corr;
            o[q].x *= corr; o[q].y *= corr; o[q].z *= corr; o[q].w *= corr;
            ts[q] = w[q];
        }
        #pragma unroll
        for (int ofs = 16; ofs; ofs >>= 1)
            #pragma unroll
            for (int q = 0; q < 4; q++)
                ts[q] += __shfl_xor_sync(0xffffffffu, ts[q], ofs);
        #pragma unroll
        for (int q = 0; q < 4; q++) l[q] += ts[q];

        const float* vcol = &smf[AVS + lane * 4];
        #pragma unroll 4
        for (int j = 0; j < 32; j++) {
            float4 vv = *(const float4*)&vcol[j * 132];
            #pragma unroll
            for (int q = 0; q < 4; q++) {
                float wq = __shfl_sync(0xffffffffu, w[q], j);
                o[q].x = fmaf(wq, vv.x, o[q].x);
                o[q].y = fmaf(wq, vv.y, o[q].y);
                o[q].z = fmaf(wq, vv.z, o[q].z);
                o[q].w = fmaf(wq, vv.w, o[q].w);
            }
        }
    }

    #pragma unroll
    for (int q = 0; q < 4; q++) {
        float inv = 1.f / l[q];
        float f[4] = {o[q].x * inv, o[q].y * inv, o[q].z * inv, o[q].w * inv};
        __nv_bfloat16 hh[4], ll[4];
        #pragma unroll
        for (int d = 0; d < 4; d++) split2(f[d], hh[d], ll[d]);
        size_t base = ((size_t)(b * Ss + q0 + q)) * Dd + h * DHh + lane * 4;
        *(ushort4*)(Oh + base) = make_ushort4(*(uint16_t*)&hh[0], *(uint16_t*)&hh[1],
                                              *(uint16_t*)&hh[2], *(uint16_t*)&hh[3]);
        *(ushort4*)(Ol + base) = make_ushort4(*(uint16_t*)&ll[0], *(uint16_t*)&ll[1],
                                              *(uint16_t*)&ll[2], *(uint16_t*)&ll[3]);
    }
}

// ---------------- router ----------------
__global__ void router_kernel(const float* __restrict__ xn, const float* __restrict__ wr,
                              const float* __restrict__ br) {
    int t = blockIdx.x;
    int warp = threadIdx.x >> 5, lane = threadIdx.x & 31;
    const float* xr = xn + (size_t)t * Dd;
    const float* w = wr + (size_t)warp * Dd;
    float s = 0.f;
    for (int i = lane; i < Dd; i += 32) s += xr[i] * w[i];
    #pragma unroll
    for (int o = 16; o; o >>= 1) s += __shfl_xor_sync(0xffffffffu, s, o);
    __shared__ float lg[Ee];
    if (lane == 0) lg[warp] = s + br[warp];
    __syncthreads();
    if (threadIdx.x == 0) {
        int i0 = 0; float v0 = lg[0];
        for (int e = 1; e < Ee; e++) if (lg[e] > v0) { v0 = lg[e]; i0 = e; }
        int i1 = -1; float v1 = -INFINITY;
        for (int e = 0; e < Ee; e++) if (e != i0 && lg[e] > v1) { v1 = lg[e]; i1 = e; }
        float e1 = expf(v1 - v0);
        float w0 = 1.f / (1.f + e1);
        g_tid2[t * 2] = i0; g_tid2[t * 2 + 1] = i1;
        g_twt[t * 2] = w0;  g_twt[t * 2 + 1] = e1 * w0;
    }
}

// ---------------- expert grouping ----------------
__global__ void build_lists_kernel() {
    __shared__ int cnt[Ee], run[Ee];
    int tid = threadIdx.x;
    if (tid < Ee) cnt[tid] = 0;
    __syncthreads();
    for (int i = tid; i < NPAIR; i += 256) atomicAdd(&cnt[g_tid2[i]], 1);
    __syncthreads();
    if (tid == 0) {
        int acc = 0;
        for (int e = 0; e < Ee; e++) { g_cnt[e] = cnt[e]; g_off[e] = acc; run[e] = acc; acc += cnt[e]; }
    }
    __syncthreads();
    for (int i = tid; i < NPAIR; i += 256) {
        int e = g_tid2[i];
        int pos = atomicAdd(&run[e], 1);
        g_tok[pos] = i >> 1;
        g_prow[i] = pos;
    }
}

// ---------------- combine ----------------
__global__ void combine_kernel(float* __restrict__ out) {
    int t = blockIdx.x;
    int r0 = g_prow[t * 2], r1 = g_prow[t * 2 + 1];
    float w0 = g_twt[t * 2], w1 = g_twt[t * 2 + 1];
    const float* e0 = g_eo + (size_t)r0 * Dd;
    const float* e1 = g_eo + (size_t)r1 * Dd;
    const float* xr = g_x2 + (size_t)t * Dd;
    float* orow = out + (size_t)t * Dd;
    for (int i = threadIdx.x; i < Dd; i += 256)
        orow[i] = xr[i] + w0 * e0[i] + w1 * e1[i];
}

// ---------------- host launcher ----------------
extern "C" void kernel_launch(void* const* d_in, const int* in_sizes, int n_in,
                              void* d_out, int out_size) {
    const float* x   = (const float*)d_in[0];
    const float* wq  = (const float*)d_in[1];
    const float* bq  = (const float*)d_in[2];
    const float* wk  = (const float*)d_in[3];
    const float* bk  = (const float*)d_in[4];
    const float* wv  = (const float*)d_in[5];
    const float* bv  = (const float*)d_in[6];
    const float* wo  = (const float*)d_in[7];
    const float* bo  = (const float*)d_in[8];
    const float* wr  = (const float*)d_in[9];
    const float* br  = (const float*)d_in[10];
    const float* wg  = (const float*)d_in[11];
    const float* wu  = (const float*)d_in[12];
    const float* wd  = (const float*)d_in[13];
    const float* r1w = (const float*)d_in[14];
    const float* r2w = (const float*)d_in[15];
    float* out = (float*)d_out;

    float *qkv, *x2, *xn2, *eo, *bqkv;
    __nv_bfloat16 *hxn1, *lxn1, *hatt, *latt, *hxn2, *lxn2, *hgb, *lgb;
    __nv_bfloat16 *hwqkv, *lwqkv, *hwo, *lwo, *hwgu, *lwgu, *hwd, *lwd;
    cudaGetSymbolAddress((void**)&qkv,  g_qkv);
    cudaGetSymbolAddress((void**)&x2,   g_x2);
    cudaGetSymbolAddress((void**)&xn2,  g_xn2);
    cudaGetSymbolAddress((void**)&eo,   g_eo);
    cudaGetSymbolAddress((void**)&bqkv, g_bqkv);
    cudaGetSymbolAddress((void**)&hxn1, g_hxn1);   cudaGetSymbolAddress((void**)&lxn1, g_lxn1);
    cudaGetSymbolAddress((void**)&hatt, g_hatt);   cudaGetSymbolAddress((void**)&latt, g_latt);
    cudaGetSymbolAddress((void**)&hxn2, g_hxn2);   cudaGetSymbolAddress((void**)&lxn2, g_lxn2);
    cudaGetSymbolAddress((void**)&hgb,  g_hgb);    cudaGetSymbolAddress((void**)&lgb,  g_lgb);
    cudaGetSymbolAddress((void**)&hwqkv, g_hwqkv); cudaGetSymbolAddress((void**)&lwqkv, g_lwqkv);
    cudaGetSymbolAddress((void**)&hwo,  g_hwo);    cudaGetSymbolAddress((void**)&lwo,  g_lwo);
    cudaGetSymbolAddress((void**)&hwgu, g_hwgu);   cudaGetSymbolAddress((void**)&lwgu, g_lwgu);
    cudaGetSymbolAddress((void**)&hwd,  g_hwd);    cudaGetSymbolAddress((void**)&lwd,  g_lwd);

    cudaFuncSetAttribute((const void*)tc_gemm<false, false, false>,
                         cudaFuncAttributeMaxDynamicSharedMemorySize, TC_SMEM);
    cudaFuncSetAttribute((const void*)tc_gemm<true, true, true>,
                         cudaFuncAttributeMaxDynamicSharedMemorySize, TC_SMEM);
    cudaFuncSetAttribute((const void*)tc_gemm<true, false, false>,
                         cudaFuncAttributeMaxDynamicSharedMemorySize, TC_SMEM);
    cudaFuncSetAttribute((const void*)attn_kernel,
                         cudaFuncAttributeMaxDynamicSharedMemorySize, ATT_SMEM);

    // 0) pack weights (hi/lo planes). n/16 per quarter; grids = n/4096.
    const size_t qD = (size_t)Dd * Dd / 16;           // quarter for Dd*Dd
    const size_t qM = (size_t)Ee * HIDh * Dd / 16;    // quarter for expert mats
    pack_kernel<<<Dd * Dd / 4096, 256>>>(wq, hwqkv, lwqkv, qD);
    pack_kernel<<<Dd * Dd / 4096, 256>>>(wk, hwqkv + (size_t)Dd * Dd, lwqkv + (size_t)Dd * Dd, qD);
    pack_kernel<<<Dd * Dd / 4096, 256>>>(wv, hwqkv + (size_t)2 * Dd * Dd, lwqkv + (size_t)2 * Dd * Dd, qD);
    pack_kernel<<<Dd * Dd / 4096, 256>>>(wo, hwo, lwo, qD);
    pack_moe_kernel<<<Ee * HIDh * Dd / 4096, 256>>>(wg, hwgu, lwgu, 0, qM);
    pack_moe_kernel<<<Ee * HIDh * Dd / 4096, 256>>>(wu, hwgu, lwgu, 1, qM);
    pack_kernel<<<Ee * Dd * HIDh / 4096, 256>>>(wd, hwd, lwd, qM);
    bias_cat_kernel<<<QKVN / 256, 256>>>(bq, bk, bv);

    // 1) rmsnorm1 -> planes only
    rmsnorm_kernel<<<Tt, 256>>>(x, r1w, nullptr, hxn1, lxn1);
    // 2) fused QKV projection (N = 6144)
    tc_gemm<false, false, false><<<dim3(QKVN / 128, Tt / 128), 256, TC_SMEM>>>(hxn1, lxn1, hwqkv, lwqkv, qkv, bqkv, nullptr, QKVN, Dd);
    // 3) RoPE on q and k slices (single launch)
    rope_kernel<<<(2 * Tt * Hh * 64) / 256, 256>>>(qkv);
    // 4) attention -> att planes
    attn_kernel<<<dim3(Ss / 32, Hh, Bb), 256, ATT_SMEM>>>(qkv, hatt, latt);
    // 5) output projection + residual
    tc_gemm<false, false, false><<<dim3(Dd / 128, Tt / 128), 256, TC_SMEM>>>(hatt, latt, hwo, lwo, x2, bo, x, Dd, Dd);
    // 6) rmsnorm2 -> fp32 (router) + planes (MoE)
    rmsnorm_kernel<<<Tt, 256>>>(x2, r2w, xn2, hxn2, lxn2);
    // 7) router + grouping
    router_kernel<<<Tt, 256>>>(xn2, wr, br);
    build_lists_kernel<<<1, 256>>>();
    // 8) MoE: fused gate+up (N = 8192, interleaved pairs) with silu epilogue, then down
    tc_gemm<true, true, true><<<dim3(GUN / 128, NPAIR / 128, Ee), 256, TC_SMEM>>>(hxn2, lxn2, hwgu, lwgu, nullptr, nullptr, nullptr, GUN, Dd);
    tc_gemm<true, false, false><<<dim3(Dd / 128, NPAIR / 128, Ee), 256, TC_SMEM>>>(hgb, lgb, hwd, lwd, eo, nullptr, nullptr, Dd, HIDh);
    // 9) combine
    combine_kernel<<<Tt, 256>>>(out);
}

// round 16
// speedup vs baseline: 2.3921x; 1.0574x over previous
#include <cuda_runtime.h>
#include <cuda_bf16.h>
#include <math.h>
#include <stdint.h>

// ---------------- problem constants ----------------
#define Bb   2
#define Ss   1024
#define Dd   2048
#define Hh   16
#define DHh  128
#define Ee   8
#define HIDh 4096
#define Tt   (Bb * Ss)       // 2048 tokens
#define NPAIR (Tt * 2)       // 4096 (token, expert) pairs
#define QKVN (3 * Dd)        // 6144
#define GUN  (2 * HIDh)      // 8192

// ---------------- device scratch ----------------
// fp32
__device__ float g_qkv[(size_t)Tt * QKVN];
__device__ float g_x2 [Tt * Dd];
__device__ float g_xn2[Tt * Dd];
__device__ float g_eo [(size_t)NPAIR * Dd];
__device__ float g_bqkv[QKVN];
// bf16 hi/lo planes (x = hi + lo split)
__device__ __nv_bfloat16 g_hxn1[Tt * Dd], g_lxn1[Tt * Dd];
__device__ __nv_bfloat16 g_hatt[Tt * Dd], g_latt[Tt * Dd];
__device__ __nv_bfloat16 g_hxn2[Tt * Dd], g_lxn2[Tt * Dd];
__device__ __nv_bfloat16 g_hgb [(size_t)NPAIR * HIDh], g_lgb[(size_t)NPAIR * HIDh];
__device__ __nv_bfloat16 g_hwqkv[(size_t)QKVN * Dd], g_lwqkv[(size_t)QKVN * Dd];
__device__ __nv_bfloat16 g_hwo [Dd * Dd], g_lwo[Dd * Dd];
// routing
__device__ int   g_tid2[NPAIR];
__device__ float g_twt [NPAIR];
__device__ int   g_cnt[Ee];
__device__ int   g_off[Ee];
__device__ int   g_tok[NPAIR];
__device__ int   g_prow[NPAIR];

// ---------------- helpers ----------------
__device__ __forceinline__ uint32_t smem_u32(const void* p) {
    uint32_t a;
    asm("{ .reg .u64 t; cvta.to.shared.u64 t, %1; cvt.u32.u64 %0, t; }" : "=r"(a) : "l"(p));
    return a;
}
__device__ __forceinline__ uint32_t swz128(uint32_t off) {
    return off ^ ((off >> 3) & 0x70);
}
__device__ __forceinline__ void ldsm_x4(uint32_t* r, uint32_t addr) {
    asm volatile("ldmatrix.sync.aligned.m8n8.x4.shared.b16 {%0,%1,%2,%3}, [%4];"
                 : "=r"(r[0]), "=r"(r[1]), "=r"(r[2]), "=r"(r[3]) : "r"(addr));
}
__device__ __forceinline__ void mma_bf16(float* c, const uint32_t* a, uint32_t b0, uint32_t b1) {
    asm volatile("mma.sync.aligned.m16n8k16.row.col.f32.bf16.bf16.f32 "
                 "{%0,%1,%2,%3}, {%4,%5,%6,%7}, {%8,%9}, {%0,%1,%2,%3};"
                 : "+f"(c[0]), "+f"(c[1]), "+f"(c[2]), "+f"(c[3])
                 : "r"(a[0]), "r"(a[1]), "r"(a[2]), "r"(a[3]), "r"(b0), "r"(b1));
}
__device__ __forceinline__ void cpa16(uint32_t dst, const void* src) {
    asm volatile("cp.async.cg.shared.global [%0], [%1], 16;" :: "r"(dst), "l"(src) : "memory");
}
__device__ __forceinline__ void split2(float f, __nv_bfloat16& h, __nv_bfloat16& l) {
    h = __float2bfloat16(f);
    l = __float2bfloat16(f - __bfloat162float(h));
}
__device__ __forceinline__ void store_split4(__nv_bfloat16* oh, __nv_bfloat16* ol,
                                             size_t o, float4 v) {
    __nv_bfloat16 h[4], l[4];
    split2(v.x, h[0], l[0]); split2(v.y, h[1], l[1]);
    split2(v.z, h[2], l[2]); split2(v.w, h[3], l[3]);
    *(ushort4*)(oh + o) = make_ushort4(*(uint16_t*)&h[0], *(uint16_t*)&h[1],
                                       *(uint16_t*)&h[2], *(uint16_t*)&h[3]);
    *(ushort4*)(ol + o) = make_ushort4(*(uint16_t*)&l[0], *(uint16_t*)&l[1],
                                       *(uint16_t*)&l[2], *(uint16_t*)&l[3]);
}

// ---------------- pack conversion (dense weights only), MLP=4 ----------------
__global__ void pack_kernel(const float* __restrict__ in,
                            __nv_bfloat16* __restrict__ oh,
                            __nv_bfloat16* __restrict__ ol, size_t nf4q) {
    size_t t = (size_t)blockIdx.x * 256 + threadIdx.x;
    float4 v[4];
    #pragma unroll
    for (int q = 0; q < 4; q++) v[q] = ((const float4*)in)[t + q * nf4q];
    #pragma unroll
    for (int q = 0; q < 4; q++) store_split4(oh, ol, (t + q * nf4q) * 4, v[q]);
}

__global__ void bias_cat_kernel(const float* __restrict__ bq, const float* __restrict__ bk,
                                const float* __restrict__ bv) {
    int i = blockIdx.x * 256 + threadIdx.x;
    float v = (i < Dd) ? bq[i] : (i < 2 * Dd) ? bk[i - Dd] : bv[i - 2 * Dd];
    g_bqkv[i] = v;
}

// ---------------- 3x-bf16 mma.sync GEMM, 3-stage cp.async pipeline ----------------
// C[M,N] = A[M,K] @ B[N,K]^T. CTA tile 128x128, K-tile 32 elems.
// Smem row (128B, swz128): [0,64) hi bf16 k0..31, [64,128) lo bf16 k0..31.
// SILU: N-cols are interleaved (gate,up) pairs; epilogue writes silu planes.
// CONVB: B comes from fp32 gmem (Bf0/Bf1), split to hi/lo in the loader.
#define STAGE_B  32768
#define TC_SMEM  (1024 + 3 * STAGE_B)

template <bool EXPERT, bool GATHER, bool SILU, bool CONVB>
__global__ __launch_bounds__(256, 2)
void tc_gemm(const __nv_bfloat16* __restrict__ Ahi, const __nv_bfloat16* __restrict__ Alo,
             const __nv_bfloat16* __restrict__ Bhi, const __nv_bfloat16* __restrict__ Blo,
             const float* __restrict__ Bf0, const float* __restrict__ Bf1,
             float* __restrict__ C, const float* __restrict__ bias,
             const float* __restrict__ resid, int N, int K) {
    extern __shared__ float sm[];
    const int tid = threadIdx.x;

    int bm, bn, cnt = 0, seg = 0, e = 0;
    if (EXPERT) {
        e = blockIdx.z; cnt = g_cnt[e]; seg = g_off[e];
        bm = blockIdx.y * 128;
        if (bm >= cnt) return;
    } else {
        bm = blockIdx.y * 128;
    }
    bn = blockIdx.x * 128;

    const uint32_t sbase = smem_u32(sm);
    const uint32_t tbase = (sbase + 1023) & ~1023u;
    char* tp = (char*)sm + (tbase - sbase);

    // ---- global source mapping: 2 threads/row, 16 elems (32B bf16 / 64B fp32) each ----
    const int arow = tid >> 1;
    const int half = tid & 1;
    int grow = bm + arow;
    size_t aoff;
    if (EXPERT) {
        int cl = (grow < cnt) ? grow : (cnt - 1);
        aoff = (size_t)(GATHER ? g_tok[seg + cl] : (seg + cl)) * K;
    } else {
        aoff = (size_t)grow * K;
    }
    const __nv_bfloat16* pAh = Ahi + aoff + half * 16;
    const __nv_bfloat16* pAl = Alo + aoff + half * 16;

    const int rB = bn + arow;
    const __nv_bfloat16* pBh = nullptr;
    const __nv_bfloat16* pBl = nullptr;
    const float* pBf = nullptr;
    if (CONVB) {
        if (SILU) {
            // interleaved: even row -> gate (Bf0), odd row -> up (Bf1), head = rB/2
            const float* src = (rB & 1) ? Bf1 : Bf0;
            pBf = src + ((size_t)e * HIDh + (rB >> 1)) * (size_t)K + half * 16;
        } else {
            pBf = Bf0 + ((size_t)(EXPERT ? e : 0) * N + rB) * (size_t)K + half * 16;
        }
    } else {
        const size_t boff = (EXPERT ? (size_t)e * N * K : 0) + (size_t)rB * K + half * 16;
        pBh = Bhi + boff;
        pBl = Blo + boff;
    }

    const uint32_t d0 = swz128((uint32_t)arow * 128 + half * 32);
    const uint32_t d1 = swz128((uint32_t)arow * 128 + half * 32 + 16);
    const uint32_t d2 = swz128((uint32_t)arow * 128 + 64 + half * 32);
    const uint32_t d3 = swz128((uint32_t)arow * 128 + 64 + half * 32 + 16);

    auto issueA = [&](int buf, int t) {
        const uint32_t aB = tbase + buf * STAGE_B;
        const int k0 = t * 32;
        cpa16(aB + d0, pAh + k0);
        cpa16(aB + d1, pAh + k0 + 8);
        cpa16(aB + d2, pAl + k0);
        cpa16(aB + d3, pAl + k0 + 8);
        if (!CONVB) {
            const uint32_t bB = aB + 16384;
            cpa16(bB + d0, pBh + k0);
            cpa16(bB + d1, pBh + k0 + 8);
            cpa16(bB + d2, pBl + k0);
            cpa16(bB + d3, pBl + k0 + 8);
        }
        asm volatile("cp.async.commit_group;" ::: "memory");
    };
    auto ldgB = [&](float4* b4, int t) {
        const float* p = pBf + t * 32;
        #pragma unroll
        for (int i = 0; i < 4; i++) b4[i] = *(const float4*)(p + i * 4);
    };
    auto stsB = [&](int buf, const float4* b4) {
        char* bB = tp + buf * STAGE_B + 16384;
        uint32_t hw[8], lw[8];
        #pragma unroll
        for (int i = 0; i < 4; i++) {
            const float* f = (const float*)&b4[i];
            #pragma unroll
            for (int j = 0; j < 2; j++) {
                __nv_bfloat16 h0, l0, h1, l1;
                split2(f[2 * j], h0, l0);
                split2(f[2 * j + 1], h1, l1);
                hw[i * 2 + j] = (uint32_t)(*(uint16_t*)&h0) | ((uint32_t)(*(uint16_t*)&h1) << 16);
                lw[i * 2 + j] = (uint32_t)(*(uint16_t*)&l0) | ((uint32_t)(*(uint16_t*)&l1) << 16);
            }
        }
        *(uint4*)(bB + d0) = make_uint4(hw[0], hw[1], hw[2], hw[3]);
        *(uint4*)(bB + d1) = make_uint4(hw[4], hw[5], hw[6], hw[7]);
        *(uint4*)(bB + d2) = make_uint4(lw[0], lw[1], lw[2], lw[3]);
        *(uint4*)(bB + d3) = make_uint4(lw[4], lw[5], lw[6], lw[7]);
    };

    // ---- warp tiling: 8 warps = 2(m) x 4(n), each 64x32 ----
    const int wid = tid >> 5, lane = tid & 31;
    const int wm = wid >> 2, wn = wid & 3;
    const int lrow = lane & 15;
    const int lcolb = (lane >> 4) * 16;

    float acc[4][4][4];
    #pragma unroll
    for (int i = 0; i < 4; i++)
        #pragma unroll
        for (int j = 0; j < 4; j++)
            #pragma unroll
            for (int q = 0; q < 4; q++) acc[i][j][q] = 0.f;

    const int NT = K >> 5;
    float4 bregs[4];

    issueA(0, 0);
    issueA(1, 1);
    if (CONVB) {
        ldgB(bregs, 0); stsB(0, bregs);
        ldgB(bregs, 1); stsB(1, bregs);
    }
    int buf = 0;
    for (int t = 0; t < NT; ++t) {
        if (t + 2 < NT) {
            asm volatile("cp.async.wait_group 1;" ::: "memory");
        } else {
            asm volatile("cp.async.wait_group 0;" ::: "memory");
        }
        __syncthreads();
        int nb = buf + 2; if (nb >= 3) nb -= 3;
        const bool more = (t + 2 < NT);
        if (more) {
            issueA(nb, t + 2);
            if (CONVB) ldgB(bregs, t + 2);
        }

        const uint32_t aB = tbase + buf * STAGE_B;
        const uint32_t bB = aB + 16384;
        #pragma unroll
        for (int s = 0; s < 2; s++) {
            uint32_t bh[2][4], bl[2][4];
            #pragma unroll
            for (int p = 0; p < 2; p++) {
                uint32_t ro = (uint32_t)(wn * 32 + p * 16 + lrow) * 128 + s * 32 + lcolb;
                ldsm_x4(bh[p], bB + swz128(ro));
                ldsm_x4(bl[p], bB + swz128(ro + 64));
            }
            #pragma unroll
            for (int i = 0; i < 4; i++) {
                uint32_t ah[4], al[4];
                uint32_t ro = (uint32_t)(wm * 64 + i * 16 + lrow) * 128 + s * 32 + lcolb;
                ldsm_x4(ah, aB + swz128(ro));
                ldsm_x4(al, aB + swz128(ro + 64));
                #pragma unroll
                for (int j = 0; j < 4; j++) {
                    const int p = j >> 1, o = j & 1;
                    mma_bf16(acc[i][j], ah, bh[p][o], bh[p][o + 2]);
                    mma_bf16(acc[i][j], ah, bl[p][o], bl[p][o + 2]);
                    mma_bf16(acc[i][j], al, bh[p][o], bh[p][o + 2]);
                }
            }
        }
        if (CONVB && more) stsB(nb, bregs);
        if (++buf == 3) buf = 0;
    }

    // ---- epilogue ----
    const int qr = lane >> 2;
    const int qc = (lane & 3) * 2;
    #pragma unroll
    for (int i = 0; i < 4; i++) {
        const int lm0 = wm * 64 + i * 16 + qr;
        #pragma unroll
        for (int j = 0; j < 4; j++) {
            const int c = bn + wn * 32 + j * 8 + qc;
            if (SILU) {
                const int h = c >> 1;
                float g0 = acc[i][j][0], u0 = acc[i][j][1];
                float g1 = acc[i][j][2], u1 = acc[i][j][3];
                float s0 = g0 / (1.f + __expf(-g0)) * u0;
                float s1 = g1 / (1.f + __expf(-g1)) * u1;
                if (bm + lm0 < cnt) {
                    __nv_bfloat16 hh, ll;
                    split2(s0, hh, ll);
                    size_t o = (size_t)(seg + bm + lm0) * HIDh + h;
                    g_hgb[o] = hh; g_lgb[o] = ll;
                }
                if (bm + lm0 + 8 < cnt) {
                    __nv_bfloat16 hh, ll;
                    split2(s1, hh, ll);
                    size_t o = (size_t)(seg + bm + lm0 + 8) * HIDh + h;
                    g_hgb[o] = hh; g_lgb[o] = ll;
                }
            } else {
                float2 v0 = make_float2(acc[i][j][0], acc[i][j][1]);
                float2 v1 = make_float2(acc[i][j][2], acc[i][j][3]);
                if (bias) {
                    float2 bv = *(const float2*)(bias + c);
                    v0.x += bv.x; v0.y += bv.y;
                    v1.x += bv.x; v1.y += bv.y;
                }
                if (EXPERT) {
                    if (bm + lm0 < cnt)
                        *(float2*)(C + (size_t)(seg + bm + lm0) * N + c) = v0;
                    if (bm + lm0 + 8 < cnt)
                        *(float2*)(C + (size_t)(seg + bm + lm0 + 8) * N + c) = v1;
                } else {
                    const int r0 = bm + lm0;
                    if (resid) {
                        float2 rv0 = *(const float2*)(resid + (size_t)r0 * Dd + c);
                        float2 rv1 = *(const float2*)(resid + (size_t)(r0 + 8) * Dd + c);
                        v0.x += rv0.x; v0.y += rv0.y;
                        v1.x += rv1.x; v1.y += rv1.y;
                    }
                    *(float2*)(C + (size_t)r0 * N + c)       = v0;
                    *(float2*)(C + (size_t)(r0 + 8) * N + c) = v1;
                }
            }
        }
    }
}

// ---------------- rmsnorm (optional fp32 + hi/lo plane outputs) ----------------
__global__ void rmsnorm_kernel(const float* __restrict__ x,
                               const float* __restrict__ w,
                               float* __restrict__ out_f32,
                               __nv_bfloat16* __restrict__ oh,
                               __nv_bfloat16* __restrict__ ol) {
    int t = blockIdx.x;
    const float* xr = x + (size_t)t * Dd;
    float ss = 0.f;
    for (int i = threadIdx.x; i < Dd; i += 256) { float vv = xr[i]; ss += vv * vv; }
    __shared__ float red[8];
    #pragma unroll
    for (int o = 16; o; o >>= 1) ss += __shfl_xor_sync(0xffffffffu, ss, o);
    if ((threadIdx.x & 31) == 0) red[threadIdx.x >> 5] = ss;
    __syncthreads();
    if (threadIdx.x < 8) {
        float v = red[threadIdx.x];
        #pragma unroll
        for (int o = 4; o; o >>= 1) v += __shfl_xor_sync(0xffu, v, o);
        if (threadIdx.x == 0) red[0] = v;
    }
    __syncthreads();
    float inv = 1.f / sqrtf(red[0] / (float)Dd + 1e-8f);
    for (int i = threadIdx.x; i < Dd; i += 256) {
        float v = xr[i] * inv * w[i];
        if (out_f32) out_f32[(size_t)t * Dd + i] = v;
        __nv_bfloat16 h, l;
        split2(v, h, l);
        oh[(size_t)t * Dd + i] = h;
        ol[(size_t)t * Dd + i] = l;
    }
}

// ---------------- RoPE on q and k slices in one launch ----------------
__global__ void rope_kernel(float* __restrict__ qkv) {
    int gid = blockIdx.x * 256 + threadIdx.x;          // 2 * Tt*Hh*64
    int coloff = (gid >= Tt * Hh * 64) ? Dd : 0;
    int g = gid & (Tt * Hh * 64 - 1);
    int t = g >> 10;
    int r = g & 1023;
    int h = r >> 6;
    int p = r & 63;
    float ang = (float)h * expf(-(float)p * (9.210340371976184f / 64.f));
    float c = cosf(ang), s = sinf(ang);
    float* base = qkv + (size_t)t * QKVN + coloff + h * DHh + 2 * p;
    float x1 = base[0], x2 = base[1];
    base[0] = x1 * c - x2 * s;
    base[1] = x1 * s + x2 * c;
}

// ---------------- attention: 32 q/block, 4 q/warp, lane-per-key ----------------
#define AQS 0
#define AKS 4096
#define AVS (4096 + 32 * 132)
#define ATT_SMEM ((4096 + 2 * 32 * 132) * 4)

__global__ __launch_bounds__(256)
void attn_kernel(const float* __restrict__ QKV,
                 __nv_bfloat16* __restrict__ Oh, __nv_bfloat16* __restrict__ Ol) {
    extern __shared__ float smf[];
    const int b = blockIdx.z, h = blockIdx.y, qg = blockIdx.x;
    const int tid = threadIdx.x;
    const int warp = tid >> 5, lane = tid & 31;

    for (int c = tid; c < 1024; c += 256) {
        int rr = c >> 5, c4 = (c & 31) * 4;
        *(float4*)&smf[AQS + rr * 128 + c4] =
            *(const float4*)&QKV[((size_t)(b * Ss + qg * 32 + rr)) * QKVN + h * DHh + c4];
    }

    const int q0 = qg * 32 + warp * 4;
    float m[4], l[4];
    float4 o[4];
    #pragma unroll
    for (int q = 0; q < 4; q++) {
        m[q] = -INFINITY; l[q] = 0.f;
        o[q] = make_float4(0.f, 0.f, 0.f, 0.f);
    }

    const int ntiles = qg + 1;
    for (int kt = 0; kt < ntiles; kt++) {
        __syncthreads();
        for (int c = tid; c < 1024; c += 256) {
            int rr = c >> 5, c4 = (c & 31) * 4;
            size_t g = ((size_t)(b * Ss + kt * 32 + rr)) * QKVN + h * DHh + c4;
            *(float4*)&smf[AKS + rr * 132 + c4] = *(const float4*)&QKV[g + Dd];
            *(float4*)&smf[AVS + rr * 132 + c4] = *(const float4*)&QKV[g + 2 * Dd];
        }
        __syncthreads();

        const int kj = kt * 32 + lane;
        float4 s4[4];
        #pragma unroll
        for (int q = 0; q < 4; q++) s4[q] = make_float4(0.f, 0.f, 0.f, 0.f);
        const float* krow = &smf[AKS + lane * 132];
        #pragma unroll 8
        for (int c4 = 0; c4 < 32; c4++) {
            float4 kv = *(const float4*)&krow[c4 * 4];
            #pragma unroll
            for (int q = 0; q < 4; q++) {
                float4 qv = *(const float4*)&smf[AQS + (warp * 4 + q) * 128 + c4 * 4];
                s4[q].x = fmaf(qv.x, kv.x, s4[q].x);
                s4[q].y = fmaf(qv.y, kv.y, s4[q].y);
                s4[q].z = fmaf(qv.z, kv.z, s4[q].z);
                s4[q].w = fmaf(qv.w, kv.w, s4[q].w);
            }
        }
        float s[4], w[4];
        #pragma unroll
        for (int q = 0; q < 4; q++) {
            float v = (s4[q].x + s4[q].y) + (s4[q].z + s4[q].w);
            s[q] = (kj <= q0 + q) ? v * 0.08838834764831845f : -INFINITY;
        }
        float tm[4];
        #pragma unroll
        for (int q = 0; q < 4; q++) tm[q] = s[q];
        #pragma unroll
        for (int ofs = 16; ofs; ofs >>= 1)
            #pragma unroll
            for (int q = 0; q < 4; q++)
                tm[q] = fmaxf(tm[q], __shfl_xor_sync(0xffffffffu, tm[q], ofs));
        float ts[4];
        #pragma unroll
        for (int q = 0; q < 4; q++) {
            float mnew = fmaxf(m[q], tm[q]);
            float corr = __expf(m[q] - mnew);
            w[q] = __expf(s[q] - mnew);
            m[q] = mnew;
            l[q] *= corr;
            o[q].x *= corr; o[q].y *= corr; o[q].z *= corr; o[q].w *= corr;
            ts[q] = w[q];
        }
        #pragma unroll
        for (int ofs = 16; ofs; ofs >>= 1)
            #pragma unroll
            for (int q = 0; q < 4; q++)
                ts[q] += __shfl_xor_sync(0xffffffffu, ts[q], ofs);
        #pragma unroll
        for (int q = 0; q < 4; q++) l[q] += ts[q];

        const float* vcol = &smf[AVS + lane * 4];
        #pragma unroll 4
        for (int j = 0; j < 32; j++) {
            float4 vv = *(const float4*)&vcol[j * 132];
            #pragma unroll
            for (int q = 0; q < 4; q++) {
                float wq = __shfl_sync(0xffffffffu, w[q], j);
                o[q].x = fmaf(wq, vv.x, o[q].x);
                o[q].y = fmaf(wq, vv.y, o[q].y);
                o[q].z = fmaf(wq, vv.z, o[q].z);
                o[q].w = fmaf(wq, vv.w, o[q].w);
            }
        }
    }

    #pragma unroll
    for (int q = 0; q < 4; q++) {
        float inv = 1.f / l[q];
        float f[4] = {o[q].x * inv, o[q].y * inv, o[q].z * inv, o[q].w * inv};
        __nv_bfloat16 hh[4], ll[4];
        #pragma unroll
        for (int d = 0; d < 4; d++) split2(f[d], hh[d], ll[d]);
        size_t base = ((size_t)(b * Ss + q0 + q)) * Dd + h * DHh + lane * 4;
        *(ushort4*)(Oh + base) = make_ushort4(*(uint16_t*)&hh[0], *(uint16_t*)&hh[1],
                                              *(uint16_t*)&hh[2], *(uint16_t*)&hh[3]);
        *(ushort4*)(Ol + base) = make_ushort4(*(uint16_t*)&ll[0], *(uint16_t*)&ll[1],
                                              *(uint16_t*)&ll[2], *(uint16_t*)&ll[3]);
    }
}

// ---------------- router ----------------
__global__ void router_kernel(const float* __restrict__ xn, const float* __restrict__ wr,
                              const float* __restrict__ br) {
    int t = blockIdx.x;
    int warp = threadIdx.x >> 5, lane = threadIdx.x & 31;
    const float* xr = xn + (size_t)t * Dd;
    const float* w = wr + (size_t)warp * Dd;
    float s = 0.f;
    for (int i = lane; i < Dd; i += 32) s += xr[i] * w[i];
    #pragma unroll
    for (int o = 16; o; o >>= 1) s += __shfl_xor_sync(0xffffffffu, s, o);
    __shared__ float lg[Ee];
    if (lane == 0) lg[warp] = s + br[warp];
    __syncthreads();
    if (threadIdx.x == 0) {
        int i0 = 0; float v0 = lg[0];
        for (int e = 1; e < Ee; e++) if (lg[e] > v0) { v0 = lg[e]; i0 = e; }
        int i1 = -1; float v1 = -INFINITY;
        for (int e = 0; e < Ee; e++) if (e != i0 && lg[e] > v1) { v1 = lg[e]; i1 = e; }
        float e1 = expf(v1 - v0);
        float w0 = 1.f / (1.f + e1);
        g_tid2[t * 2] = i0; g_tid2[t * 2 + 1] = i1;
        g_twt[t * 2] = w0;  g_twt[t * 2 + 1] = e1 * w0;
    }
}

// ---------------- expert grouping ----------------
__global__ void build_lists_kernel() {
    __shared__ int cnt[Ee], run[Ee];
    int tid = threadIdx.x;
    if (tid < Ee) cnt[tid] = 0;
    __syncthreads();
    for (int i = tid; i < NPAIR; i += 256) atomicAdd(&cnt[g_tid2[i]], 1);
    __syncthreads();
    if (tid == 0) {
        int acc = 0;
        for (int e = 0; e < Ee; e++) { g_cnt[e] = cnt[e]; g_off[e] = acc; run[e] = acc; acc += cnt[e]; }
    }
    __syncthreads();
    for (int i = tid; i < NPAIR; i += 256) {
        int e = g_tid2[i];
        int pos = atomicAdd(&run[e], 1);
        g_tok[pos] = i >> 1;
        g_prow[i] = pos;
    }
}

// ---------------- combine ----------------
__global__ void combine_kernel(float* __restrict__ out) {
    int t = blockIdx.x;
    int r0 = g_prow[t * 2], r1 = g_prow[t * 2 + 1];
    float w0 = g_twt[t * 2], w1 = g_twt[t * 2 + 1];
    const float* e0 = g_eo + (size_t)r0 * Dd;
    const float* e1 = g_eo + (size_t)r1 * Dd;
    const float* xr = g_x2 + (size_t)t * Dd;
    float* orow = out + (size_t)t * Dd;
    for (int i = threadIdx.x; i < Dd; i += 256)
        orow[i] = xr[i] + w0 * e0[i] + w1 * e1[i];
}

// ---------------- host launcher ----------------
extern "C" void kernel_launch(void* const* d_in, const int* in_sizes, int n_in,
                              void* d_out, int out_size) {
    const float* x   = (const float*)d_in[0];
    const float* wq  = (const float*)d_in[1];
    const float* bq  = (const float*)d_in[2];
    const float* wk  = (const float*)d_in[3];
    const float* bk  = (const float*)d_in[4];
    const float* wv  = (const float*)d_in[5];
    const float* bv  = (const float*)d_in[6];
    const float* wo  = (const float*)d_in[7];
    const float* bo  = (const float*)d_in[8];
    const float* wr  = (const float*)d_in[9];
    const float* br  = (const float*)d_in[10];
    const float* wg  = (const float*)d_in[11];
    const float* wu  = (const float*)d_in[12];
    const float* wd  = (const float*)d_in[13];
    const float* r1w = (const float*)d_in[14];
    const float* r2w = (const float*)d_in[15];
    float* out = (float*)d_out;

    float *qkv, *x2, *xn2, *eo, *bqkv;
    __nv_bfloat16 *hxn1, *lxn1, *hatt, *latt, *hxn2, *lxn2, *hgb, *lgb;
    __nv_bfloat16 *hwqkv, *lwqkv, *hwo, *lwo;
    cudaGetSymbolAddress((void**)&qkv,  g_qkv);
    cudaGetSymbolAddress((void**)&x2,   g_x2);
    cudaGetSymbolAddress((void**)&xn2,  g_xn2);
    cudaGetSymbolAddress((void**)&eo,   g_eo);
    cudaGetSymbolAddress((void**)&bqkv, g_bqkv);
    cudaGetSymbolAddress((void**)&hxn1, g_hxn1);   cudaGetSymbolAddress((void**)&lxn1, g_lxn1);
    cudaGetSymbolAddress((void**)&hatt, g_hatt);   cudaGetSymbolAddress((void**)&latt, g_latt);
    cudaGetSymbolAddress((void**)&hxn2, g_hxn2);   cudaGetSymbolAddress((void**)&lxn2, g_lxn2);
    cudaGetSymbolAddress((void**)&hgb,  g_hgb);    cudaGetSymbolAddress((void**)&lgb,  g_lgb);
    cudaGetSymbolAddress((void**)&hwqkv, g_hwqkv); cudaGetSymbolAddress((void**)&lwqkv, g_lwqkv);
    cudaGetSymbolAddress((void**)&hwo,  g_hwo);    cudaGetSymbolAddress((void**)&lwo,  g_lwo);

    cudaFuncSetAttribute((const void*)tc_gemm<false, false, false, false>,
                         cudaFuncAttributeMaxDynamicSharedMemorySize, TC_SMEM);
    cudaFuncSetAttribute((const void*)tc_gemm<true, true, true, true>,
                         cudaFuncAttributeMaxDynamicSharedMemorySize, TC_SMEM);
    cudaFuncSetAttribute((const void*)tc_gemm<true, false, false, true>,
                         cudaFuncAttributeMaxDynamicSharedMemorySize, TC_SMEM);
    cudaFuncSetAttribute((const void*)attn_kernel,
                         cudaFuncAttributeMaxDynamicSharedMemorySize, ATT_SMEM);

    // 0) pack dense weights only (small); MoE weights are converted in-GEMM
    const size_t qD = (size_t)Dd * Dd / 16;
    pack_kernel<<<Dd * Dd / 4096, 256>>>(wq, hwqkv, lwqkv, qD);
    pack_kernel<<<Dd * Dd / 4096, 256>>>(wk, hwqkv + (size_t)Dd * Dd, lwqkv + (size_t)Dd * Dd, qD);
    pack_kernel<<<Dd * Dd / 4096, 256>>>(wv, hwqkv + (size_t)2 * Dd * Dd, lwqkv + (size_t)2 * Dd * Dd, qD);
    pack_kernel<<<Dd * Dd / 4096, 256>>>(wo, hwo, lwo, qD);
    bias_cat_kernel<<<QKVN / 256, 256>>>(bq, bk, bv);

    // 1) rmsnorm1 -> planes only
    rmsnorm_kernel<<<Tt, 256>>>(x, r1w, nullptr, hxn1, lxn1);
    // 2) fused QKV projection (N = 6144)
    tc_gemm<false, false, false, false><<<dim3(QKVN / 128, Tt / 128), 256, TC_SMEM>>>(
        hxn1, lxn1, hwqkv, lwqkv, nullptr, nullptr, qkv, bqkv, nullptr, QKVN, Dd);
    // 3) RoPE on q and k slices (single launch)
    rope_kernel<<<(2 * Tt * Hh * 64) / 256, 256>>>(qkv);
    // 4) attention -> att planes
    attn_kernel<<<dim3(Ss / 32, Hh, Bb), 256, ATT_SMEM>>>(qkv, hatt, latt);
    // 5) output projection + residual
    tc_gemm<false, false, false, false><<<dim3(Dd / 128, Tt / 128), 256, TC_SMEM>>>(
        hatt, latt, hwo, lwo, nullptr, nullptr, x2, bo, x, Dd, Dd);
    // 6) rmsnorm2 -> fp32 (router) + planes (MoE)
    rmsnorm_kernel<<<Tt, 256>>>(x2, r2w, xn2, hxn2, lxn2);
    // 7) router + grouping
    router_kernel<<<Tt, 256>>>(xn2, wr, br);
    build_lists_kernel<<<1, 256>>>();
    // 8) MoE: fused gate+up (interleaved, silu epilogue, fp32 B in-GEMM), then down (fp32 B)
    tc_gemm<true, true, true, true><<<dim3(GUN / 128, NPAIR / 128, Ee), 256, TC_SMEM>>>(
        hxn2, lxn2, nullptr, nullptr, wg, wu, nullptr, nullptr, nullptr, GUN, Dd);
    tc_gemm<true, false, false, true><<<dim3(Dd / 128, NPAIR / 128, Ee), 256, TC_SMEM>>>(
        hgb, lgb, nullptr, nullptr, wd, nullptr, eo, nullptr, nullptr, Dd, HIDh);
    // 9) combine
    combine_kernel<<<Tt, 256>>>(out);
}